// round 4
// baseline (speedup 1.0000x reference)
#include <cuda_runtime.h>
#include <math.h>
#include <stddef.h>

namespace {
constexpr int B = 8, T = 2048, C = 1024, H = 128;
constexpr int NR = B * T;          // 16384 rows of q/k/v
constexpr int TQ = 64, TSZ = 64;   // query tile, key tile
constexpr int NT = T / TSZ;        // 32 s-tiles
constexpr int QS_LD = 132, KS_LD = 68, PS_LD = 68;
constexpr int SMEM_FLOATS = 64 * QS_LD + 128 * KS_LD + 64 * 128 + 64 * PS_LD + 128;
}

// scratch (device globals: allocation-free per harness rules)
__device__ float g_q[NR * H];
__device__ float g_k[NR * H];
__device__ float g_v[NR * H];
__device__ float g_sq[NR];
__device__ float g_sk[NR];

// ---------------- projection GEMM: out[NR][128] = x[NR][1024] @ W[128][1024]^T
__global__ __launch_bounds__(256) void proj_kernel(
    const float* __restrict__ x, const float* __restrict__ Wq,
    const float* __restrict__ Wk, const float* __restrict__ Wv)
{
    __shared__ float As[16][64];
    __shared__ float Bs[16][128];
    const float* W   = (blockIdx.y == 0) ? Wq  : (blockIdx.y == 1) ? Wk  : Wv;
    float*       out = (blockIdx.y == 0) ? g_q : (blockIdx.y == 1) ? g_k : g_v;
    const int m0 = blockIdx.x * 64;
    const int tid = threadIdx.x;
    const int tx = tid & 31, ty = tid >> 5;

    const int ar = tid >> 2, ac = (tid & 3) * 4;   // A loader: row, col4
    const int bn = tid >> 1, bk = (tid & 1) * 8;   // B loader: n, k-offset
    const float* xrow = x + (size_t)(m0 + ar) * C + ac;
    const float* wrow = W + (size_t)bn * C + bk;

    float acc[8][4];
#pragma unroll
    for (int i = 0; i < 8; i++)
#pragma unroll
        for (int j = 0; j < 4; j++) acc[i][j] = 0.f;

    for (int k0 = 0; k0 < C; k0 += 16) {
        float4 av = *(const float4*)(xrow + k0);
        float4 b0 = *(const float4*)(wrow + k0);
        float4 b1 = *(const float4*)(wrow + k0 + 4);
        __syncthreads();
        As[ac + 0][ar] = av.x; As[ac + 1][ar] = av.y;
        As[ac + 2][ar] = av.z; As[ac + 3][ar] = av.w;
        Bs[bk + 0][bn] = b0.x; Bs[bk + 1][bn] = b0.y;
        Bs[bk + 2][bn] = b0.z; Bs[bk + 3][bn] = b0.w;
        Bs[bk + 4][bn] = b1.x; Bs[bk + 5][bn] = b1.y;
        Bs[bk + 6][bn] = b1.z; Bs[bk + 7][bn] = b1.w;
        __syncthreads();
#pragma unroll
        for (int kk = 0; kk < 16; kk++) {
            float4 a0 = *(const float4*)&As[kk][ty * 8];
            float4 a1 = *(const float4*)&As[kk][ty * 8 + 4];
            float4 bv = *(const float4*)&Bs[kk][tx * 4];
            float a[8] = {a0.x, a0.y, a0.z, a0.w, a1.x, a1.y, a1.z, a1.w};
            float bb[4] = {bv.x, bv.y, bv.z, bv.w};
#pragma unroll
            for (int i = 0; i < 8; i++)
#pragma unroll
                for (int j = 0; j < 4; j++)
                    acc[i][j] = fmaf(a[i], bb[j], acc[i][j]);
        }
    }
#pragma unroll
    for (int i = 0; i < 8; i++) {
        float4 o = make_float4(acc[i][0], acc[i][1], acc[i][2], acc[i][3]);
        *(float4*)&out[(size_t)(m0 + ty * 8 + i) * H + tx * 4] = o;
    }
}

// ---------------- per-row feature sums of q and k (for the pos decomposition)
__global__ __launch_bounds__(256) void rowsum_kernel()
{
    int w = (blockIdx.x * blockDim.x + threadIdx.x) >> 5;
    int lane = threadIdx.x & 31;
    if (w >= NR) return;
    float4 q = *(const float4*)&g_q[(size_t)w * H + lane * 4];
    float4 k = *(const float4*)&g_k[(size_t)w * H + lane * 4];
    float sq = q.x + q.y + q.z + q.w;
    float sk = k.x + k.y + k.z + k.w;
#pragma unroll
    for (int o = 16; o > 0; o >>= 1) {
        sq += __shfl_xor_sync(0xffffffffu, sq, o);
        sk += __shfl_xor_sync(0xffffffffu, sk, o);
    }
    if (lane == 0) { g_sq[w] = sq; g_sk[w] = sk; }
}

// ---------------- two-pass causal attention, 64x64 tiles
// score(t,s) = (qx.kx + s*sum_h qx[t] + t*sum_h kx[s] + 128*t*s) / 32
__global__ __launch_bounds__(256) void attn_kernel(
    float* __restrict__ res, float* __restrict__ attn)
{
    extern __shared__ float sm[];
    float* Qs  = sm;                  // [64][132] row-major
    float* Ks  = Qs + 64 * QS_LD;     // [128][68] k-major
    float* Vs  = Ks + 128 * KS_LD;    // [64][128] row-major
    float* Ps  = Vs + 64 * 128;       // [64][68]
    float* sqs = Ps + 64 * PS_LD;     // [64]
    float* sks = sqs + 64;            // [64]

    const int b  = blockIdx.y;
    const int kt = (gridDim.x - 1) - blockIdx.x;   // reversed: heavy blocks first
    const int t0 = kt * TQ;
    const int tid = threadIdx.x;
    const int tx = tid & 15, ty = tid >> 4;
    const int lc4 = tid & 31, lr0 = tid >> 5;

    {   // load Q tile (row-major) + sq
        const float* qbase = g_q + (size_t)(b * T + t0) * H;
#pragma unroll
        for (int it = 0; it < 8; it++) {
            int r = lr0 + it * 8;
            float4 v = *(const float4*)(qbase + (size_t)r * H + lc4 * 4);
            *(float4*)&Qs[r * QS_LD + lc4 * 4] = v;
        }
        if (tid < 64) sqs[tid] = g_sq[b * T + t0 + tid];
    }
    __syncthreads();

    float m_i[4], l_i[4], sq_i[4];
    int t_i[4];
#pragma unroll
    for (int ii = 0; ii < 4; ii++) {
        int i = ty * 4 + ii;
        m_i[ii] = -INFINITY; l_i[ii] = 0.f;
        sq_i[ii] = sqs[i];
        t_i[ii]  = t0 + i;
    }
    const int ntiles = kt + 1;

    // ------------ pass A: exact row max and sum (online) ------------
    for (int st = 0; st < ntiles; st++) {
        const int s0 = st * TSZ;
        __syncthreads();
        {
            const float* kbase = g_k + (size_t)(b * T + s0) * H;
#pragma unroll
            for (int it = 0; it < 8; it++) {
                int r = lr0 + it * 8;
                float4 v = *(const float4*)(kbase + (size_t)r * H + lc4 * 4);
                Ks[(lc4 * 4 + 0) * KS_LD + r] = v.x;
                Ks[(lc4 * 4 + 1) * KS_LD + r] = v.y;
                Ks[(lc4 * 4 + 2) * KS_LD + r] = v.z;
                Ks[(lc4 * 4 + 3) * KS_LD + r] = v.w;
            }
            if (tid < 64) sks[tid] = g_sk[b * T + s0 + tid];
        }
        __syncthreads();

        float acc[4][4];
#pragma unroll
        for (int ii = 0; ii < 4; ii++)
#pragma unroll
            for (int jj = 0; jj < 4; jj++) acc[ii][jj] = 0.f;
#pragma unroll 4
        for (int kk = 0; kk < 128; kk++) {
            float4 kv = *(const float4*)&Ks[kk * KS_LD + tx * 4];
            float kvv[4] = {kv.x, kv.y, kv.z, kv.w};
#pragma unroll
            for (int ii = 0; ii < 4; ii++) {
                float qv = Qs[(ty * 4 + ii) * QS_LD + kk];
#pragma unroll
                for (int jj = 0; jj < 4; jj++)
                    acc[ii][jj] = fmaf(qv, kvv[jj], acc[ii][jj]);
            }
        }
        float skv[4]; int sidx[4];
#pragma unroll
        for (int jj = 0; jj < 4; jj++) {
            sidx[jj] = s0 + tx * 4 + jj;
            skv[jj]  = sks[tx * 4 + jj];
        }
#pragma unroll
        for (int ii = 0; ii < 4; ii++) {
            float tmax = -INFINITY;
            float lg[4];
#pragma unroll
            for (int jj = 0; jj < 4; jj++) {
                int s = sidx[jj];
                float v = (acc[ii][jj] + (float)s * sq_i[ii] + (float)t_i[ii] * skv[jj]
                           + 128.f * (float)(t_i[ii] * s)) * 0.03125f;
                lg[jj] = (s <= t_i[ii]) ? v : -INFINITY;
                tmax = fmaxf(tmax, lg[jj]);
            }
#pragma unroll
            for (int o = 1; o < 16; o <<= 1)
                tmax = fmaxf(tmax, __shfl_xor_sync(0xffffffffu, tmax, o));
            float mn = fmaxf(m_i[ii], tmax);
            float psum = 0.f;
#pragma unroll
            for (int jj = 0; jj < 4; jj++) psum += __expf(lg[jj] - mn);
#pragma unroll
            for (int o = 1; o < 16; o <<= 1)
                psum += __shfl_xor_sync(0xffffffffu, psum, o);
            l_i[ii] = l_i[ii] * __expf(m_i[ii] - mn) + psum;
            m_i[ii] = mn;
        }
    }

    float rinv[4];
#pragma unroll
    for (int ii = 0; ii < 4; ii++) rinv[ii] = 1.f / l_i[ii];

    float oa[4][8];
#pragma unroll
    for (int ii = 0; ii < 4; ii++)
#pragma unroll
        for (int h = 0; h < 8; h++) oa[ii][h] = 0.f;

    // ------------ pass B: normalized attn write + PV ------------
    for (int st = 0; st < ntiles; st++) {
        const int s0 = st * TSZ;
        __syncthreads();
        {
            const float* kbase = g_k + (size_t)(b * T + s0) * H;
            const float* vbase = g_v + (size_t)(b * T + s0) * H;
#pragma unroll
            for (int it = 0; it < 8; it++) {
                int r = lr0 + it * 8;
                float4 v = *(const float4*)(kbase + (size_t)r * H + lc4 * 4);
                Ks[(lc4 * 4 + 0) * KS_LD + r] = v.x;
                Ks[(lc4 * 4 + 1) * KS_LD + r] = v.y;
                Ks[(lc4 * 4 + 2) * KS_LD + r] = v.z;
                Ks[(lc4 * 4 + 3) * KS_LD + r] = v.w;
                float4 vv = *(const float4*)(vbase + (size_t)r * H + lc4 * 4);
                *(float4*)&Vs[r * 128 + lc4 * 4] = vv;
            }
            if (tid < 64) sks[tid] = g_sk[b * T + s0 + tid];
        }
        __syncthreads();

        float acc[4][4];
#pragma unroll
        for (int ii = 0; ii < 4; ii++)
#pragma unroll
            for (int jj = 0; jj < 4; jj++) acc[ii][jj] = 0.f;
#pragma unroll 4
        for (int kk = 0; kk < 128; kk++) {
            float4 kv = *(const float4*)&Ks[kk * KS_LD + tx * 4];
            float kvv[4] = {kv.x, kv.y, kv.z, kv.w};
#pragma unroll
            for (int ii = 0; ii < 4; ii++) {
                float qv = Qs[(ty * 4 + ii) * QS_LD + kk];
#pragma unroll
                for (int jj = 0; jj < 4; jj++)
                    acc[ii][jj] = fmaf(qv, kvv[jj], acc[ii][jj]);
            }
        }
#pragma unroll
        for (int ii = 0; ii < 4; ii++) {
            float p[4];
#pragma unroll
            for (int jj = 0; jj < 4; jj++) {
                int s = s0 + tx * 4 + jj;
                float v = (acc[ii][jj] + (float)s * sq_i[ii] + (float)t_i[ii] * sks[tx * 4 + jj]
                           + 128.f * (float)(t_i[ii] * s)) * 0.03125f;
                p[jj] = (s <= t_i[ii]) ? __expf(v - m_i[ii]) * rinv[ii] : 0.f;
            }
            float4 pv = make_float4(p[0], p[1], p[2], p[3]);
            *(float4*)&attn[((size_t)(b * T + t_i[ii])) * T + s0 + tx * 4] = pv;
            *(float4*)&Ps[(ty * 4 + ii) * PS_LD + tx * 4] = pv;
        }
        __syncthreads();
#pragma unroll 2
        for (int j = 0; j < 64; j++) {
            float4 v0 = *(const float4*)&Vs[j * 128 + tx * 8];
            float4 v1 = *(const float4*)&Vs[j * 128 + tx * 8 + 4];
            float vv[8] = {v0.x, v0.y, v0.z, v0.w, v1.x, v1.y, v1.z, v1.w};
#pragma unroll
            for (int ii = 0; ii < 4; ii++) {
                float pp = Ps[(ty * 4 + ii) * PS_LD + j];
#pragma unroll
                for (int h = 0; h < 8; h++)
                    oa[ii][h] = fmaf(pp, vv[h], oa[ii][h]);
            }
        }
    }

    // zero the strictly-upper (masked) attn tiles — output is poisoned
    float4 z4 = make_float4(0.f, 0.f, 0.f, 0.f);
    for (int st = ntiles; st < NT; st++) {
        int s0 = st * TSZ;
#pragma unroll
        for (int ii = 0; ii < 4; ii++)
            *(float4*)&attn[((size_t)(b * T + t_i[ii])) * T + s0 + tx * 4] = z4;
    }
    // write res
#pragma unroll
    for (int ii = 0; ii < 4; ii++) {
        float4 r0 = make_float4(oa[ii][0], oa[ii][1], oa[ii][2], oa[ii][3]);
        float4 r1 = make_float4(oa[ii][4], oa[ii][5], oa[ii][6], oa[ii][7]);
        float* rp = res + ((size_t)(b * T + t_i[ii])) * H + tx * 8;
        *(float4*)rp = r0;
        *(float4*)(rp + 4) = r1;
    }
}

extern "C" void kernel_launch(void* const* d_in, const int* in_sizes, int n_in,
                              void* d_out, int out_size)
{
    const float* x  = (const float*)d_in[0];
    const float* Wq = (const float*)d_in[1];
    const float* Wk = (const float*)d_in[2];
    const float* Wv = (const float*)d_in[3];
    float* res  = (float*)d_out;
    float* attn = res + (size_t)B * T * H;

    proj_kernel<<<dim3(NR / 64, 3), 256>>>(x, Wq, Wk, Wv);
    rowsum_kernel<<<NR / 8, 256>>>();
    cudaFuncSetAttribute(attn_kernel, cudaFuncAttributeMaxDynamicSharedMemorySize,
                         SMEM_FLOATS * (int)sizeof(float));
    attn_kernel<<<dim3(NT, B), 256, SMEM_FLOATS * sizeof(float)>>>(res, attn);
}

// round 5
// speedup vs baseline: 1.6689x; 1.6689x over previous
#include <cuda_runtime.h>
#include <math.h>
#include <stddef.h>

namespace {
constexpr int B = 8, T = 2048, C = 1024, H = 128;
constexpr int NR = B * T;   // 16384 rows
}

// scratch (device globals: allocation-free per harness rules)
__device__ float g_q[NR * H];
__device__ float g_k[NR * H];
__device__ float g_v[NR * H];
__device__ float g_sq[NR];
__device__ float g_sk[NR];

// ---------------------------------------------------------------------------
// proj: out[NR][128] = x[NR][1024] @ W[128][1024]^T
// 128x128 block tile, 256 threads, 8x8 per thread, k-slab 16, reg prefetch.
__global__ __launch_bounds__(256, 2) void proj_kernel(
    const float* __restrict__ x, const float* __restrict__ Wq,
    const float* __restrict__ Wk, const float* __restrict__ Wv)
{
    __shared__ float As[16][128];   // As[kk][row]
    __shared__ float Bs[16][128];   // Bs[kk][col]
    const int which = blockIdx.y;
    const float* W   = (which == 0) ? Wq  : (which == 1) ? Wk  : Wv;
    float*       out = (which == 0) ? g_q : (which == 1) ? g_k : g_v;
    const int m0 = blockIdx.x * 128;
    const int tid = threadIdx.x;
    const int tx = tid & 15, ty = tid >> 4;
    const int lr = tid >> 1, lc = (tid & 1) * 8;

    const float* xp = x + (size_t)(m0 + lr) * C + lc;
    const float* wp = W + (size_t)lr * C + lc;

    float4 A0 = *(const float4*)(xp);
    float4 A1 = *(const float4*)(xp + 4);
    float4 B0 = *(const float4*)(wp);
    float4 B1 = *(const float4*)(wp + 4);

    float acc[8][8];
#pragma unroll
    for (int i = 0; i < 8; i++)
#pragma unroll
        for (int j = 0; j < 8; j++) acc[i][j] = 0.f;

    for (int k0 = 0; k0 < C; k0 += 16) {
        As[lc + 0][lr] = A0.x; As[lc + 1][lr] = A0.y;
        As[lc + 2][lr] = A0.z; As[lc + 3][lr] = A0.w;
        As[lc + 4][lr] = A1.x; As[lc + 5][lr] = A1.y;
        As[lc + 6][lr] = A1.z; As[lc + 7][lr] = A1.w;
        Bs[lc + 0][lr] = B0.x; Bs[lc + 1][lr] = B0.y;
        Bs[lc + 2][lr] = B0.z; Bs[lc + 3][lr] = B0.w;
        Bs[lc + 4][lr] = B1.x; Bs[lc + 5][lr] = B1.y;
        Bs[lc + 6][lr] = B1.z; Bs[lc + 7][lr] = B1.w;
        __syncthreads();
        if (k0 + 16 < C) {
            A0 = *(const float4*)(xp + k0 + 16);
            A1 = *(const float4*)(xp + k0 + 20);
            B0 = *(const float4*)(wp + k0 + 16);
            B1 = *(const float4*)(wp + k0 + 20);
        }
#pragma unroll
        for (int kk = 0; kk < 16; kk++) {
            float4 a0 = *(const float4*)&As[kk][ty * 8];
            float4 a1 = *(const float4*)&As[kk][ty * 8 + 4];
            float4 b0 = *(const float4*)&Bs[kk][tx * 8];
            float4 b1 = *(const float4*)&Bs[kk][tx * 8 + 4];
            float a[8] = {a0.x, a0.y, a0.z, a0.w, a1.x, a1.y, a1.z, a1.w};
            float bb[8] = {b0.x, b0.y, b0.z, b0.w, b1.x, b1.y, b1.z, b1.w};
#pragma unroll
            for (int i = 0; i < 8; i++)
#pragma unroll
                for (int j = 0; j < 8; j++)
                    acc[i][j] = fmaf(a[i], bb[j], acc[i][j]);
        }
        __syncthreads();
    }
#pragma unroll
    for (int i = 0; i < 8; i++) {
        float* op = out + (size_t)(m0 + ty * 8 + i) * H + tx * 8;
        *(float4*)op       = make_float4(acc[i][0], acc[i][1], acc[i][2], acc[i][3]);
        *(float4*)(op + 4) = make_float4(acc[i][4], acc[i][5], acc[i][6], acc[i][7]);
    }
}

// ---------------------------------------------------------------------------
// per-row feature sums of q and k (pos decomposition)
__global__ __launch_bounds__(256) void rowsum_kernel()
{
    int w = (blockIdx.x * blockDim.x + threadIdx.x) >> 5;
    int lane = threadIdx.x & 31;
    if (w >= NR) return;
    float4 q = *(const float4*)&g_q[(size_t)w * H + lane * 4];
    float4 k = *(const float4*)&g_k[(size_t)w * H + lane * 4];
    float sq = q.x + q.y + q.z + q.w;
    float sk = k.x + k.y + k.z + k.w;
#pragma unroll
    for (int o = 16; o > 0; o >>= 1) {
        sq += __shfl_xor_sync(0xffffffffu, sq, o);
        sk += __shfl_xor_sync(0xffffffffu, sk, o);
    }
    if (lane == 0) { g_sq[w] = sq; g_sk[w] = sk; }
}

// ---------------------------------------------------------------------------
// score: raw S[b,t,s] = q[b,t,:].k[b,s,:] for lower-band 128x128 tiles.
// grid.x enumerates the 136 lower-triangular tile pairs, grid.y = batch.
__global__ __launch_bounds__(256, 2) void score_kernel(float* __restrict__ attn)
{
    __shared__ float As[16][128];   // As[kk][t]
    __shared__ float Bs[16][128];   // Bs[kk][s]
    const int b = blockIdx.y;
    const int idx = blockIdx.x;
    int ti = (int)((sqrtf(8.f * (float)idx + 1.f) - 1.f) * 0.5f);
    if (ti > 15) ti = 15;
    while ((ti + 1) * (ti + 2) / 2 <= idx) ti++;
    while (ti * (ti + 1) / 2 > idx) ti--;
    const int tj = idx - ti * (ti + 1) / 2;
    const int t0 = ti * 128, s0 = tj * 128;

    const int tid = threadIdx.x;
    const int tx = tid & 15, ty = tid >> 4;
    const int lr = tid >> 1, lc = (tid & 1) * 8;

    const float* qp = g_q + (size_t)(b * T + t0 + lr) * H + lc;
    const float* kp = g_k + (size_t)(b * T + s0 + lr) * H + lc;

    float4 A0 = *(const float4*)(qp);
    float4 A1 = *(const float4*)(qp + 4);
    float4 B0 = *(const float4*)(kp);
    float4 B1 = *(const float4*)(kp + 4);

    float acc[8][8];
#pragma unroll
    for (int i = 0; i < 8; i++)
#pragma unroll
        for (int j = 0; j < 8; j++) acc[i][j] = 0.f;

    for (int k0 = 0; k0 < H; k0 += 16) {
        As[lc + 0][lr] = A0.x; As[lc + 1][lr] = A0.y;
        As[lc + 2][lr] = A0.z; As[lc + 3][lr] = A0.w;
        As[lc + 4][lr] = A1.x; As[lc + 5][lr] = A1.y;
        As[lc + 6][lr] = A1.z; As[lc + 7][lr] = A1.w;
        Bs[lc + 0][lr] = B0.x; Bs[lc + 1][lr] = B0.y;
        Bs[lc + 2][lr] = B0.z; Bs[lc + 3][lr] = B0.w;
        Bs[lc + 4][lr] = B1.x; Bs[lc + 5][lr] = B1.y;
        Bs[lc + 6][lr] = B1.z; Bs[lc + 7][lr] = B1.w;
        __syncthreads();
        if (k0 + 16 < H) {
            A0 = *(const float4*)(qp + k0 + 16);
            A1 = *(const float4*)(qp + k0 + 20);
            B0 = *(const float4*)(kp + k0 + 16);
            B1 = *(const float4*)(kp + k0 + 20);
        }
#pragma unroll
        for (int kk = 0; kk < 16; kk++) {
            float4 a0 = *(const float4*)&As[kk][ty * 8];
            float4 a1 = *(const float4*)&As[kk][ty * 8 + 4];
            float4 b0 = *(const float4*)&Bs[kk][tx * 8];
            float4 b1 = *(const float4*)&Bs[kk][tx * 8 + 4];
            float a[8] = {a0.x, a0.y, a0.z, a0.w, a1.x, a1.y, a1.z, a1.w};
            float bb[8] = {b0.x, b0.y, b0.z, b0.w, b1.x, b1.y, b1.z, b1.w};
#pragma unroll
            for (int i = 0; i < 8; i++)
#pragma unroll
                for (int j = 0; j < 8; j++)
                    acc[i][j] = fmaf(a[i], bb[j], acc[i][j]);
        }
        __syncthreads();
    }
#pragma unroll
    for (int i = 0; i < 8; i++) {
        float* op = attn + (size_t)(b * T + t0 + ty * 8 + i) * T + s0 + tx * 8;
        *(float4*)op       = make_float4(acc[i][0], acc[i][1], acc[i][2], acc[i][3]);
        *(float4*)(op + 4) = make_float4(acc[i][4], acc[i][5], acc[i][6], acc[i][7]);
    }
}

// ---------------------------------------------------------------------------
// softmax: in-place over each attn row; adds pos terms, masks, normalizes.
// logit = (qk + s*sum(q[t]) + t*sum(k[s]) + 128*t*s) / 32
__global__ __launch_bounds__(256) void softmax_kernel(float* __restrict__ attn)
{
    __shared__ float red[8];
    const int r = blockIdx.x;
    const int b = r >> 11;          // r / T
    const int t = r & (T - 1);
    float* row = attn + (size_t)r * T;
    const float* skrow = g_sk + (size_t)b * T;
    const float sq = g_sq[r];
    const float tf = (float)t;
    const int tid = threadIdx.x;
    const int c0 = tid * 8;

    float4 v0 = *(const float4*)(row + c0);
    float4 v1 = *(const float4*)(row + c0 + 4);
    float4 s0 = *(const float4*)(skrow + c0);
    float4 s1 = *(const float4*)(skrow + c0 + 4);
    float qk[8] = {v0.x, v0.y, v0.z, v0.w, v1.x, v1.y, v1.z, v1.w};
    float sk[8] = {s0.x, s0.y, s0.z, s0.w, s1.x, s1.y, s1.z, s1.w};

    float lg[8];
    float mx = -INFINITY;
#pragma unroll
    for (int j = 0; j < 8; j++) {
        int s = c0 + j;
        float v = (qk[j] + (float)s * sq + tf * sk[j] + 128.f * (float)(t * s)) * 0.03125f;
        lg[j] = (s <= t) ? v : -INFINITY;
        mx = fmaxf(mx, lg[j]);
    }
#pragma unroll
    for (int o = 16; o > 0; o >>= 1)
        mx = fmaxf(mx, __shfl_xor_sync(0xffffffffu, mx, o));
    if ((tid & 31) == 0) red[tid >> 5] = mx;
    __syncthreads();
    float m = red[0];
#pragma unroll
    for (int i = 1; i < 8; i++) m = fmaxf(m, red[i]);
    __syncthreads();

    float ev[8];
    float sum = 0.f;
#pragma unroll
    for (int j = 0; j < 8; j++) {
        ev[j] = __expf(lg[j] - m);   // masked lanes: exp(-inf) = 0
        sum += ev[j];
    }
#pragma unroll
    for (int o = 16; o > 0; o >>= 1)
        sum += __shfl_xor_sync(0xffffffffu, sum, o);
    if ((tid & 31) == 0) red[tid >> 5] = sum;
    __syncthreads();
    float tot = red[0];
#pragma unroll
    for (int i = 1; i < 8; i++) tot += red[i];
    const float rinv = 1.f / tot;

    *(float4*)(row + c0)     = make_float4(ev[0] * rinv, ev[1] * rinv, ev[2] * rinv, ev[3] * rinv);
    *(float4*)(row + c0 + 4) = make_float4(ev[4] * rinv, ev[5] * rinv, ev[6] * rinv, ev[7] * rinv);
}

// ---------------------------------------------------------------------------
// pv: res[b,t,:] = attn[b,t,:] @ v[b,:,:] over the causal band.
// 64x128 tile, 128 threads, 8x8 per thread. Zeros above diagonal make
// rectangular slabs exact. Reversed launch order for balance.
__global__ __launch_bounds__(128) void pv_kernel(
    const float* __restrict__ attn, float* __restrict__ res)
{
    __shared__ float As[16][68];    // As[ss][t]  (64 t-rows, padded)
    __shared__ float Bs[16][132];   // Bs[ss][h]  (padded)
    const int b = blockIdx.y;
    const int kt = (int)(gridDim.x - 1 - blockIdx.x);
    const int t0 = kt * 64;
    const int nk = 4 * (kt + 1);    // 16-wide s slabs
    const int tid = threadIdx.x;
    const int tx = tid & 15, ty = tid >> 4;

    const int atr = tid >> 1, asc = (tid & 1) * 8;       // A loader
    const int bvr = tid >> 3, bc = (tid & 7) * 4;        // B loader (4 strided f4)

    const float* ap = attn + (size_t)(b * T + t0 + atr) * T + asc;
    const float* vp = g_v + (size_t)(b * T + bvr) * H;

    float4 A0 = *(const float4*)(ap);
    float4 A1 = *(const float4*)(ap + 4);
    float4 V0 = *(const float4*)(vp + bc);
    float4 V1 = *(const float4*)(vp + bc + 32);
    float4 V2 = *(const float4*)(vp + bc + 64);
    float4 V3 = *(const float4*)(vp + bc + 96);

    float acc[8][8];
#pragma unroll
    for (int i = 0; i < 8; i++)
#pragma unroll
        for (int j = 0; j < 8; j++) acc[i][j] = 0.f;

    for (int s = 0; s < nk; s++) {
        As[asc + 0][atr] = A0.x; As[asc + 1][atr] = A0.y;
        As[asc + 2][atr] = A0.z; As[asc + 3][atr] = A0.w;
        As[asc + 4][atr] = A1.x; As[asc + 5][atr] = A1.y;
        As[asc + 6][atr] = A1.z; As[asc + 7][atr] = A1.w;
        *(float4*)&Bs[bvr][bc]      = V0;
        *(float4*)&Bs[bvr][bc + 32] = V1;
        *(float4*)&Bs[bvr][bc + 64] = V2;
        *(float4*)&Bs[bvr][bc + 96] = V3;
        __syncthreads();
        if (s + 1 < nk) {
            const float* ap2 = ap + (s + 1) * 16;
            A0 = *(const float4*)(ap2);
            A1 = *(const float4*)(ap2 + 4);
            const float* vp2 = vp + (size_t)((s + 1) * 16) * H;
            V0 = *(const float4*)(vp2 + bc);
            V1 = *(const float4*)(vp2 + bc + 32);
            V2 = *(const float4*)(vp2 + bc + 64);
            V3 = *(const float4*)(vp2 + bc + 96);
        }
#pragma unroll
        for (int kk = 0; kk < 16; kk++) {
            float4 a0 = *(const float4*)&As[kk][ty * 8];
            float4 a1 = *(const float4*)&As[kk][ty * 8 + 4];
            float4 b0 = *(const float4*)&Bs[kk][tx * 8];
            float4 b1 = *(const float4*)&Bs[kk][tx * 8 + 4];
            float a[8] = {a0.x, a0.y, a0.z, a0.w, a1.x, a1.y, a1.z, a1.w};
            float bb[8] = {b0.x, b0.y, b0.z, b0.w, b1.x, b1.y, b1.z, b1.w};
#pragma unroll
            for (int i = 0; i < 8; i++)
#pragma unroll
                for (int j = 0; j < 8; j++)
                    acc[i][j] = fmaf(a[i], bb[j], acc[i][j]);
        }
        __syncthreads();
    }
#pragma unroll
    for (int i = 0; i < 8; i++) {
        float* op = res + (size_t)(b * T + t0 + ty * 8 + i) * H + tx * 8;
        *(float4*)op       = make_float4(acc[i][0], acc[i][1], acc[i][2], acc[i][3]);
        *(float4*)(op + 4) = make_float4(acc[i][4], acc[i][5], acc[i][6], acc[i][7]);
    }
}

// ---------------------------------------------------------------------------
extern "C" void kernel_launch(void* const* d_in, const int* in_sizes, int n_in,
                              void* d_out, int out_size)
{
    const float* x  = (const float*)d_in[0];
    const float* Wq = (const float*)d_in[1];
    const float* Wk = (const float*)d_in[2];
    const float* Wv = (const float*)d_in[3];
    float* res  = (float*)d_out;
    float* attn = res + (size_t)B * T * H;

    proj_kernel<<<dim3(NR / 128, 3), 256>>>(x, Wq, Wk, Wv);
    rowsum_kernel<<<NR / 8, 256>>>();
    score_kernel<<<dim3(136, 8), 256>>>(attn);
    softmax_kernel<<<NR, 256>>>(attn);
    pv_kernel<<<dim3(32, 8), 128>>>(attn, res);
}

// round 7
// speedup vs baseline: 2.2066x; 1.3222x over previous
#include <cuda_runtime.h>
#include <math.h>
#include <stddef.h>
#include <stdint.h>

namespace {
constexpr int B = 8, T = 2048, C = 1024, H = 128;
constexpr int NR = B * T;   // 16384 rows
constexpr int LDA = 20;     // [row][k16] padded
constexpr int LDB = 136;    // [k16][n128] padded (pv V tile)
}

// scratch (device globals: allocation-free per harness rules)
__device__ float g_q[NR * H];
__device__ float g_k[NR * H];
__device__ float g_v[NR * H];
__device__ float g_sq[NR];
__device__ float g_sk[NR];

// ---------------------------------------------------------------------------
__device__ __forceinline__ float tf32r(float x) {
    uint32_t r; asm("cvt.rna.tf32.f32 %0, %1;" : "=r"(r) : "f"(x));
    return __uint_as_float(r);
}
__device__ __forceinline__ void split4(float4 v, float4& h, float4& l) {
    h.x = tf32r(v.x); h.y = tf32r(v.y); h.z = tf32r(v.z); h.w = tf32r(v.w);
    l.x = tf32r(v.x - h.x); l.y = tf32r(v.y - h.y);
    l.z = tf32r(v.z - h.z); l.w = tf32r(v.w - h.w);
}

#define MMA4(c, a, b) \
    asm volatile("mma.sync.aligned.m16n8k8.row.col.f32.tf32.tf32.f32 " \
        "{%0,%1,%2,%3},{%4,%5,%6,%7},{%8,%9},{%0,%1,%2,%3};" \
        : "+f"((c)[0]), "+f"((c)[1]), "+f"((c)[2]), "+f"((c)[3]) \
        : "r"((a)[0]), "r"((a)[1]), "r"((a)[2]), "r"((a)[3]), \
          "r"((b)[0]), "r"((b)[1]))

// Consumer fragment loads + 3-pass mma for one k8 step.
// A layout: [row][k] LDA ; B layout: [col][k] LDA  (proj/score)
#define GEMM_K8_NK(AhU, AlU, BhU, BlU, kc, wm, wn, g, acc)                    \
    do {                                                                      \
        uint32_t ah[4][4], al[4][4], bh[4][2], bl[4][2];                      \
        _Pragma("unroll")                                                     \
        for (int i = 0; i < 4; i++) {                                         \
            int r0 = (wm + 16 * i + g) * LDA + (kc);                          \
            ah[i][0] = AhU[r0];            ah[i][1] = AhU[r0 + 8 * LDA];      \
            ah[i][2] = AhU[r0 + 4];        ah[i][3] = AhU[r0 + 8 * LDA + 4];  \
            al[i][0] = AlU[r0];            al[i][1] = AlU[r0 + 8 * LDA];      \
            al[i][2] = AlU[r0 + 4];        al[i][3] = AlU[r0 + 8 * LDA + 4];  \
        }                                                                     \
        _Pragma("unroll")                                                     \
        for (int j = 0; j < 4; j++) {                                         \
            int r0 = (wn + 8 * j + g) * LDA + (kc);                           \
            bh[j][0] = BhU[r0];  bh[j][1] = BhU[r0 + 4];                      \
            bl[j][0] = BlU[r0];  bl[j][1] = BlU[r0 + 4];                      \
        }                                                                     \
        _Pragma("unroll")                                                     \
        for (int i = 0; i < 4; i++)                                           \
            _Pragma("unroll")                                                 \
            for (int j = 0; j < 4; j++) {                                     \
                MMA4(acc[i][j], ah[i], bh[j]);                                \
                MMA4(acc[i][j], al[i], bh[j]);                                \
                MMA4(acc[i][j], ah[i], bl[j]);                                \
            }                                                                 \
    } while (0)

// ---------------------------------------------------------------------------
// proj: out[NR][128] = x[NR][1024] @ W[128][1024]^T   (tf32 hi/lo, 3-pass)
__global__ __launch_bounds__(256) void proj_mma_kernel(
    const float* __restrict__ x, const float* __restrict__ Wq,
    const float* __restrict__ Wk, const float* __restrict__ Wv)
{
    __shared__ float Ah[128 * LDA], Al[128 * LDA];
    __shared__ float Bh[128 * LDA], Bl[128 * LDA];
    const int which = blockIdx.y;
    const float* W   = (which == 0) ? Wq  : (which == 1) ? Wk  : Wv;
    float*       out = (which == 0) ? g_q : (which == 1) ? g_k : g_v;
    const int m0 = blockIdx.x * 128;
    const int tid = threadIdx.x;
    const int w = tid >> 5, lane = tid & 31;
    const int wm = (w & 1) * 64, wn = (w >> 1) * 32;
    const int g = lane >> 2, t = lane & 3;
    const int pr = tid >> 1, pk = (tid & 1) * 8;

    const float* ap = x + (size_t)(m0 + pr) * C + pk;
    const float* bp = W + (size_t)pr * C + pk;

    float4 rA0 = *(const float4*)ap, rA1 = *(const float4*)(ap + 4);
    float4 rB0 = *(const float4*)bp, rB1 = *(const float4*)(bp + 4);

    float acc[4][4][4];
#pragma unroll
    for (int i = 0; i < 4; i++)
#pragma unroll
        for (int j = 0; j < 4; j++)
#pragma unroll
            for (int q = 0; q < 4; q++) acc[i][j][q] = 0.f;

    const int NS = C / 16;
    for (int s = 0; s < NS; s++) {
        float4 h, l;
        split4(rA0, h, l); *(float4*)&Ah[pr * LDA + pk] = h; *(float4*)&Al[pr * LDA + pk] = l;
        split4(rA1, h, l); *(float4*)&Ah[pr * LDA + pk + 4] = h; *(float4*)&Al[pr * LDA + pk + 4] = l;
        split4(rB0, h, l); *(float4*)&Bh[pr * LDA + pk] = h; *(float4*)&Bl[pr * LDA + pk] = l;
        split4(rB1, h, l); *(float4*)&Bh[pr * LDA + pk + 4] = h; *(float4*)&Bl[pr * LDA + pk + 4] = l;
        __syncthreads();
        if (s + 1 < NS) {
            rA0 = *(const float4*)(ap + (s + 1) * 16);
            rA1 = *(const float4*)(ap + (s + 1) * 16 + 4);
            rB0 = *(const float4*)(bp + (s + 1) * 16);
            rB1 = *(const float4*)(bp + (s + 1) * 16 + 4);
        }
        const uint32_t* AhU = (const uint32_t*)Ah;
        const uint32_t* AlU = (const uint32_t*)Al;
        const uint32_t* BhU = (const uint32_t*)Bh;
        const uint32_t* BlU = (const uint32_t*)Bl;
#pragma unroll
        for (int ks = 0; ks < 2; ks++) {
            int kc = ks * 8 + t;
            GEMM_K8_NK(AhU, AlU, BhU, BlU, kc, wm, wn, g, acc);
        }
        __syncthreads();
    }
#pragma unroll
    for (int i = 0; i < 4; i++)
#pragma unroll
        for (int j = 0; j < 4; j++) {
            int row = m0 + wm + 16 * i + g;
            int col = wn + 8 * j + 2 * t;
            *(float2*)&out[(size_t)row * H + col]       = make_float2(acc[i][j][0], acc[i][j][1]);
            *(float2*)&out[(size_t)(row + 8) * H + col] = make_float2(acc[i][j][2], acc[i][j][3]);
        }
}

// ---------------------------------------------------------------------------
// per-row feature sums of q and k (pos decomposition)
__global__ __launch_bounds__(256) void rowsum_kernel()
{
    int w = (blockIdx.x * blockDim.x + threadIdx.x) >> 5;
    int lane = threadIdx.x & 31;
    if (w >= NR) return;
    float4 q = *(const float4*)&g_q[(size_t)w * H + lane * 4];
    float4 k = *(const float4*)&g_k[(size_t)w * H + lane * 4];
    float sq = q.x + q.y + q.z + q.w;
    float sk = k.x + k.y + k.z + k.w;
#pragma unroll
    for (int o = 16; o > 0; o >>= 1) {
        sq += __shfl_xor_sync(0xffffffffu, sq, o);
        sk += __shfl_xor_sync(0xffffffffu, sk, o);
    }
    if (lane == 0) { g_sq[w] = sq; g_sk[w] = sk; }
}

// ---------------------------------------------------------------------------
// score: raw S = q.k over lower-band 128x128 tiles (tf32 hi/lo)
__global__ __launch_bounds__(256) void score_mma_kernel(float* __restrict__ attn)
{
    __shared__ float Ah[128 * LDA], Al[128 * LDA];
    __shared__ float Bh[128 * LDA], Bl[128 * LDA];
    const int b = blockIdx.y;
    const int idx = blockIdx.x;
    int ti = (int)((sqrtf(8.f * (float)idx + 1.f) - 1.f) * 0.5f);
    if (ti > 15) ti = 15;
    while ((ti + 1) * (ti + 2) / 2 <= idx) ti++;
    while (ti * (ti + 1) / 2 > idx) ti--;
    const int tj = idx - ti * (ti + 1) / 2;
    const int t0 = ti * 128, s0 = tj * 128;

    const int tid = threadIdx.x;
    const int w = tid >> 5, lane = tid & 31;
    const int wm = (w & 1) * 64, wn = (w >> 1) * 32;
    const int g = lane >> 2, t = lane & 3;
    const int pr = tid >> 1, pk = (tid & 1) * 8;

    const float* ap = g_q + (size_t)(b * T + t0 + pr) * H + pk;
    const float* bp = g_k + (size_t)(b * T + s0 + pr) * H + pk;

    float4 rA0 = *(const float4*)ap, rA1 = *(const float4*)(ap + 4);
    float4 rB0 = *(const float4*)bp, rB1 = *(const float4*)(bp + 4);

    float acc[4][4][4];
#pragma unroll
    for (int i = 0; i < 4; i++)
#pragma unroll
        for (int j = 0; j < 4; j++)
#pragma unroll
            for (int q = 0; q < 4; q++) acc[i][j][q] = 0.f;

    const int NS = H / 16;  // 8
    for (int s = 0; s < NS; s++) {
        float4 h, l;
        split4(rA0, h, l); *(float4*)&Ah[pr * LDA + pk] = h; *(float4*)&Al[pr * LDA + pk] = l;
        split4(rA1, h, l); *(float4*)&Ah[pr * LDA + pk + 4] = h; *(float4*)&Al[pr * LDA + pk + 4] = l;
        split4(rB0, h, l); *(float4*)&Bh[pr * LDA + pk] = h; *(float4*)&Bl[pr * LDA + pk] = l;
        split4(rB1, h, l); *(float4*)&Bh[pr * LDA + pk + 4] = h; *(float4*)&Bl[pr * LDA + pk + 4] = l;
        __syncthreads();
        if (s + 1 < NS) {
            rA0 = *(const float4*)(ap + (s + 1) * 16);
            rA1 = *(const float4*)(ap + (s + 1) * 16 + 4);
            rB0 = *(const float4*)(bp + (s + 1) * 16);
            rB1 = *(const float4*)(bp + (s + 1) * 16 + 4);
        }
        const uint32_t* AhU = (const uint32_t*)Ah;
        const uint32_t* AlU = (const uint32_t*)Al;
        const uint32_t* BhU = (const uint32_t*)Bh;
        const uint32_t* BlU = (const uint32_t*)Bl;
#pragma unroll
        for (int ks = 0; ks < 2; ks++) {
            int kc = ks * 8 + t;
            GEMM_K8_NK(AhU, AlU, BhU, BlU, kc, wm, wn, g, acc);
        }
        __syncthreads();
    }
#pragma unroll
    for (int i = 0; i < 4; i++)
#pragma unroll
        for (int j = 0; j < 4; j++) {
            int row = t0 + wm + 16 * i + g;
            int col = s0 + wn + 8 * j + 2 * t;
            float* op0 = attn + (size_t)(b * T + row) * T + col;
            float* op1 = attn + (size_t)(b * T + row + 8) * T + col;
            *(float2*)op0 = make_float2(acc[i][j][0], acc[i][j][1]);
            *(float2*)op1 = make_float2(acc[i][j][2], acc[i][j][3]);
        }
}

// ---------------------------------------------------------------------------
// softmax: in-place per row; adds pos terms, masks, normalizes.
__global__ __launch_bounds__(256) void softmax_kernel(float* __restrict__ attn)
{
    __shared__ float red[8];
    const int r = blockIdx.x;
    const int b = r >> 11;
    const int t = r & (T - 1);
    float* row = attn + (size_t)r * T;
    const float* skrow = g_sk + (size_t)b * T;
    const float sq = g_sq[r];
    const float tf = (float)t;
    const int tid = threadIdx.x;
    const int c0 = tid * 8;

    float4 v0 = *(const float4*)(row + c0);
    float4 v1 = *(const float4*)(row + c0 + 4);
    float4 s0 = *(const float4*)(skrow + c0);
    float4 s1 = *(const float4*)(skrow + c0 + 4);
    float qk[8] = {v0.x, v0.y, v0.z, v0.w, v1.x, v1.y, v1.z, v1.w};
    float sk[8] = {s0.x, s0.y, s0.z, s0.w, s1.x, s1.y, s1.z, s1.w};

    float lg[8];
    float mx = -INFINITY;
#pragma unroll
    for (int j = 0; j < 8; j++) {
        int s = c0 + j;
        float v = (qk[j] + (float)s * sq + tf * sk[j] + 128.f * (float)(t * s)) * 0.03125f;
        lg[j] = (s <= t) ? v : -INFINITY;
        mx = fmaxf(mx, lg[j]);
    }
#pragma unroll
    for (int o = 16; o > 0; o >>= 1)
        mx = fmaxf(mx, __shfl_xor_sync(0xffffffffu, mx, o));
    if ((tid & 31) == 0) red[tid >> 5] = mx;
    __syncthreads();
    float m = red[0];
#pragma unroll
    for (int i = 1; i < 8; i++) m = fmaxf(m, red[i]);
    __syncthreads();

    float ev[8];
    float sum = 0.f;
#pragma unroll
    for (int j = 0; j < 8; j++) {
        ev[j] = __expf(lg[j] - m);
        sum += ev[j];
    }
#pragma unroll
    for (int o = 16; o > 0; o >>= 1)
        sum += __shfl_xor_sync(0xffffffffu, sum, o);
    if ((tid & 31) == 0) red[tid >> 5] = sum;
    __syncthreads();
    float tot = red[0];
#pragma unroll
    for (int i = 1; i < 8; i++) tot += red[i];
    const float rinv = 1.f / tot;

    *(float4*)(row + c0)     = make_float4(ev[0] * rinv, ev[1] * rinv, ev[2] * rinv, ev[3] * rinv);
    *(float4*)(row + c0 + 4) = make_float4(ev[4] * rinv, ev[5] * rinv, ev[6] * rinv, ev[7] * rinv);
}

// ---------------------------------------------------------------------------
// pv: res += attn_chunk @ v_chunk  (tf32 hi/lo, split-K via 256-wide s-chunks,
// atomicAdd accumulation into zeroed res)
__global__ __launch_bounds__(256) void pv_mma_kernel(
    const float* __restrict__ attn, float* __restrict__ res)
{
    __shared__ float Ah[128 * LDA], Al[128 * LDA];
    __shared__ float Bh[16 * LDB], Bl[16 * LDB];
    const int b = blockIdx.y;
    int bx = blockIdx.x;
    int kt = 15, chunk = 0;
#pragma unroll
    for (int k = 15; k >= 0; k--) {
        int cnt = (k + 2) >> 1;          // ceil((k+1)/2) 256-chunks
        if (bx < cnt) { kt = k; chunk = bx; break; }
        bx -= cnt;
    }
    const int t0 = kt * 128;
    const int sbeg = chunk * 256;
    const int send = min(sbeg + 256, (kt + 1) * 128);
    const int NS = (send - sbeg) >> 4;

    const int tid = threadIdx.x;
    const int w = tid >> 5, lane = tid & 31;
    const int wm = (w & 1) * 64, wn = (w >> 1) * 32;
    const int g = lane >> 2, t = lane & 3;
    const int pr = tid >> 1, pk = (tid & 1) * 8;       // A loader
    const int vr = tid >> 4, vc = (tid & 15) * 8;      // B (V) loader

    const float* ap = attn + (size_t)(b * T + t0 + pr) * T + sbeg + pk;
    const float* bp = g_v + (size_t)(b * T + sbeg + vr) * H + vc;

    float4 rA0 = *(const float4*)ap, rA1 = *(const float4*)(ap + 4);
    float4 rB0 = *(const float4*)bp, rB1 = *(const float4*)(bp + 4);

    float acc[4][4][4];
#pragma unroll
    for (int i = 0; i < 4; i++)
#pragma unroll
        for (int j = 0; j < 4; j++)
#pragma unroll
            for (int q = 0; q < 4; q++) acc[i][j][q] = 0.f;

    for (int s = 0; s < NS; s++) {
        float4 h, l;
        split4(rA0, h, l); *(float4*)&Ah[pr * LDA + pk] = h; *(float4*)&Al[pr * LDA + pk] = l;
        split4(rA1, h, l); *(float4*)&Ah[pr * LDA + pk + 4] = h; *(float4*)&Al[pr * LDA + pk + 4] = l;
        split4(rB0, h, l); *(float4*)&Bh[vr * LDB + vc] = h; *(float4*)&Bl[vr * LDB + vc] = l;
        split4(rB1, h, l); *(float4*)&Bh[vr * LDB + vc + 4] = h; *(float4*)&Bl[vr * LDB + vc + 4] = l;
        __syncthreads();
        if (s + 1 < NS) {
            rA0 = *(const float4*)(ap + (s + 1) * 16);
            rA1 = *(const float4*)(ap + (s + 1) * 16 + 4);
            const float* bp2 = bp + (size_t)(s + 1) * 16 * H;
            rB0 = *(const float4*)(bp2);
            rB1 = *(const float4*)(bp2 + 4);
        }
        const uint32_t* AhU = (const uint32_t*)Ah;
        const uint32_t* AlU = (const uint32_t*)Al;
        const uint32_t* BhU = (const uint32_t*)Bh;
        const uint32_t* BlU = (const uint32_t*)Bl;
#pragma unroll
        for (int ks = 0; ks < 2; ks++) {
            int kc = ks * 8 + t;
            uint32_t ah[4][4], al[4][4], bh[4][2], bl[4][2];
#pragma unroll
            for (int i = 0; i < 4; i++) {
                int r0 = (wm + 16 * i + g) * LDA + kc;
                ah[i][0] = AhU[r0];     ah[i][1] = AhU[r0 + 8 * LDA];
                ah[i][2] = AhU[r0 + 4]; ah[i][3] = AhU[r0 + 8 * LDA + 4];
                al[i][0] = AlU[r0];     al[i][1] = AlU[r0 + 8 * LDA];
                al[i][2] = AlU[r0 + 4]; al[i][3] = AlU[r0 + 8 * LDA + 4];
            }
#pragma unroll
            for (int j = 0; j < 4; j++) {
                int c0i = kc * LDB + wn + 8 * j + g;
                bh[j][0] = BhU[c0i];  bh[j][1] = BhU[c0i + 4 * LDB];
                bl[j][0] = BlU[c0i];  bl[j][1] = BlU[c0i + 4 * LDB];
            }
#pragma unroll
            for (int i = 0; i < 4; i++)
#pragma unroll
                for (int j = 0; j < 4; j++) {
                    MMA4(acc[i][j], ah[i], bh[j]);
                    MMA4(acc[i][j], al[i], bh[j]);
                    MMA4(acc[i][j], ah[i], bl[j]);
                }
        }
        __syncthreads();
    }
#pragma unroll
    for (int i = 0; i < 4; i++)
#pragma unroll
        for (int j = 0; j < 4; j++) {
            int row = t0 + wm + 16 * i + g;
            int col = wn + 8 * j + 2 * t;
            float* p0 = res + (size_t)(b * T + row) * H + col;
            float* p1 = res + (size_t)(b * T + row + 8) * H + col;
            atomicAdd(p0,     acc[i][j][0]);
            atomicAdd(p0 + 1, acc[i][j][1]);
            atomicAdd(p1,     acc[i][j][2]);
            atomicAdd(p1 + 1, acc[i][j][3]);
        }
}

// ---------------------------------------------------------------------------
extern "C" void kernel_launch(void* const* d_in, const int* in_sizes, int n_in,
                              void* d_out, int out_size)
{
    const float* x  = (const float*)d_in[0];
    const float* Wq = (const float*)d_in[1];
    const float* Wk = (const float*)d_in[2];
    const float* Wv = (const float*)d_in[3];
    float* res  = (float*)d_out;
    float* attn = res + (size_t)B * T * H;

    cudaMemsetAsync(res, 0, (size_t)NR * H * sizeof(float));
    proj_mma_kernel<<<dim3(NR / 128, 3), 256>>>(x, Wq, Wk, Wv);
    rowsum_kernel<<<NR / 8, 256>>>();
    score_mma_kernel<<<dim3(136, 8), 256>>>(attn);
    softmax_kernel<<<NR, 256>>>(attn);
    pv_mma_kernel<<<dim3(72, 8), 256>>>(attn, res);
}

// round 9
// speedup vs baseline: 3.2730x; 1.4832x over previous
#include <cuda_runtime.h>
#include <cuda_fp16.h>
#include <math.h>
#include <stddef.h>
#include <stdint.h>

namespace {
constexpr int B = 8, T = 2048, C = 1024, H = 128;
constexpr int NR = B * T;   // 16384 rows
constexpr int LD = 12;      // smem row stride in u32 (k-pairs), bank-conflict-free
}

// scratch (device globals: allocation-free per harness rules)
__device__ float    g_q[NR * H];
__device__ float    g_k[NR * H];
__device__ float    g_v[NR * H];
__device__ float    g_sq[NR];
__device__ float    g_sk[NR];
// pre-split packed half2 (k-pair) operands
__device__ uint32_t g_qh[NR * 64], g_ql[NR * 64];
__device__ uint32_t g_kh[NR * 64], g_kl[NR * 64];
__device__ uint32_t g_vh[NR * 64], g_vl[NR * 64];   // plain h-order halves

// ---------------------------------------------------------------------------
__device__ __forceinline__ void splitH4(float4 v, uint32_t& h0, uint32_t& h1,
                                        uint32_t& l0, uint32_t& l1) {
    __half2 a = __floats2half2_rn(v.x, v.y);
    __half2 b = __floats2half2_rn(v.z, v.w);
    float2 af = __half22float2(a), bf = __half22float2(b);
    __half2 al = __floats2half2_rn(v.x - af.x, v.y - af.y);
    __half2 bl = __floats2half2_rn(v.z - bf.x, v.w - bf.y);
    h0 = *(uint32_t*)&a;  h1 = *(uint32_t*)&b;
    l0 = *(uint32_t*)&al; l1 = *(uint32_t*)&bl;
}

#define MMAH(c, a, b) \
    asm volatile("mma.sync.aligned.m16n8k16.row.col.f32.f16.f16.f32 " \
        "{%0,%1,%2,%3},{%4,%5,%6,%7},{%8,%9},{%0,%1,%2,%3};" \
        : "+f"((c)[0]), "+f"((c)[1]), "+f"((c)[2]), "+f"((c)[3]) \
        : "r"((a)[0]), "r"((a)[1]), "r"((a)[2]), "r"((a)[3]), \
          "r"((b)[0]), "r"((b)[1]))

// one k16 slab: A [row][kpair] LD, B [n][kpair] LD, 3-pass hi/lo
__device__ __forceinline__ void mma_slab(
    const uint32_t* __restrict__ AhU, const uint32_t* __restrict__ AlU,
    const uint32_t* __restrict__ BhU, const uint32_t* __restrict__ BlU,
    int wm, int wn, int g, int t, float acc[4][4][4])
{
    uint32_t ah[4][4], al[4][4], bh[4][2], bl[4][2];
#pragma unroll
    for (int i = 0; i < 4; i++) {
        int r0 = (wm + 16 * i + g) * LD + t;
        ah[i][0] = AhU[r0];     ah[i][1] = AhU[r0 + 8 * LD];
        ah[i][2] = AhU[r0 + 4]; ah[i][3] = AhU[r0 + 8 * LD + 4];
        al[i][0] = AlU[r0];     al[i][1] = AlU[r0 + 8 * LD];
        al[i][2] = AlU[r0 + 4]; al[i][3] = AlU[r0 + 8 * LD + 4];
    }
#pragma unroll
    for (int j = 0; j < 4; j++) {
        int r0 = (wn + 8 * j + g) * LD + t;
        bh[j][0] = BhU[r0]; bh[j][1] = BhU[r0 + 4];
        bl[j][0] = BlU[r0]; bl[j][1] = BlU[r0 + 4];
    }
#pragma unroll
    for (int i = 0; i < 4; i++)
#pragma unroll
        for (int j = 0; j < 4; j++) {
            MMAH(acc[i][j], ah[i], bh[j]);
            MMAH(acc[i][j], al[i], bh[j]);
            MMAH(acc[i][j], ah[i], bl[j]);
        }
}

// ---------------------------------------------------------------------------
// proj: out[NR][128] = x[NR][1024] @ W[128][1024]^T   (fp16 hi/lo, 3-pass)
__global__ __launch_bounds__(256) void proj_mma_kernel(
    const float* __restrict__ x, const float* __restrict__ Wq,
    const float* __restrict__ Wk, const float* __restrict__ Wv)
{
    __shared__ uint32_t Ah[128 * LD], Al[128 * LD];
    __shared__ uint32_t Bh[128 * LD], Bl[128 * LD];
    const int which = blockIdx.y;
    const float* W   = (which == 0) ? Wq  : (which == 1) ? Wk  : Wv;
    float*       out = (which == 0) ? g_q : (which == 1) ? g_k : g_v;
    const int m0 = blockIdx.x * 128;
    const int tid = threadIdx.x;
    const int w = tid >> 5, lane = tid & 31;
    const int wm = (w & 1) * 64, wn = (w >> 1) * 32;
    const int g = lane >> 2, t = lane & 3;
    const int pr = tid >> 1, pc = (tid & 1) * 4;   // pc in u32 pairs (0 or 4)

    const float* ap = x + (size_t)(m0 + pr) * C + pc * 2;
    const float* bp = W + (size_t)pr * C + pc * 2;

    float4 rA0 = *(const float4*)ap, rA1 = *(const float4*)(ap + 4);
    float4 rB0 = *(const float4*)bp, rB1 = *(const float4*)(bp + 4);

    float acc[4][4][4];
#pragma unroll
    for (int i = 0; i < 4; i++)
#pragma unroll
        for (int j = 0; j < 4; j++)
#pragma unroll
            for (int q = 0; q < 4; q++) acc[i][j][q] = 0.f;

    const int NS = C / 16;
    for (int s = 0; s < NS; s++) {
        uint32_t h0, h1, h2, h3, l0, l1, l2, l3;
        splitH4(rA0, h0, h1, l0, l1); splitH4(rA1, h2, h3, l2, l3);
        *(uint4*)&Ah[pr * LD + pc] = make_uint4(h0, h1, h2, h3);
        *(uint4*)&Al[pr * LD + pc] = make_uint4(l0, l1, l2, l3);
        splitH4(rB0, h0, h1, l0, l1); splitH4(rB1, h2, h3, l2, l3);
        *(uint4*)&Bh[pr * LD + pc] = make_uint4(h0, h1, h2, h3);
        *(uint4*)&Bl[pr * LD + pc] = make_uint4(l0, l1, l2, l3);
        __syncthreads();
        if (s + 1 < NS) {
            rA0 = *(const float4*)(ap + (s + 1) * 16);
            rA1 = *(const float4*)(ap + (s + 1) * 16 + 4);
            rB0 = *(const float4*)(bp + (s + 1) * 16);
            rB1 = *(const float4*)(bp + (s + 1) * 16 + 4);
        }
        mma_slab(Ah, Al, Bh, Bl, wm, wn, g, t, acc);
        __syncthreads();
    }
#pragma unroll
    for (int i = 0; i < 4; i++)
#pragma unroll
        for (int j = 0; j < 4; j++) {
            int row = m0 + wm + 16 * i + g;
            int col = wn + 8 * j + 2 * t;
            *(float2*)&out[(size_t)row * H + col]       = make_float2(acc[i][j][0], acc[i][j][1]);
            *(float2*)&out[(size_t)(row + 8) * H + col] = make_float2(acc[i][j][2], acc[i][j][3]);
        }
}

// ---------------------------------------------------------------------------
// split+rowsum: per-row sums of q,k (pos decomposition) + pre-split q,k,v
__global__ __launch_bounds__(256) void split_kernel()
{
    int w = (blockIdx.x * blockDim.x + threadIdx.x) >> 5;
    int lane = threadIdx.x & 31;
    if (w >= NR) return;
    float4 q = *(const float4*)&g_q[(size_t)w * H + lane * 4];
    float4 k = *(const float4*)&g_k[(size_t)w * H + lane * 4];
    float4 v = *(const float4*)&g_v[(size_t)w * H + lane * 4];
    float sq = q.x + q.y + q.z + q.w;
    float sk = k.x + k.y + k.z + k.w;
#pragma unroll
    for (int o = 16; o > 0; o >>= 1) {
        sq += __shfl_xor_sync(0xffffffffu, sq, o);
        sk += __shfl_xor_sync(0xffffffffu, sk, o);
    }
    if (lane == 0) { g_sq[w] = sq; g_sk[w] = sk; }

    uint32_t h0, h1, l0, l1;
    const int idx = w * 32 + lane;
    splitH4(q, h0, h1, l0, l1);
    ((uint2*)g_qh)[idx] = make_uint2(h0, h1);
    ((uint2*)g_ql)[idx] = make_uint2(l0, l1);
    splitH4(k, h0, h1, l0, l1);
    ((uint2*)g_kh)[idx] = make_uint2(h0, h1);
    ((uint2*)g_kl)[idx] = make_uint2(l0, l1);
    splitH4(v, h0, h1, l0, l1);
    ((uint2*)g_vh)[idx] = make_uint2(h0, h1);
    ((uint2*)g_vl)[idx] = make_uint2(l0, l1);
}

// ---------------------------------------------------------------------------
// score: raw S = q.k over lower-band 128x128 tiles (fp16 hi/lo, pre-split)
__global__ __launch_bounds__(256) void score_mma_kernel(float* __restrict__ attn)
{
    __shared__ uint32_t Ah[128 * LD], Al[128 * LD];
    __shared__ uint32_t Bh[128 * LD], Bl[128 * LD];
    const int b = blockIdx.y;
    const int idx = blockIdx.x;
    int ti = (int)((sqrtf(8.f * (float)idx + 1.f) - 1.f) * 0.5f);
    if (ti > 15) ti = 15;
    while ((ti + 1) * (ti + 2) / 2 <= idx) ti++;
    while (ti * (ti + 1) / 2 > idx) ti--;
    const int tj = idx - ti * (ti + 1) / 2;
    const int t0 = ti * 128, s0 = tj * 128;

    const int tid = threadIdx.x;
    const int w = tid >> 5, lane = tid & 31;
    const int wm = (w & 1) * 64, wn = (w >> 1) * 32;
    const int g = lane >> 2, t = lane & 3;
    const int pr = tid >> 1, pc = (tid & 1) * 4;

    const uint32_t* qh = g_qh + (size_t)(b * T + t0 + pr) * 64 + pc;
    const uint32_t* ql = g_ql + (size_t)(b * T + t0 + pr) * 64 + pc;
    const uint32_t* kh = g_kh + (size_t)(b * T + s0 + pr) * 64 + pc;
    const uint32_t* kl = g_kl + (size_t)(b * T + s0 + pr) * 64 + pc;

    uint4 rAh = *(const uint4*)qh, rAl = *(const uint4*)ql;
    uint4 rBh = *(const uint4*)kh, rBl = *(const uint4*)kl;

    float acc[4][4][4];
#pragma unroll
    for (int i = 0; i < 4; i++)
#pragma unroll
        for (int j = 0; j < 4; j++)
#pragma unroll
            for (int q = 0; q < 4; q++) acc[i][j][q] = 0.f;

    const int NS = H / 16;  // 8
    for (int s = 0; s < NS; s++) {
        *(uint4*)&Ah[pr * LD + pc] = rAh;
        *(uint4*)&Al[pr * LD + pc] = rAl;
        *(uint4*)&Bh[pr * LD + pc] = rBh;
        *(uint4*)&Bl[pr * LD + pc] = rBl;
        __syncthreads();
        if (s + 1 < NS) {
            rAh = *(const uint4*)(qh + (s + 1) * 8);
            rAl = *(const uint4*)(ql + (s + 1) * 8);
            rBh = *(const uint4*)(kh + (s + 1) * 8);
            rBl = *(const uint4*)(kl + (s + 1) * 8);
        }
        mma_slab(Ah, Al, Bh, Bl, wm, wn, g, t, acc);
        __syncthreads();
    }
#pragma unroll
    for (int i = 0; i < 4; i++)
#pragma unroll
        for (int j = 0; j < 4; j++) {
            int row = t0 + wm + 16 * i + g;
            int col = s0 + wn + 8 * j + 2 * t;
            *(float2*)&attn[(size_t)(b * T + row) * T + col]     = make_float2(acc[i][j][0], acc[i][j][1]);
            *(float2*)&attn[(size_t)(b * T + row + 8) * T + col] = make_float2(acc[i][j][2], acc[i][j][3]);
        }
}

// ---------------------------------------------------------------------------
// softmax: in-place per row; adds pos terms, masks, normalizes.
__global__ __launch_bounds__(256) void softmax_kernel(float* __restrict__ attn)
{
    __shared__ float red[8];
    const int r = blockIdx.x;
    const int b = r >> 11;
    const int t = r & (T - 1);
    float* row = attn + (size_t)r * T;
    const float* skrow = g_sk + (size_t)b * T;
    const float sq = g_sq[r];
    const float tf = (float)t;
    const int tid = threadIdx.x;
    const int c0 = tid * 8;

    float4 v0 = *(const float4*)(row + c0);
    float4 v1 = *(const float4*)(row + c0 + 4);
    float4 s0 = *(const float4*)(skrow + c0);
    float4 s1 = *(const float4*)(skrow + c0 + 4);
    float qk[8] = {v0.x, v0.y, v0.z, v0.w, v1.x, v1.y, v1.z, v1.w};
    float sk[8] = {s0.x, s0.y, s0.z, s0.w, s1.x, s1.y, s1.z, s1.w};

    float lg[8];
    float mx = -INFINITY;
#pragma unroll
    for (int j = 0; j < 8; j++) {
        int s = c0 + j;
        float v = (qk[j] + (float)s * sq + tf * sk[j] + 128.f * (float)(t * s)) * 0.03125f;
        lg[j] = (s <= t) ? v : -INFINITY;
        mx = fmaxf(mx, lg[j]);
    }
#pragma unroll
    for (int o = 16; o > 0; o >>= 1)
        mx = fmaxf(mx, __shfl_xor_sync(0xffffffffu, mx, o));
    if ((tid & 31) == 0) red[tid >> 5] = mx;
    __syncthreads();
    float m = red[0];
#pragma unroll
    for (int i = 1; i < 8; i++) m = fmaxf(m, red[i]);
    __syncthreads();

    float ev[8];
    float sum = 0.f;
#pragma unroll
    for (int j = 0; j < 8; j++) {
        ev[j] = __expf(lg[j] - m);
        sum += ev[j];
    }
#pragma unroll
    for (int o = 16; o > 0; o >>= 1)
        sum += __shfl_xor_sync(0xffffffffu, sum, o);
    if ((tid & 31) == 0) red[tid >> 5] = sum;
    __syncthreads();
    float tot = red[0];
#pragma unroll
    for (int i = 1; i < 8; i++) tot += red[i];
    const float rinv = 1.f / tot;

    *(float4*)(row + c0)     = make_float4(ev[0] * rinv, ev[1] * rinv, ev[2] * rinv, ev[3] * rinv);
    *(float4*)(row + c0 + 4) = make_float4(ev[4] * rinv, ev[5] * rinv, ev[6] * rinv, ev[7] * rinv);
}

// ---------------------------------------------------------------------------
// pv: res += attn_chunk @ v_chunk  (fp16 hi/lo 3-pass, split-K 256-wide chunks,
// atomicAdd into zeroed res). B staged transposed: Bs[h][s-pair].
__global__ __launch_bounds__(256) void pv_mma_kernel(
    const float* __restrict__ attn, float* __restrict__ res)
{
    __shared__ uint32_t Ah[128 * LD], Al[128 * LD];
    __shared__ uint32_t Bh[128 * LD], Bl[128 * LD];
    const int b = blockIdx.y;
    int bx = blockIdx.x;
    int kt = 15, chunk = 0;
#pragma unroll
    for (int k = 15; k >= 0; k--) {
        int cnt = (k + 2) >> 1;
        if (bx < cnt) { kt = k; chunk = bx; break; }
        bx -= cnt;
    }
    const int t0 = kt * 128;
    const int sbeg = chunk * 256;
    const int send = min(sbeg + 256, (kt + 1) * 128);
    const int NS = (send - sbeg) >> 4;

    const int tid = threadIdx.x;
    const int w = tid >> 5, lane = tid & 31;
    const int wm = (w & 1) * 64, wn = (w >> 1) * 32;
    const int g = lane >> 2, t = lane & 3;
    const int pr = tid >> 1, pc = (tid & 1) * 4;   // A stager
    const int sp = tid & 7, hq = tid >> 3;         // B stager: s-pair, h-quad

    const float* ap = attn + (size_t)(b * T + t0 + pr) * T + sbeg + pc * 2;
    const uint32_t* vh = g_vh + (size_t)(b * T + sbeg + 2 * sp) * 64 + 2 * hq;
    const uint32_t* vl = g_vl + (size_t)(b * T + sbeg + 2 * sp) * 64 + 2 * hq;

    float4 rA0 = *(const float4*)ap, rA1 = *(const float4*)(ap + 4);
    uint2 rha = *(const uint2*)vh,        rhb = *(const uint2*)(vh + 64);
    uint2 rla = *(const uint2*)vl,        rlb = *(const uint2*)(vl + 64);

    float acc[4][4][4];
#pragma unroll
    for (int i = 0; i < 4; i++)
#pragma unroll
        for (int j = 0; j < 4; j++)
#pragma unroll
            for (int q = 0; q < 4; q++) acc[i][j][q] = 0.f;

    for (int s = 0; s < NS; s++) {
        uint32_t h0, h1, h2, h3, l0, l1, l2, l3;
        splitH4(rA0, h0, h1, l0, l1); splitH4(rA1, h2, h3, l2, l3);
        *(uint4*)&Ah[pr * LD + pc] = make_uint4(h0, h1, h2, h3);
        *(uint4*)&Al[pr * LD + pc] = make_uint4(l0, l1, l2, l3);
        // transpose-pack V: (row s, row s+1) halves -> k-pair u32 per h
        Bh[(4 * hq + 0) * LD + sp] = __byte_perm(rha.x, rhb.x, 0x5410);
        Bh[(4 * hq + 1) * LD + sp] = __byte_perm(rha.x, rhb.x, 0x7632);
        Bh[(4 * hq + 2) * LD + sp] = __byte_perm(rha.y, rhb.y, 0x5410);
        Bh[(4 * hq + 3) * LD + sp] = __byte_perm(rha.y, rhb.y, 0x7632);
        Bl[(4 * hq + 0) * LD + sp] = __byte_perm(rla.x, rlb.x, 0x5410);
        Bl[(4 * hq + 1) * LD + sp] = __byte_perm(rla.x, rlb.x, 0x7632);
        Bl[(4 * hq + 2) * LD + sp] = __byte_perm(rla.y, rlb.y, 0x5410);
        Bl[(4 * hq + 3) * LD + sp] = __byte_perm(rla.y, rlb.y, 0x7632);
        __syncthreads();
        if (s + 1 < NS) {
            rA0 = *(const float4*)(ap + (s + 1) * 16);
            rA1 = *(const float4*)(ap + (s + 1) * 16 + 4);
            const uint32_t* vh2 = vh + (size_t)(s + 1) * 16 * 64;
            const uint32_t* vl2 = vl + (size_t)(s + 1) * 16 * 64;
            rha = *(const uint2*)vh2; rhb = *(const uint2*)(vh2 + 64);
            rla = *(const uint2*)vl2; rlb = *(const uint2*)(vl2 + 64);
        }
        mma_slab(Ah, Al, Bh, Bl, wm, wn, g, t, acc);
        __syncthreads();
    }
#pragma unroll
    for (int i = 0; i < 4; i++)
#pragma unroll
        for (int j = 0; j < 4; j++) {
            int row = t0 + wm + 16 * i + g;
            int col = wn + 8 * j + 2 * t;
            float* p0 = res + (size_t)(b * T + row) * H + col;
            float* p1 = res + (size_t)(b * T + row + 8) * H + col;
            atomicAdd(p0,     acc[i][j][0]);
            atomicAdd(p0 + 1, acc[i][j][1]);
            atomicAdd(p1,     acc[i][j][2]);
            atomicAdd(p1 + 1, acc[i][j][3]);
        }
}

// ---------------------------------------------------------------------------
extern "C" void kernel_launch(void* const* d_in, const int* in_sizes, int n_in,
                              void* d_out, int out_size)
{
    const float* x  = (const float*)d_in[0];
    const float* Wq = (const float*)d_in[1];
    const float* Wk = (const float*)d_in[2];
    const float* Wv = (const float*)d_in[3];
    float* res  = (float*)d_out;
    float* attn = res + (size_t)B * T * H;

    cudaMemsetAsync(res, 0, (size_t)NR * H * sizeof(float));
    proj_mma_kernel<<<dim3(NR / 128, 3), 256>>>(x, Wq, Wk, Wv);
    split_kernel<<<NR / 8, 256>>>();
    score_mma_kernel<<<dim3(136, 8), 256>>>(attn);
    softmax_kernel<<<NR, 256>>>(attn);
    pv_mma_kernel<<<dim3(72, 8), 256>>>(attn, res);
}

// round 11
// speedup vs baseline: 3.2892x; 1.0050x over previous
#include <cuda_runtime.h>
#include <cuda_fp16.h>
#include <math.h>
#include <stddef.h>
#include <stdint.h>

// NOTE: harness builds via compute_103 virtual arch -> tcgen05/TMEM PTX is
// rejected by ptxas. mma.sync (HMMA) is the available tensor path.

namespace {
constexpr int B = 8, T = 2048, C = 1024, H = 128;
constexpr int NR = B * T;   // 16384 rows
constexpr int LD = 12;      // smem row stride in u32 (k-pairs), bank-conflict-free
}

// scratch (device globals: allocation-free per harness rules)
__device__ float    g_q[NR * H];
__device__ float    g_k[NR * H];
__device__ float    g_v[NR * H];
__device__ float    g_sq[NR];
__device__ float    g_sk[NR];
// pre-split packed half2 (k-pair) operands
__device__ uint32_t g_qh[NR * 64], g_ql[NR * 64];
__device__ uint32_t g_kh[NR * 64], g_kl[NR * 64];
__device__ uint32_t g_vh[NR * 64], g_vl[NR * 64];   // plain h-order halves

// ---------------------------------------------------------------------------
__device__ __forceinline__ void splitH4(float4 v, uint32_t& h0, uint32_t& h1,
                                        uint32_t& l0, uint32_t& l1) {
    __half2 a = __floats2half2_rn(v.x, v.y);
    __half2 b = __floats2half2_rn(v.z, v.w);
    float2 af = __half22float2(a), bf = __half22float2(b);
    __half2 al = __floats2half2_rn(v.x - af.x, v.y - af.y);
    __half2 bl = __floats2half2_rn(v.z - bf.x, v.w - bf.y);
    h0 = *(uint32_t*)&a;  h1 = *(uint32_t*)&b;
    l0 = *(uint32_t*)&al; l1 = *(uint32_t*)&bl;
}

#define MMAH(c, a, b) \
    asm volatile("mma.sync.aligned.m16n8k16.row.col.f32.f16.f16.f32 " \
        "{%0,%1,%2,%3},{%4,%5,%6,%7},{%8,%9},{%0,%1,%2,%3};" \
        : "+f"((c)[0]), "+f"((c)[1]), "+f"((c)[2]), "+f"((c)[3]) \
        : "r"((a)[0]), "r"((a)[1]), "r"((a)[2]), "r"((a)[3]), \
          "r"((b)[0]), "r"((b)[1]))

// one k16 slab: A [row][kpair] LD, B [n][kpair] LD, 3-pass hi/lo
__device__ __forceinline__ void mma_slab(
    const uint32_t* __restrict__ AhU, const uint32_t* __restrict__ AlU,
    const uint32_t* __restrict__ BhU, const uint32_t* __restrict__ BlU,
    int wm, int wn, int g, int t, float acc[4][4][4])
{
    uint32_t ah[4][4], al[4][4], bh[4][2], bl[4][2];
#pragma unroll
    for (int i = 0; i < 4; i++) {
        int r0 = (wm + 16 * i + g) * LD + t;
        ah[i][0] = AhU[r0];     ah[i][1] = AhU[r0 + 8 * LD];
        ah[i][2] = AhU[r0 + 4]; ah[i][3] = AhU[r0 + 8 * LD + 4];
        al[i][0] = AlU[r0];     al[i][1] = AlU[r0 + 8 * LD];
        al[i][2] = AlU[r0 + 4]; al[i][3] = AlU[r0 + 8 * LD + 4];
    }
#pragma unroll
    for (int j = 0; j < 4; j++) {
        int r0 = (wn + 8 * j + g) * LD + t;
        bh[j][0] = BhU[r0]; bh[j][1] = BhU[r0 + 4];
        bl[j][0] = BlU[r0]; bl[j][1] = BlU[r0 + 4];
    }
#pragma unroll
    for (int i = 0; i < 4; i++)
#pragma unroll
        for (int j = 0; j < 4; j++) {
            MMAH(acc[i][j], ah[i], bh[j]);
            MMAH(acc[i][j], al[i], bh[j]);
            MMAH(acc[i][j], ah[i], bl[j]);
        }
}

// ---------------------------------------------------------------------------
// proj: out[NR][128] = x[NR][1024] @ W[128][1024]^T (fp16 hi/lo, double-buffered)
__global__ __launch_bounds__(256) void proj_mma_kernel(
    const float* __restrict__ x, const float* __restrict__ Wq,
    const float* __restrict__ Wk, const float* __restrict__ Wv)
{
    __shared__ uint32_t Ah[2][128 * LD], Al[2][128 * LD];
    __shared__ uint32_t Bh[2][128 * LD], Bl[2][128 * LD];
    const int which = blockIdx.y;
    const float* W   = (which == 0) ? Wq  : (which == 1) ? Wk  : Wv;
    float*       out = (which == 0) ? g_q : (which == 1) ? g_k : g_v;
    const int m0 = blockIdx.x * 128;
    const int tid = threadIdx.x;
    const int w = tid >> 5, lane = tid & 31;
    const int wm = (w & 1) * 64, wn = (w >> 1) * 32;
    const int g = lane >> 2, t = lane & 3;
    const int pr = tid >> 1, pc = (tid & 1) * 4;   // pc in u32 pairs (0 or 4)

    const float* ap = x + (size_t)(m0 + pr) * C + pc * 2;
    const float* bp = W + (size_t)pr * C + pc * 2;

    float4 rA0 = *(const float4*)ap, rA1 = *(const float4*)(ap + 4);
    float4 rB0 = *(const float4*)bp, rB1 = *(const float4*)(bp + 4);

    float acc[4][4][4];
#pragma unroll
    for (int i = 0; i < 4; i++)
#pragma unroll
        for (int j = 0; j < 4; j++)
#pragma unroll
            for (int q = 0; q < 4; q++) acc[i][j][q] = 0.f;

    const int NS = C / 16;
    // stage slab 0 into buffer 0
    {
        uint32_t h0, h1, h2, h3, l0, l1, l2, l3;
        splitH4(rA0, h0, h1, l0, l1); splitH4(rA1, h2, h3, l2, l3);
        *(uint4*)&Ah[0][pr * LD + pc] = make_uint4(h0, h1, h2, h3);
        *(uint4*)&Al[0][pr * LD + pc] = make_uint4(l0, l1, l2, l3);
        splitH4(rB0, h0, h1, l0, l1); splitH4(rB1, h2, h3, l2, l3);
        *(uint4*)&Bh[0][pr * LD + pc] = make_uint4(h0, h1, h2, h3);
        *(uint4*)&Bl[0][pr * LD + pc] = make_uint4(l0, l1, l2, l3);
    }
#pragma unroll 1
    for (int s = 0; s < NS; s++) {
        const int cur = s & 1, nxt = cur ^ 1;
        __syncthreads();
        if (s + 1 < NS) {
            rA0 = *(const float4*)(ap + (s + 1) * 16);
            rA1 = *(const float4*)(ap + (s + 1) * 16 + 4);
            rB0 = *(const float4*)(bp + (s + 1) * 16);
            rB1 = *(const float4*)(bp + (s + 1) * 16 + 4);
        }
        mma_slab(Ah[cur], Al[cur], Bh[cur], Bl[cur], wm, wn, g, t, acc);
        if (s + 1 < NS) {
            uint32_t h0, h1, h2, h3, l0, l1, l2, l3;
            splitH4(rA0, h0, h1, l0, l1); splitH4(rA1, h2, h3, l2, l3);
            *(uint4*)&Ah[nxt][pr * LD + pc] = make_uint4(h0, h1, h2, h3);
            *(uint4*)&Al[nxt][pr * LD + pc] = make_uint4(l0, l1, l2, l3);
            splitH4(rB0, h0, h1, l0, l1); splitH4(rB1, h2, h3, l2, l3);
            *(uint4*)&Bh[nxt][pr * LD + pc] = make_uint4(h0, h1, h2, h3);
            *(uint4*)&Bl[nxt][pr * LD + pc] = make_uint4(l0, l1, l2, l3);
        }
    }
#pragma unroll
    for (int i = 0; i < 4; i++)
#pragma unroll
        for (int j = 0; j < 4; j++) {
            int row = m0 + wm + 16 * i + g;
            int col = wn + 8 * j + 2 * t;
            *(float2*)&out[(size_t)row * H + col]       = make_float2(acc[i][j][0], acc[i][j][1]);
            *(float2*)&out[(size_t)(row + 8) * H + col] = make_float2(acc[i][j][2], acc[i][j][3]);
        }
}

// ---------------------------------------------------------------------------
// split+rowsum: per-row sums of q,k (pos decomposition) + pre-split q,k,v
__global__ __launch_bounds__(256) void split_kernel()
{
    int w = (blockIdx.x * blockDim.x + threadIdx.x) >> 5;
    int lane = threadIdx.x & 31;
    if (w >= NR) return;
    float4 q = *(const float4*)&g_q[(size_t)w * H + lane * 4];
    float4 k = *(const float4*)&g_k[(size_t)w * H + lane * 4];
    float4 v = *(const float4*)&g_v[(size_t)w * H + lane * 4];
    float sq = q.x + q.y + q.z + q.w;
    float sk = k.x + k.y + k.z + k.w;
#pragma unroll
    for (int o = 16; o > 0; o >>= 1) {
        sq += __shfl_xor_sync(0xffffffffu, sq, o);
        sk += __shfl_xor_sync(0xffffffffu, sk, o);
    }
    if (lane == 0) { g_sq[w] = sq; g_sk[w] = sk; }

    uint32_t h0, h1, l0, l1;
    const int idx = w * 32 + lane;
    splitH4(q, h0, h1, l0, l1);
    ((uint2*)g_qh)[idx] = make_uint2(h0, h1);
    ((uint2*)g_ql)[idx] = make_uint2(l0, l1);
    splitH4(k, h0, h1, l0, l1);
    ((uint2*)g_kh)[idx] = make_uint2(h0, h1);
    ((uint2*)g_kl)[idx] = make_uint2(l0, l1);
    splitH4(v, h0, h1, l0, l1);
    ((uint2*)g_vh)[idx] = make_uint2(h0, h1);
    ((uint2*)g_vl)[idx] = make_uint2(l0, l1);
}

// ---------------------------------------------------------------------------
// score: raw S = q.k over lower-band 128x128 tiles (fp16 hi/lo, pre-split,
// double-buffered)
__global__ __launch_bounds__(256) void score_mma_kernel(float* __restrict__ attn)
{
    __shared__ uint32_t Ah[2][128 * LD], Al[2][128 * LD];
    __shared__ uint32_t Bh[2][128 * LD], Bl[2][128 * LD];
    const int b = blockIdx.y;
    const int idx = blockIdx.x;
    int ti = (int)((sqrtf(8.f * (float)idx + 1.f) - 1.f) * 0.5f);
    if (ti > 15) ti = 15;
    while ((ti + 1) * (ti + 2) / 2 <= idx) ti++;
    while (ti * (ti + 1) / 2 > idx) ti--;
    const int tj = idx - ti * (ti + 1) / 2;
    const int t0 = ti * 128, s0 = tj * 128;

    const int tid = threadIdx.x;
    const int w = tid >> 5, lane = tid & 31;
    const int wm = (w & 1) * 64, wn = (w >> 1) * 32;
    const int g = lane >> 2, t = lane & 3;
    const int pr = tid >> 1, pc = (tid & 1) * 4;

    const uint32_t* qh = g_qh + (size_t)(b * T + t0 + pr) * 64 + pc;
    const uint32_t* ql = g_ql + (size_t)(b * T + t0 + pr) * 64 + pc;
    const uint32_t* kh = g_kh + (size_t)(b * T + s0 + pr) * 64 + pc;
    const uint32_t* kl = g_kl + (size_t)(b * T + s0 + pr) * 64 + pc;

    uint4 rAh = *(const uint4*)qh, rAl = *(const uint4*)ql;
    uint4 rBh = *(const uint4*)kh, rBl = *(const uint4*)kl;

    float acc[4][4][4];
#pragma unroll
    for (int i = 0; i < 4; i++)
#pragma unroll
        for (int j = 0; j < 4; j++)
#pragma unroll
            for (int q = 0; q < 4; q++) acc[i][j][q] = 0.f;

    const int NS = H / 16;  // 8
    *(uint4*)&Ah[0][pr * LD + pc] = rAh;
    *(uint4*)&Al[0][pr * LD + pc] = rAl;
    *(uint4*)&Bh[0][pr * LD + pc] = rBh;
    *(uint4*)&Bl[0][pr * LD + pc] = rBl;
#pragma unroll 1
    for (int s = 0; s < NS; s++) {
        const int cur = s & 1, nxt = cur ^ 1;
        __syncthreads();
        if (s + 1 < NS) {
            rAh = *(const uint4*)(qh + (s + 1) * 8);
            rAl = *(const uint4*)(ql + (s + 1) * 8);
            rBh = *(const uint4*)(kh + (s + 1) * 8);
            rBl = *(const uint4*)(kl + (s + 1) * 8);
        }
        mma_slab(Ah[cur], Al[cur], Bh[cur], Bl[cur], wm, wn, g, t, acc);
        if (s + 1 < NS) {
            *(uint4*)&Ah[nxt][pr * LD + pc] = rAh;
            *(uint4*)&Al[nxt][pr * LD + pc] = rAl;
            *(uint4*)&Bh[nxt][pr * LD + pc] = rBh;
            *(uint4*)&Bl[nxt][pr * LD + pc] = rBl;
        }
    }
#pragma unroll
    for (int i = 0; i < 4; i++)
#pragma unroll
        for (int j = 0; j < 4; j++) {
            int row = t0 + wm + 16 * i + g;
            int col = s0 + wn + 8 * j + 2 * t;
            *(float2*)&attn[(size_t)(b * T + row) * T + col]     = make_float2(acc[i][j][0], acc[i][j][1]);
            *(float2*)&attn[(size_t)(b * T + row + 8) * T + col] = make_float2(acc[i][j][2], acc[i][j][3]);
        }
}

// ---------------------------------------------------------------------------
// softmax: in-place per row; adds pos terms, masks, normalizes.
__global__ __launch_bounds__(256) void softmax_kernel(float* __restrict__ attn)
{
    __shared__ float red[8];
    const int r = blockIdx.x;
    const int b = r >> 11;
    const int t = r & (T - 1);
    float* row = attn + (size_t)r * T;
    const float* skrow = g_sk + (size_t)b * T;
    const float sq = g_sq[r];
    const float tf = (float)t;
    const int tid = threadIdx.x;
    const int c0 = tid * 8;

    float4 v0 = *(const float4*)(row + c0);
    float4 v1 = *(const float4*)(row + c0 + 4);
    float4 s0 = *(const float4*)(skrow + c0);
    float4 s1 = *(const float4*)(skrow + c0 + 4);
    float qk[8] = {v0.x, v0.y, v0.z, v0.w, v1.x, v1.y, v1.z, v1.w};
    float sk[8] = {s0.x, s0.y, s0.z, s0.w, s1.x, s1.y, s1.z, s1.w};

    float lg[8];
    float mx = -INFINITY;
#pragma unroll
    for (int j = 0; j < 8; j++) {
        int s = c0 + j;
        float v = (qk[j] + (float)s * sq + tf * sk[j] + 128.f * (float)(t * s)) * 0.03125f;
        lg[j] = (s <= t) ? v : -INFINITY;
        mx = fmaxf(mx, lg[j]);
    }
#pragma unroll
    for (int o = 16; o > 0; o >>= 1)
        mx = fmaxf(mx, __shfl_xor_sync(0xffffffffu, mx, o));
    if ((tid & 31) == 0) red[tid >> 5] = mx;
    __syncthreads();
    float m = red[0];
#pragma unroll
    for (int i = 1; i < 8; i++) m = fmaxf(m, red[i]);
    __syncthreads();

    float ev[8];
    float sum = 0.f;
#pragma unroll
    for (int j = 0; j < 8; j++) {
        ev[j] = __expf(lg[j] - m);
        sum += ev[j];
    }
#pragma unroll
    for (int o = 16; o > 0; o >>= 1)
        sum += __shfl_xor_sync(0xffffffffu, sum, o);
    if ((tid & 31) == 0) red[tid >> 5] = sum;
    __syncthreads();
    float tot = red[0];
#pragma unroll
    for (int i = 1; i < 8; i++) tot += red[i];
    const float rinv = 1.f / tot;

    *(float4*)(row + c0)     = make_float4(ev[0] * rinv, ev[1] * rinv, ev[2] * rinv, ev[3] * rinv);
    *(float4*)(row + c0 + 4) = make_float4(ev[4] * rinv, ev[5] * rinv, ev[6] * rinv, ev[7] * rinv);
}

// ---------------------------------------------------------------------------
// pv: res += attn_chunk @ v_chunk (fp16 hi/lo 3-pass, split-K 256-wide chunks,
// atomicAdd into zeroed res, double-buffered). B staged transposed.
__global__ __launch_bounds__(256) void pv_mma_kernel(
    const float* __restrict__ attn, float* __restrict__ res)
{
    __shared__ uint32_t Ah[2][128 * LD], Al[2][128 * LD];
    __shared__ uint32_t Bh[2][128 * LD], Bl[2][128 * LD];
    const int b = blockIdx.y;
    int bx = blockIdx.x;
    int kt = 15, chunk = 0;
#pragma unroll
    for (int k = 15; k >= 0; k--) {
        int cnt = (k + 2) >> 1;
        if (bx < cnt) { kt = k; chunk = bx; break; }
        bx -= cnt;
    }
    const int t0 = kt * 128;
    const int sbeg = chunk * 256;
    const int send = min(sbeg + 256, (kt + 1) * 128);
    const int NS = (send - sbeg) >> 4;

    const int tid = threadIdx.x;
    const int w = tid >> 5, lane = tid & 31;
    const int wm = (w & 1) * 64, wn = (w >> 1) * 32;
    const int g = lane >> 2, t = lane & 3;
    const int pr = tid >> 1, pc = (tid & 1) * 4;   // A stager
    const int sp = tid & 7, hq = tid >> 3;         // B stager: s-pair, h-quad

    const float* ap = attn + (size_t)(b * T + t0 + pr) * T + sbeg + pc * 2;
    const uint32_t* vh = g_vh + (size_t)(b * T + sbeg + 2 * sp) * 64 + 2 * hq;
    const uint32_t* vl = g_vl + (size_t)(b * T + sbeg + 2 * sp) * 64 + 2 * hq;

    float4 rA0 = *(const float4*)ap, rA1 = *(const float4*)(ap + 4);
    uint2 rha = *(const uint2*)vh,   rhb = *(const uint2*)(vh + 64);
    uint2 rla = *(const uint2*)vl,   rlb = *(const uint2*)(vl + 64);

    float acc[4][4][4];
#pragma unroll
    for (int i = 0; i < 4; i++)
#pragma unroll
        for (int j = 0; j < 4; j++)
#pragma unroll
            for (int q = 0; q < 4; q++) acc[i][j][q] = 0.f;

    // stage slab 0 into buffer 0
    {
        uint32_t h0, h1, h2, h3, l0, l1, l2, l3;
        splitH4(rA0, h0, h1, l0, l1); splitH4(rA1, h2, h3, l2, l3);
        *(uint4*)&Ah[0][pr * LD + pc] = make_uint4(h0, h1, h2, h3);
        *(uint4*)&Al[0][pr * LD + pc] = make_uint4(l0, l1, l2, l3);
        Bh[0][(4 * hq + 0) * LD + sp] = __byte_perm(rha.x, rhb.x, 0x5410);
        Bh[0][(4 * hq + 1) * LD + sp] = __byte_perm(rha.x, rhb.x, 0x7632);
        Bh[0][(4 * hq + 2) * LD + sp] = __byte_perm(rha.y, rhb.y, 0x5410);
        Bh[0][(4 * hq + 3) * LD + sp] = __byte_perm(rha.y, rhb.y, 0x7632);
        Bl[0][(4 * hq + 0) * LD + sp] = __byte_perm(rla.x, rlb.x, 0x5410);
        Bl[0][(4 * hq + 1) * LD + sp] = __byte_perm(rla.x, rlb.x, 0x7632);
        Bl[0][(4 * hq + 2) * LD + sp] = __byte_perm(rla.y, rlb.y, 0x5410);
        Bl[0][(4 * hq + 3) * LD + sp] = __byte_perm(rla.y, rlb.y, 0x7632);
    }
#pragma unroll 1
    for (int s = 0; s < NS; s++) {
        const int cur = s & 1, nxt = cur ^ 1;
        __syncthreads();
        if (s + 1 < NS) {
            rA0 = *(const float4*)(ap + (s + 1) * 16);
            rA1 = *(const float4*)(ap + (s + 1) * 16 + 4);
            const uint32_t* vh2 = vh + (size_t)(s + 1) * 16 * 64;
            const uint32_t* vl2 = vl + (size_t)(s + 1) * 16 * 64;
            rha = *(const uint2*)vh2; rhb = *(const uint2*)(vh2 + 64);
            rla = *(const uint2*)vl2; rlb = *(const uint2*)(vl2 + 64);
        }
        mma_slab(Ah[cur], Al[cur], Bh[cur], Bl[cur], wm, wn, g, t, acc);
        if (s + 1 < NS) {
            uint32_t h0, h1, h2, h3, l0, l1, l2, l3;
            splitH4(rA0, h0, h1, l0, l1); splitH4(rA1, h2, h3, l2, l3);
            *(uint4*)&Ah[nxt][pr * LD + pc] = make_uint4(h0, h1, h2, h3);
            *(uint4*)&Al[nxt][pr * LD + pc] = make_uint4(l0, l1, l2, l3);
            Bh[nxt][(4 * hq + 0) * LD + sp] = __byte_perm(rha.x, rhb.x, 0x5410);
            Bh[nxt][(4 * hq + 1) * LD + sp] = __byte_perm(rha.x, rhb.x, 0x7632);
            Bh[nxt][(4 * hq + 2) * LD + sp] = __byte_perm(rha.y, rhb.y, 0x5410);
            Bh[nxt][(4 * hq + 3) * LD + sp] = __byte_perm(rha.y, rhb.y, 0x7632);
            Bl[nxt][(4 * hq + 0) * LD + sp] = __byte_perm(rla.x, rlb.x, 0x5410);
            Bl[nxt][(4 * hq + 1) * LD + sp] = __byte_perm(rla.x, rlb.x, 0x7632);
            Bl[nxt][(4 * hq + 2) * LD + sp] = __byte_perm(rla.y, rlb.y, 0x5410);
            Bl[nxt][(4 * hq + 3) * LD + sp] = __byte_perm(rla.y, rlb.y, 0x7632);
        }
    }
#pragma unroll
    for (int i = 0; i < 4; i++)
#pragma unroll
        for (int j = 0; j < 4; j++) {
            int row = t0 + wm + 16 * i + g;
            int col = wn + 8 * j + 2 * t;
            float* p0 = res + (size_t)(b * T + row) * H + col;
            float* p1 = res + (size_t)(b * T + row + 8) * H + col;
            atomicAdd(p0,     acc[i][j][0]);
            atomicAdd(p0 + 1, acc[i][j][1]);
            atomicAdd(p1,     acc[i][j][2]);
            atomicAdd(p1 + 1, acc[i][j][3]);
        }
}

// ---------------------------------------------------------------------------
extern "C" void kernel_launch(void* const* d_in, const int* in_sizes, int n_in,
                              void* d_out, int out_size)
{
    const float* x  = (const float*)d_in[0];
    const float* Wq = (const float*)d_in[1];
    const float* Wk = (const float*)d_in[2];
    const float* Wv = (const float*)d_in[3];
    float* res  = (float*)d_out;
    float* attn = res + (size_t)B * T * H;

    cudaMemsetAsync(res, 0, (size_t)NR * H * sizeof(float));
    proj_mma_kernel<<<dim3(NR / 128, 3), 256>>>(x, Wq, Wk, Wv);
    split_kernel<<<NR / 8, 256>>>();
    score_mma_kernel<<<dim3(136, 8), 256>>>(attn);
    softmax_kernel<<<NR, 256>>>(attn);
    pv_mma_kernel<<<dim3(72, 8), 256>>>(attn, res);
}

// round 12
// speedup vs baseline: 3.6791x; 1.1185x over previous
#include <cuda_runtime.h>
#include <cuda_fp16.h>
#include <math.h>
#include <stddef.h>
#include <stdint.h>

// NOTE: harness builds via compute_103 virtual arch -> tcgen05/TMEM PTX is
// rejected by ptxas. mma.sync (HMMA) + ldmatrix is the available tensor path.

namespace {
constexpr int B = 8, T = 2048, C = 1024, H = 128;
constexpr int NR = B * T;   // 16384 rows
constexpr int LD = 12;      // smem row stride in u32 (48B rows: LDSM conflict-free)
constexpr int BUF_BYTES = 128 * LD * 4;   // one buffer of one operand array
}

// scratch (device globals: allocation-free per harness rules)
__device__ float    g_q[NR * H];
__device__ float    g_k[NR * H];
__device__ float    g_v[NR * H];
__device__ float    g_sq[NR];
__device__ float    g_sk[NR];
// pre-split packed half2 (k-pair) operands
__device__ uint32_t g_qh[NR * 64], g_ql[NR * 64];
__device__ uint32_t g_kh[NR * 64], g_kl[NR * 64];
__device__ uint32_t g_vh[NR * 64], g_vl[NR * 64];   // plain h-order halves

// ---------------------------------------------------------------------------
__device__ __forceinline__ uint32_t smem_u32(const void* p) {
    uint32_t a;
    asm("{ .reg .u64 t; cvta.to.shared.u64 t, %1; cvt.u32.u64 %0, t; }" : "=r"(a) : "l"(p));
    return a;
}

__device__ __forceinline__ void splitH4(float4 v, uint32_t& h0, uint32_t& h1,
                                        uint32_t& l0, uint32_t& l1) {
    __half2 a = __floats2half2_rn(v.x, v.y);
    __half2 b = __floats2half2_rn(v.z, v.w);
    float2 af = __half22float2(a), bf = __half22float2(b);
    __half2 al = __floats2half2_rn(v.x - af.x, v.y - af.y);
    __half2 bl = __floats2half2_rn(v.z - bf.x, v.w - bf.y);
    h0 = *(uint32_t*)&a;  h1 = *(uint32_t*)&b;
    l0 = *(uint32_t*)&al; l1 = *(uint32_t*)&bl;
}

#define MMAH(c, a, b) \
    asm volatile("mma.sync.aligned.m16n8k16.row.col.f32.f16.f16.f32 " \
        "{%0,%1,%2,%3},{%4,%5,%6,%7},{%8,%9},{%0,%1,%2,%3};" \
        : "+f"((c)[0]), "+f"((c)[1]), "+f"((c)[2]), "+f"((c)[3]) \
        : "r"((a)[0]), "r"((a)[1]), "r"((a)[2]), "r"((a)[3]), \
          "r"((b)[0]), "r"((b)[1]))

__device__ __forceinline__ void ldsm_x4(uint32_t addr, uint32_t* r) {
    asm volatile("ldmatrix.sync.aligned.m8n8.x4.shared.b16 {%0,%1,%2,%3}, [%4];"
        : "=r"(r[0]), "=r"(r[1]), "=r"(r[2]), "=r"(r[3]) : "r"(addr));
}

// one k16 slab via ldmatrix: A [row][kpair] LD, B [n][kpair] LD, 3-pass hi/lo
__device__ __forceinline__ void mma_slab(
    uint32_t aAh, uint32_t aAl, uint32_t aBh, uint32_t aBl,
    const uint32_t* aoff, const uint32_t* boff, float acc[4][4][4])
{
    uint32_t ah[4][4], al[4][4], bh[4][2], bl[4][2];
#pragma unroll
    for (int i = 0; i < 4; i++) {
        ldsm_x4(aAh + aoff[i], ah[i]);
        ldsm_x4(aAl + aoff[i], al[i]);
    }
#pragma unroll
    for (int p = 0; p < 2; p++) {
        uint32_t rb[4];
        ldsm_x4(aBh + boff[p], rb);
        bh[2 * p][0] = rb[0]; bh[2 * p + 1][0] = rb[1];
        bh[2 * p][1] = rb[2]; bh[2 * p + 1][1] = rb[3];
        ldsm_x4(aBl + boff[p], rb);
        bl[2 * p][0] = rb[0]; bl[2 * p + 1][0] = rb[1];
        bl[2 * p][1] = rb[2]; bl[2 * p + 1][1] = rb[3];
    }
#pragma unroll
    for (int i = 0; i < 4; i++)
#pragma unroll
        for (int j = 0; j < 4; j++) {
            MMAH(acc[i][j], ah[i], bh[j]);
            MMAH(acc[i][j], al[i], bh[j]);
            MMAH(acc[i][j], ah[i], bl[j]);
        }
}

// per-warp ldmatrix address offsets (bytes) within one operand buffer
#define MAKE_LDSM_OFFSETS()                                              \
    uint32_t aoff[4], boff[2];                                           \
    {                                                                    \
        const int l15 = lane & 15, lhi = lane >> 4;                      \
        _Pragma("unroll")                                                \
        for (int i = 0; i < 4; i++)                                      \
            aoff[i] = (uint32_t)((wm + 16 * i + l15) * 48 + lhi * 16);   \
        _Pragma("unroll")                                                \
        for (int p = 0; p < 2; p++)                                      \
            boff[p] = (uint32_t)((wn + 16 * p + l15) * 48 + lhi * 16);   \
    }

// ---------------------------------------------------------------------------
// proj: out[NR][128] = x[NR][1024] @ W[128][1024]^T (fp16 hi/lo, double-buffered)
__global__ __launch_bounds__(256) void proj_mma_kernel(
    const float* __restrict__ x, const float* __restrict__ Wq,
    const float* __restrict__ Wk, const float* __restrict__ Wv)
{
    __shared__ uint32_t Ah[2][128 * LD], Al[2][128 * LD];
    __shared__ uint32_t Bh[2][128 * LD], Bl[2][128 * LD];
    const int which = blockIdx.y;
    const float* W   = (which == 0) ? Wq  : (which == 1) ? Wk  : Wv;
    float*       out = (which == 0) ? g_q : (which == 1) ? g_k : g_v;
    const int m0 = blockIdx.x * 128;
    const int tid = threadIdx.x;
    const int w = tid >> 5, lane = tid & 31;
    const int wm = (w & 1) * 64, wn = (w >> 1) * 32;
    const int g = lane >> 2, t = lane & 3;
    const int pr = tid >> 1, pc = (tid & 1) * 4;   // pc in u32 pairs (0 or 4)

    MAKE_LDSM_OFFSETS();
    const uint32_t bAh = smem_u32(&Ah[0][0]), bAl = smem_u32(&Al[0][0]);
    const uint32_t bBh = smem_u32(&Bh[0][0]), bBl = smem_u32(&Bl[0][0]);

    const float* ap = x + (size_t)(m0 + pr) * C + pc * 2;
    const float* bp = W + (size_t)pr * C + pc * 2;

    float4 rA0 = *(const float4*)ap, rA1 = *(const float4*)(ap + 4);
    float4 rB0 = *(const float4*)bp, rB1 = *(const float4*)(bp + 4);

    float acc[4][4][4];
#pragma unroll
    for (int i = 0; i < 4; i++)
#pragma unroll
        for (int j = 0; j < 4; j++)
#pragma unroll
            for (int q = 0; q < 4; q++) acc[i][j][q] = 0.f;

    const int NS = C / 16;
    {
        uint32_t h0, h1, h2, h3, l0, l1, l2, l3;
        splitH4(rA0, h0, h1, l0, l1); splitH4(rA1, h2, h3, l2, l3);
        *(uint4*)&Ah[0][pr * LD + pc] = make_uint4(h0, h1, h2, h3);
        *(uint4*)&Al[0][pr * LD + pc] = make_uint4(l0, l1, l2, l3);
        splitH4(rB0, h0, h1, l0, l1); splitH4(rB1, h2, h3, l2, l3);
        *(uint4*)&Bh[0][pr * LD + pc] = make_uint4(h0, h1, h2, h3);
        *(uint4*)&Bl[0][pr * LD + pc] = make_uint4(l0, l1, l2, l3);
    }
#pragma unroll 1
    for (int s = 0; s < NS; s++) {
        const int cur = s & 1, nxt = cur ^ 1;
        const uint32_t bo = (uint32_t)(cur * BUF_BYTES);
        __syncthreads();
        if (s + 1 < NS) {
            rA0 = *(const float4*)(ap + (s + 1) * 16);
            rA1 = *(const float4*)(ap + (s + 1) * 16 + 4);
            rB0 = *(const float4*)(bp + (s + 1) * 16);
            rB1 = *(const float4*)(bp + (s + 1) * 16 + 4);
        }
        mma_slab(bAh + bo, bAl + bo, bBh + bo, bBl + bo, aoff, boff, acc);
        if (s + 1 < NS) {
            uint32_t h0, h1, h2, h3, l0, l1, l2, l3;
            splitH4(rA0, h0, h1, l0, l1); splitH4(rA1, h2, h3, l2, l3);
            *(uint4*)&Ah[nxt][pr * LD + pc] = make_uint4(h0, h1, h2, h3);
            *(uint4*)&Al[nxt][pr * LD + pc] = make_uint4(l0, l1, l2, l3);
            splitH4(rB0, h0, h1, l0, l1); splitH4(rB1, h2, h3, l2, l3);
            *(uint4*)&Bh[nxt][pr * LD + pc] = make_uint4(h0, h1, h2, h3);
            *(uint4*)&Bl[nxt][pr * LD + pc] = make_uint4(l0, l1, l2, l3);
        }
    }
#pragma unroll
    for (int i = 0; i < 4; i++)
#pragma unroll
        for (int j = 0; j < 4; j++) {
            int row = m0 + wm + 16 * i + g;
            int col = wn + 8 * j + 2 * t;
            *(float2*)&out[(size_t)row * H + col]       = make_float2(acc[i][j][0], acc[i][j][1]);
            *(float2*)&out[(size_t)(row + 8) * H + col] = make_float2(acc[i][j][2], acc[i][j][3]);
        }
}

// ---------------------------------------------------------------------------
// split+rowsum: per-row sums of q,k (pos decomposition) + pre-split q,k,v
__global__ __launch_bounds__(256) void split_kernel()
{
    int w = (blockIdx.x * blockDim.x + threadIdx.x) >> 5;
    int lane = threadIdx.x & 31;
    if (w >= NR) return;
    float4 q = *(const float4*)&g_q[(size_t)w * H + lane * 4];
    float4 k = *(const float4*)&g_k[(size_t)w * H + lane * 4];
    float4 v = *(const float4*)&g_v[(size_t)w * H + lane * 4];
    float sq = q.x + q.y + q.z + q.w;
    float sk = k.x + k.y + k.z + k.w;
#pragma unroll
    for (int o = 16; o > 0; o >>= 1) {
        sq += __shfl_xor_sync(0xffffffffu, sq, o);
        sk += __shfl_xor_sync(0xffffffffu, sk, o);
    }
    if (lane == 0) { g_sq[w] = sq; g_sk[w] = sk; }

    uint32_t h0, h1, l0, l1;
    const int idx = w * 32 + lane;
    splitH4(q, h0, h1, l0, l1);
    ((uint2*)g_qh)[idx] = make_uint2(h0, h1);
    ((uint2*)g_ql)[idx] = make_uint2(l0, l1);
    splitH4(k, h0, h1, l0, l1);
    ((uint2*)g_kh)[idx] = make_uint2(h0, h1);
    ((uint2*)g_kl)[idx] = make_uint2(l0, l1);
    splitH4(v, h0, h1, l0, l1);
    ((uint2*)g_vh)[idx] = make_uint2(h0, h1);
    ((uint2*)g_vl)[idx] = make_uint2(l0, l1);
}

// ---------------------------------------------------------------------------
// score: raw S = q.k over lower-band 128x128 tiles (fp16 hi/lo, pre-split,
// double-buffered, ldmatrix)
__global__ __launch_bounds__(256) void score_mma_kernel(float* __restrict__ attn)
{
    __shared__ uint32_t Ah[2][128 * LD], Al[2][128 * LD];
    __shared__ uint32_t Bh[2][128 * LD], Bl[2][128 * LD];
    const int b = blockIdx.y;
    const int idx = blockIdx.x;
    int ti = (int)((sqrtf(8.f * (float)idx + 1.f) - 1.f) * 0.5f);
    if (ti > 15) ti = 15;
    while ((ti + 1) * (ti + 2) / 2 <= idx) ti++;
    while (ti * (ti + 1) / 2 > idx) ti--;
    const int tj = idx - ti * (ti + 1) / 2;
    const int t0 = ti * 128, s0 = tj * 128;

    const int tid = threadIdx.x;
    const int w = tid >> 5, lane = tid & 31;
    const int wm = (w & 1) * 64, wn = (w >> 1) * 32;
    const int g = lane >> 2, t = lane & 3;
    const int pr = tid >> 1, pc = (tid & 1) * 4;

    MAKE_LDSM_OFFSETS();
    const uint32_t bAh = smem_u32(&Ah[0][0]), bAl = smem_u32(&Al[0][0]);
    const uint32_t bBh = smem_u32(&Bh[0][0]), bBl = smem_u32(&Bl[0][0]);

    const uint32_t* qh = g_qh + (size_t)(b * T + t0 + pr) * 64 + pc;
    const uint32_t* ql = g_ql + (size_t)(b * T + t0 + pr) * 64 + pc;
    const uint32_t* kh = g_kh + (size_t)(b * T + s0 + pr) * 64 + pc;
    const uint32_t* kl = g_kl + (size_t)(b * T + s0 + pr) * 64 + pc;

    uint4 rAh = *(const uint4*)qh, rAl = *(const uint4*)ql;
    uint4 rBh = *(const uint4*)kh, rBl = *(const uint4*)kl;

    float acc[4][4][4];
#pragma unroll
    for (int i = 0; i < 4; i++)
#pragma unroll
        for (int j = 0; j < 4; j++)
#pragma unroll
            for (int q = 0; q < 4; q++) acc[i][j][q] = 0.f;

    const int NS = H / 16;  // 8
    *(uint4*)&Ah[0][pr * LD + pc] = rAh;
    *(uint4*)&Al[0][pr * LD + pc] = rAl;
    *(uint4*)&Bh[0][pr * LD + pc] = rBh;
    *(uint4*)&Bl[0][pr * LD + pc] = rBl;
#pragma unroll 1
    for (int s = 0; s < NS; s++) {
        const int cur = s & 1, nxt = cur ^ 1;
        const uint32_t bo = (uint32_t)(cur * BUF_BYTES);
        __syncthreads();
        if (s + 1 < NS) {
            rAh = *(const uint4*)(qh + (s + 1) * 8);
            rAl = *(const uint4*)(ql + (s + 1) * 8);
            rBh = *(const uint4*)(kh + (s + 1) * 8);
            rBl = *(const uint4*)(kl + (s + 1) * 8);
        }
        mma_slab(bAh + bo, bAl + bo, bBh + bo, bBl + bo, aoff, boff, acc);
        if (s + 1 < NS) {
            *(uint4*)&Ah[nxt][pr * LD + pc] = rAh;
            *(uint4*)&Al[nxt][pr * LD + pc] = rAl;
            *(uint4*)&Bh[nxt][pr * LD + pc] = rBh;
            *(uint4*)&Bl[nxt][pr * LD + pc] = rBl;
        }
    }
#pragma unroll
    for (int i = 0; i < 4; i++)
#pragma unroll
        for (int j = 0; j < 4; j++) {
            int row = t0 + wm + 16 * i + g;
            int col = s0 + wn + 8 * j + 2 * t;
            *(float2*)&attn[(size_t)(b * T + row) * T + col]     = make_float2(acc[i][j][0], acc[i][j][1]);
            *(float2*)&attn[(size_t)(b * T + row + 8) * T + col] = make_float2(acc[i][j][2], acc[i][j][3]);
        }
}

// ---------------------------------------------------------------------------
// softmax: in-place per row; adds pos terms, masks, normalizes.
__global__ __launch_bounds__(256) void softmax_kernel(float* __restrict__ attn)
{
    __shared__ float red[8];
    const int r = blockIdx.x;
    const int b = r >> 11;
    const int t = r & (T - 1);
    float* row = attn + (size_t)r * T;
    const float* skrow = g_sk + (size_t)b * T;
    const float sq = g_sq[r];
    const float tf = (float)t;
    const int tid = threadIdx.x;
    const int c0 = tid * 8;

    float4 v0 = *(const float4*)(row + c0);
    float4 v1 = *(const float4*)(row + c0 + 4);
    float4 s0 = *(const float4*)(skrow + c0);
    float4 s1 = *(const float4*)(skrow + c0 + 4);
    float qk[8] = {v0.x, v0.y, v0.z, v0.w, v1.x, v1.y, v1.z, v1.w};
    float sk[8] = {s0.x, s0.y, s0.z, s0.w, s1.x, s1.y, s1.z, s1.w};

    float lg[8];
    float mx = -INFINITY;
#pragma unroll
    for (int j = 0; j < 8; j++) {
        int s = c0 + j;
        float v = (qk[j] + (float)s * sq + tf * sk[j] + 128.f * (float)(t * s)) * 0.03125f;
        lg[j] = (s <= t) ? v : -INFINITY;
        mx = fmaxf(mx, lg[j]);
    }
#pragma unroll
    for (int o = 16; o > 0; o >>= 1)
        mx = fmaxf(mx, __shfl_xor_sync(0xffffffffu, mx, o));
    if ((tid & 31) == 0) red[tid >> 5] = mx;
    __syncthreads();
    float m = red[0];
#pragma unroll
    for (int i = 1; i < 8; i++) m = fmaxf(m, red[i]);
    __syncthreads();

    float ev[8];
    float sum = 0.f;
#pragma unroll
    for (int j = 0; j < 8; j++) {
        ev[j] = __expf(lg[j] - m);
        sum += ev[j];
    }
#pragma unroll
    for (int o = 16; o > 0; o >>= 1)
        sum += __shfl_xor_sync(0xffffffffu, sum, o);
    if ((tid & 31) == 0) red[tid >> 5] = sum;
    __syncthreads();
    float tot = red[0];
#pragma unroll
    for (int i = 1; i < 8; i++) tot += red[i];
    const float rinv = 1.f / tot;

    *(float4*)(row + c0)     = make_float4(ev[0] * rinv, ev[1] * rinv, ev[2] * rinv, ev[3] * rinv);
    *(float4*)(row + c0 + 4) = make_float4(ev[4] * rinv, ev[5] * rinv, ev[6] * rinv, ev[7] * rinv);
}

// ---------------------------------------------------------------------------
// pv: res += attn_chunk @ v_chunk (fp16 hi/lo 3-pass, split-K 256-wide chunks,
// atomicAdd into zeroed res, double-buffered, ldmatrix). B staged transposed.
__global__ __launch_bounds__(256) void pv_mma_kernel(
    const float* __restrict__ attn, float* __restrict__ res)
{
    __shared__ uint32_t Ah[2][128 * LD], Al[2][128 * LD];
    __shared__ uint32_t Bh[2][128 * LD], Bl[2][128 * LD];
    const int b = blockIdx.y;
    int bx = blockIdx.x;
    int kt = 15, chunk = 0;
#pragma unroll
    for (int k = 15; k >= 0; k--) {
        int cnt = (k + 2) >> 1;
        if (bx < cnt) { kt = k; chunk = bx; break; }
        bx -= cnt;
    }
    const int t0 = kt * 128;
    const int sbeg = chunk * 256;
    const int send = min(sbeg + 256, (kt + 1) * 128);
    const int NS = (send - sbeg) >> 4;

    const int tid = threadIdx.x;
    const int w = tid >> 5, lane = tid & 31;
    const int wm = (w & 1) * 64, wn = (w >> 1) * 32;
    const int g = lane >> 2, t = lane & 3;
    const int pr = tid >> 1, pc = (tid & 1) * 4;   // A stager
    const int sp = tid & 7, hq = tid >> 3;         // B stager: s-pair, h-quad

    MAKE_LDSM_OFFSETS();
    const uint32_t bAh = smem_u32(&Ah[0][0]), bAl = smem_u32(&Al[0][0]);
    const uint32_t bBh = smem_u32(&Bh[0][0]), bBl = smem_u32(&Bl[0][0]);

    const float* ap = attn + (size_t)(b * T + t0 + pr) * T + sbeg + pc * 2;
    const uint32_t* vh = g_vh + (size_t)(b * T + sbeg + 2 * sp) * 64 + 2 * hq;
    const uint32_t* vl = g_vl + (size_t)(b * T + sbeg + 2 * sp) * 64 + 2 * hq;

    float4 rA0 = *(const float4*)ap, rA1 = *(const float4*)(ap + 4);
    uint2 rha = *(const uint2*)vh,   rhb = *(const uint2*)(vh + 64);
    uint2 rla = *(const uint2*)vl,   rlb = *(const uint2*)(vl + 64);

    float acc[4][4][4];
#pragma unroll
    for (int i = 0; i < 4; i++)
#pragma unroll
        for (int j = 0; j < 4; j++)
#pragma unroll
            for (int q = 0; q < 4; q++) acc[i][j][q] = 0.f;

    {
        uint32_t h0, h1, h2, h3, l0, l1, l2, l3;
        splitH4(rA0, h0, h1, l0, l1); splitH4(rA1, h2, h3, l2, l3);
        *(uint4*)&Ah[0][pr * LD + pc] = make_uint4(h0, h1, h2, h3);
        *(uint4*)&Al[0][pr * LD + pc] = make_uint4(l0, l1, l2, l3);
        Bh[0][(4 * hq + 0) * LD + sp] = __byte_perm(rha.x, rhb.x, 0x5410);
        Bh[0][(4 * hq + 1) * LD + sp] = __byte_perm(rha.x, rhb.x, 0x7632);
        Bh[0][(4 * hq + 2) * LD + sp] = __byte_perm(rha.y, rhb.y, 0x5410);
        Bh[0][(4 * hq + 3) * LD + sp] = __byte_perm(rha.y, rhb.y, 0x7632);
        Bl[0][(4 * hq + 0) * LD + sp] = __byte_perm(rla.x, rlb.x, 0x5410);
        Bl[0][(4 * hq + 1) * LD + sp] = __byte_perm(rla.x, rlb.x, 0x7632);
        Bl[0][(4 * hq + 2) * LD + sp] = __byte_perm(rla.y, rlb.y, 0x5410);
        Bl[0][(4 * hq + 3) * LD + sp] = __byte_perm(rla.y, rlb.y, 0x7632);
    }
#pragma unroll 1
    for (int s = 0; s < NS; s++) {
        const int cur = s & 1, nxt = cur ^ 1;
        const uint32_t bo = (uint32_t)(cur * BUF_BYTES);
        __syncthreads();
        if (s + 1 < NS) {
            rA0 = *(const float4*)(ap + (s + 1) * 16);
            rA1 = *(const float4*)(ap + (s + 1) * 16 + 4);
            const uint32_t* vh2 = vh + (size_t)(s + 1) * 16 * 64;
            const uint32_t* vl2 = vl + (size_t)(s + 1) * 16 * 64;
            rha = *(const uint2*)vh2; rhb = *(const uint2*)(vh2 + 64);
            rla = *(const uint2*)vl2; rlb = *(const uint2*)(vl2 + 64);
        }
        mma_slab(bAh + bo, bAl + bo, bBh + bo, bBl + bo, aoff, boff, acc);
        if (s + 1 < NS) {
            uint32_t h0, h1, h2, h3, l0, l1, l2, l3;
            splitH4(rA0, h0, h1, l0, l1); splitH4(rA1, h2, h3, l2, l3);
            *(uint4*)&Ah[nxt][pr * LD + pc] = make_uint4(h0, h1, h2, h3);
            *(uint4*)&Al[nxt][pr * LD + pc] = make_uint4(l0, l1, l2, l3);
            Bh[nxt][(4 * hq + 0) * LD + sp] = __byte_perm(rha.x, rhb.x, 0x5410);
            Bh[nxt][(4 * hq + 1) * LD + sp] = __byte_perm(rha.x, rhb.x, 0x7632);
            Bh[nxt][(4 * hq + 2) * LD + sp] = __byte_perm(rha.y, rhb.y, 0x5410);
            Bh[nxt][(4 * hq + 3) * LD + sp] = __byte_perm(rha.y, rhb.y, 0x7632);
            Bl[nxt][(4 * hq + 0) * LD + sp] = __byte_perm(rla.x, rlb.x, 0x5410);
            Bl[nxt][(4 * hq + 1) * LD + sp] = __byte_perm(rla.x, rlb.x, 0x7632);
            Bl[nxt][(4 * hq + 2) * LD + sp] = __byte_perm(rla.y, rlb.y, 0x5410);
            Bl[nxt][(4 * hq + 3) * LD + sp] = __byte_perm(rla.y, rlb.y, 0x7632);
        }
    }
#pragma unroll
    for (int i = 0; i < 4; i++)
#pragma unroll
        for (int j = 0; j < 4; j++) {
            int row = t0 + wm + 16 * i + g;
            int col = wn + 8 * j + 2 * t;
            float* p0 = res + (size_t)(b * T + row) * H + col;
            float* p1 = res + (size_t)(b * T + row + 8) * H + col;
            atomicAdd(p0,     acc[i][j][0]);
            atomicAdd(p0 + 1, acc[i][j][1]);
            atomicAdd(p1,     acc[i][j][2]);
            atomicAdd(p1 + 1, acc[i][j][3]);
        }
}

// ---------------------------------------------------------------------------
extern "C" void kernel_launch(void* const* d_in, const int* in_sizes, int n_in,
                              void* d_out, int out_size)
{
    const float* x  = (const float*)d_in[0];
    const float* Wq = (const float*)d_in[1];
    const float* Wk = (const float*)d_in[2];
    const float* Wv = (const float*)d_in[3];
    float* res  = (float*)d_out;
    float* attn = res + (size_t)B * T * H;

    cudaMemsetAsync(res, 0, (size_t)NR * H * sizeof(float));
    proj_mma_kernel<<<dim3(NR / 128, 3), 256>>>(x, Wq, Wk, Wv);
    split_kernel<<<NR / 8, 256>>>();
    score_mma_kernel<<<dim3(136, 8), 256>>>(attn);
    softmax_kernel<<<NR, 256>>>(attn);
    pv_mma_kernel<<<dim3(72, 8), 256>>>(attn, res);
}

// round 13
// speedup vs baseline: 3.7711x; 1.0250x over previous
#include <cuda_runtime.h>
#include <cuda_fp16.h>
#include <math.h>
#include <stddef.h>
#include <stdint.h>

// NOTE: harness builds via compute_103 virtual arch -> tcgen05/TMEM PTX is
// rejected by ptxas. mma.sync (HMMA) + ldmatrix is the available tensor path.

namespace {
constexpr int B = 8, T = 2048, C = 1024, H = 128;
constexpr int NR = B * T;   // 16384 rows
constexpr int LD = 12;      // smem row stride in u32 (48B rows: LDSM conflict-free)
constexpr int BUF_BYTES = 128 * LD * 4;   // one buffer of one operand array
}

// scratch (device globals: allocation-free per harness rules)
__device__ float    g_sq[NR];
__device__ float    g_sk[NR];
// pre-split packed half2 (k-pair) operands
__device__ uint32_t g_qh[NR * 64], g_ql[NR * 64];
__device__ uint32_t g_kh[NR * 64], g_kl[NR * 64];
__device__ uint32_t g_vh[NR * 64], g_vl[NR * 64];   // plain h-order halves

// ---------------------------------------------------------------------------
__device__ __forceinline__ uint32_t smem_u32(const void* p) {
    uint32_t a;
    asm("{ .reg .u64 t; cvta.to.shared.u64 t, %1; cvt.u32.u64 %0, t; }" : "=r"(a) : "l"(p));
    return a;
}

__device__ __forceinline__ void splitH4(float4 v, uint32_t& h0, uint32_t& h1,
                                        uint32_t& l0, uint32_t& l1) {
    __half2 a = __floats2half2_rn(v.x, v.y);
    __half2 b = __floats2half2_rn(v.z, v.w);
    float2 af = __half22float2(a), bf = __half22float2(b);
    __half2 al = __floats2half2_rn(v.x - af.x, v.y - af.y);
    __half2 bl = __floats2half2_rn(v.z - bf.x, v.w - bf.y);
    h0 = *(uint32_t*)&a;  h1 = *(uint32_t*)&b;
    l0 = *(uint32_t*)&al; l1 = *(uint32_t*)&bl;
}

__device__ __forceinline__ void splitH2(float a, float b, uint32_t& h, uint32_t& l) {
    __half2 hh = __floats2half2_rn(a, b);
    float2 hf = __half22float2(hh);
    __half2 ll = __floats2half2_rn(a - hf.x, b - hf.y);
    h = *(uint32_t*)&hh; l = *(uint32_t*)&ll;
}

#define MMAH(c, a, b) \
    asm volatile("mma.sync.aligned.m16n8k16.row.col.f32.f16.f16.f32 " \
        "{%0,%1,%2,%3},{%4,%5,%6,%7},{%8,%9},{%0,%1,%2,%3};" \
        : "+f"((c)[0]), "+f"((c)[1]), "+f"((c)[2]), "+f"((c)[3]) \
        : "r"((a)[0]), "r"((a)[1]), "r"((a)[2]), "r"((a)[3]), \
          "r"((b)[0]), "r"((b)[1]))

__device__ __forceinline__ void ldsm_x4(uint32_t addr, uint32_t* r) {
    asm volatile("ldmatrix.sync.aligned.m8n8.x4.shared.b16 {%0,%1,%2,%3}, [%4];"
        : "=r"(r[0]), "=r"(r[1]), "=r"(r[2]), "=r"(r[3]) : "r"(addr));
}

// one k16 slab via ldmatrix: A [row][kpair] LD, B [n][kpair] LD, 3-pass hi/lo
__device__ __forceinline__ void mma_slab(
    uint32_t aAh, uint32_t aAl, uint32_t aBh, uint32_t aBl,
    const uint32_t* aoff, const uint32_t* boff, float acc[4][4][4])
{
    uint32_t ah[4][4], al[4][4], bh[4][2], bl[4][2];
#pragma unroll
    for (int i = 0; i < 4; i++) {
        ldsm_x4(aAh + aoff[i], ah[i]);
        ldsm_x4(aAl + aoff[i], al[i]);
    }
#pragma unroll
    for (int p = 0; p < 2; p++) {
        uint32_t rb[4];
        ldsm_x4(aBh + boff[p], rb);
        bh[2 * p][0] = rb[0]; bh[2 * p + 1][0] = rb[1];
        bh[2 * p][1] = rb[2]; bh[2 * p + 1][1] = rb[3];
        ldsm_x4(aBl + boff[p], rb);
        bl[2 * p][0] = rb[0]; bl[2 * p + 1][0] = rb[1];
        bl[2 * p][1] = rb[2]; bl[2 * p + 1][1] = rb[3];
    }
#pragma unroll
    for (int i = 0; i < 4; i++)
#pragma unroll
        for (int j = 0; j < 4; j++) {
            MMAH(acc[i][j], ah[i], bh[j]);
            MMAH(acc[i][j], al[i], bh[j]);
            MMAH(acc[i][j], ah[i], bl[j]);
        }
}

// per-warp ldmatrix address offsets (bytes) within one operand buffer
#define MAKE_LDSM_OFFSETS()                                              \
    uint32_t aoff[4], boff[2];                                           \
    {                                                                    \
        const int l15 = lane & 15, lhi = lane >> 4;                      \
        _Pragma("unroll")                                                \
        for (int i = 0; i < 4; i++)                                      \
            aoff[i] = (uint32_t)((wm + 16 * i + l15) * 48 + lhi * 16);   \
        _Pragma("unroll")                                                \
        for (int p = 0; p < 2; p++)                                      \
            boff[p] = (uint32_t)((wn + 16 * p + l15) * 48 + lhi * 16);   \
    }

// ---------------------------------------------------------------------------
// proj: q/k/v = x @ W^T (fp16 hi/lo, double-buffered, ldmatrix).
// Epilogue writes PRE-SPLIT half pairs directly + block row-sums (q,k).
__global__ __launch_bounds__(256) void proj_mma_kernel(
    const float* __restrict__ x, const float* __restrict__ Wq,
    const float* __restrict__ Wk, const float* __restrict__ Wv)
{
    __shared__ uint32_t Ah[2][128 * LD], Al[2][128 * LD];
    __shared__ uint32_t Bh[2][128 * LD], Bl[2][128 * LD];
    __shared__ float ssum[128];
    const int which = blockIdx.y;
    const float* W = (which == 0) ? Wq : (which == 1) ? Wk : Wv;
    uint32_t* outh = (which == 0) ? g_qh : (which == 1) ? g_kh : g_vh;
    uint32_t* outl = (which == 0) ? g_ql : (which == 1) ? g_kl : g_vl;
    const int m0 = blockIdx.x * 128;
    const int tid = threadIdx.x;
    const int w = tid >> 5, lane = tid & 31;
    const int wm = (w & 1) * 64, wn = (w >> 1) * 32;
    const int g = lane >> 2, t = lane & 3;
    const int pr = tid >> 1, pc = (tid & 1) * 4;   // pc in u32 pairs (0 or 4)

    MAKE_LDSM_OFFSETS();
    const uint32_t bAh = smem_u32(&Ah[0][0]), bAl = smem_u32(&Al[0][0]);
    const uint32_t bBh = smem_u32(&Bh[0][0]), bBl = smem_u32(&Bl[0][0]);

    if (tid < 128) ssum[tid] = 0.f;

    const float* ap = x + (size_t)(m0 + pr) * C + pc * 2;
    const float* bp = W + (size_t)pr * C + pc * 2;

    float4 rA0 = *(const float4*)ap, rA1 = *(const float4*)(ap + 4);
    float4 rB0 = *(const float4*)bp, rB1 = *(const float4*)(bp + 4);

    float acc[4][4][4];
#pragma unroll
    for (int i = 0; i < 4; i++)
#pragma unroll
        for (int j = 0; j < 4; j++)
#pragma unroll
            for (int q = 0; q < 4; q++) acc[i][j][q] = 0.f;

    const int NS = C / 16;
    {
        uint32_t h0, h1, h2, h3, l0, l1, l2, l3;
        splitH4(rA0, h0, h1, l0, l1); splitH4(rA1, h2, h3, l2, l3);
        *(uint4*)&Ah[0][pr * LD + pc] = make_uint4(h0, h1, h2, h3);
        *(uint4*)&Al[0][pr * LD + pc] = make_uint4(l0, l1, l2, l3);
        splitH4(rB0, h0, h1, l0, l1); splitH4(rB1, h2, h3, l2, l3);
        *(uint4*)&Bh[0][pr * LD + pc] = make_uint4(h0, h1, h2, h3);
        *(uint4*)&Bl[0][pr * LD + pc] = make_uint4(l0, l1, l2, l3);
    }
#pragma unroll 1
    for (int s = 0; s < NS; s++) {
        const int cur = s & 1, nxt = cur ^ 1;
        const uint32_t bo = (uint32_t)(cur * BUF_BYTES);
        __syncthreads();
        if (s + 1 < NS) {
            rA0 = *(const float4*)(ap + (s + 1) * 16);
            rA1 = *(const float4*)(ap + (s + 1) * 16 + 4);
            rB0 = *(const float4*)(bp + (s + 1) * 16);
            rB1 = *(const float4*)(bp + (s + 1) * 16 + 4);
        }
        mma_slab(bAh + bo, bAl + bo, bBh + bo, bBl + bo, aoff, boff, acc);
        if (s + 1 < NS) {
            uint32_t h0, h1, h2, h3, l0, l1, l2, l3;
            splitH4(rA0, h0, h1, l0, l1); splitH4(rA1, h2, h3, l2, l3);
            *(uint4*)&Ah[nxt][pr * LD + pc] = make_uint4(h0, h1, h2, h3);
            *(uint4*)&Al[nxt][pr * LD + pc] = make_uint4(l0, l1, l2, l3);
            splitH4(rB0, h0, h1, l0, l1); splitH4(rB1, h2, h3, l2, l3);
            *(uint4*)&Bh[nxt][pr * LD + pc] = make_uint4(h0, h1, h2, h3);
            *(uint4*)&Bl[nxt][pr * LD + pc] = make_uint4(l0, l1, l2, l3);
        }
    }
    // epilogue: split to halves in-register, write pairs, reduce row sums
#pragma unroll
    for (int i = 0; i < 4; i++) {
        const int r0 = wm + 16 * i + g;      // block-local rows r0, r0+8
        float s0 = 0.f, s1 = 0.f;
#pragma unroll
        for (int j = 0; j < 4; j++) {
            const int p = (wn >> 1) + 4 * j + t;   // k-pair index (col/2)
            uint32_t h, l;
            splitH2(acc[i][j][0], acc[i][j][1], h, l);
            outh[(size_t)(m0 + r0) * 64 + p] = h;
            outl[(size_t)(m0 + r0) * 64 + p] = l;
            s0 += acc[i][j][0] + acc[i][j][1];
            splitH2(acc[i][j][2], acc[i][j][3], h, l);
            outh[(size_t)(m0 + r0 + 8) * 64 + p] = h;
            outl[(size_t)(m0 + r0 + 8) * 64 + p] = l;
            s1 += acc[i][j][2] + acc[i][j][3];
        }
        if (which != 2) {
            atomicAdd(&ssum[r0], s0);
            atomicAdd(&ssum[r0 + 8], s1);
        }
    }
    if (which != 2) {
        __syncthreads();
        if (tid < 128) {
            float* gs = (which == 0) ? g_sq : g_sk;
            gs[m0 + tid] = ssum[tid];
        }
    }
}

// ---------------------------------------------------------------------------
// score: raw S = q.k over lower-band 128x128 tiles (fp16 hi/lo, pre-split,
// double-buffered, ldmatrix)
__global__ __launch_bounds__(256) void score_mma_kernel(float* __restrict__ attn)
{
    __shared__ uint32_t Ah[2][128 * LD], Al[2][128 * LD];
    __shared__ uint32_t Bh[2][128 * LD], Bl[2][128 * LD];
    const int b = blockIdx.y;
    const int idx = blockIdx.x;
    int ti = (int)((sqrtf(8.f * (float)idx + 1.f) - 1.f) * 0.5f);
    if (ti > 15) ti = 15;
    while ((ti + 1) * (ti + 2) / 2 <= idx) ti++;
    while (ti * (ti + 1) / 2 > idx) ti--;
    const int tj = idx - ti * (ti + 1) / 2;
    const int t0 = ti * 128, s0 = tj * 128;

    const int tid = threadIdx.x;
    const int w = tid >> 5, lane = tid & 31;
    const int wm = (w & 1) * 64, wn = (w >> 1) * 32;
    const int g = lane >> 2, t = lane & 3;
    const int pr = tid >> 1, pc = (tid & 1) * 4;

    MAKE_LDSM_OFFSETS();
    const uint32_t bAh = smem_u32(&Ah[0][0]), bAl = smem_u32(&Al[0][0]);
    const uint32_t bBh = smem_u32(&Bh[0][0]), bBl = smem_u32(&Bl[0][0]);

    const uint32_t* qh = g_qh + (size_t)(b * T + t0 + pr) * 64 + pc;
    const uint32_t* ql = g_ql + (size_t)(b * T + t0 + pr) * 64 + pc;
    const uint32_t* kh = g_kh + (size_t)(b * T + s0 + pr) * 64 + pc;
    const uint32_t* kl = g_kl + (size_t)(b * T + s0 + pr) * 64 + pc;

    uint4 rAh = *(const uint4*)qh, rAl = *(const uint4*)ql;
    uint4 rBh = *(const uint4*)kh, rBl = *(const uint4*)kl;

    float acc[4][4][4];
#pragma unroll
    for (int i = 0; i < 4; i++)
#pragma unroll
        for (int j = 0; j < 4; j++)
#pragma unroll
            for (int q = 0; q < 4; q++) acc[i][j][q] = 0.f;

    const int NS = H / 16;  // 8
    *(uint4*)&Ah[0][pr * LD + pc] = rAh;
    *(uint4*)&Al[0][pr * LD + pc] = rAl;
    *(uint4*)&Bh[0][pr * LD + pc] = rBh;
    *(uint4*)&Bl[0][pr * LD + pc] = rBl;
#pragma unroll 1
    for (int s = 0; s < NS; s++) {
        const int cur = s & 1, nxt = cur ^ 1;
        const uint32_t bo = (uint32_t)(cur * BUF_BYTES);
        __syncthreads();
        if (s + 1 < NS) {
            rAh = *(const uint4*)(qh + (s + 1) * 8);
            rAl = *(const uint4*)(ql + (s + 1) * 8);
            rBh = *(const uint4*)(kh + (s + 1) * 8);
            rBl = *(const uint4*)(kl + (s + 1) * 8);
        }
        mma_slab(bAh + bo, bAl + bo, bBh + bo, bBl + bo, aoff, boff, acc);
        if (s + 1 < NS) {
            *(uint4*)&Ah[nxt][pr * LD + pc] = rAh;
            *(uint4*)&Al[nxt][pr * LD + pc] = rAl;
            *(uint4*)&Bh[nxt][pr * LD + pc] = rBh;
            *(uint4*)&Bl[nxt][pr * LD + pc] = rBl;
        }
    }
#pragma unroll
    for (int i = 0; i < 4; i++)
#pragma unroll
        for (int j = 0; j < 4; j++) {
            int row = t0 + wm + 16 * i + g;
            int col = s0 + wn + 8 * j + 2 * t;
            *(float2*)&attn[(size_t)(b * T + row) * T + col]     = make_float2(acc[i][j][0], acc[i][j][1]);
            *(float2*)&attn[(size_t)(b * T + row + 8) * T + col] = make_float2(acc[i][j][2], acc[i][j][3]);
        }
}

// ---------------------------------------------------------------------------
// softmax: in-place per row; band-only reads, adds pos terms, masks, normalizes.
__global__ __launch_bounds__(256) void softmax_kernel(float* __restrict__ attn)
{
    __shared__ float red[8];
    const int r = blockIdx.x;
    const int b = r >> 11;
    const int t = r & (T - 1);
    float* row = attn + (size_t)r * T;
    const float* skrow = g_sk + (size_t)b * T;
    const float sq = g_sq[r];
    const float tf = (float)t;
    const int tid = threadIdx.x;
    const int c0 = tid * 8;
    const bool act = (c0 <= t);       // any live column in this thread's span

    float qk[8] = {0, 0, 0, 0, 0, 0, 0, 0};
    float sk[8] = {0, 0, 0, 0, 0, 0, 0, 0};
    if (act) {
        float4 v0 = *(const float4*)(row + c0);
        float4 v1 = *(const float4*)(row + c0 + 4);
        float4 s0 = *(const float4*)(skrow + c0);
        float4 s1 = *(const float4*)(skrow + c0 + 4);
        qk[0] = v0.x; qk[1] = v0.y; qk[2] = v0.z; qk[3] = v0.w;
        qk[4] = v1.x; qk[5] = v1.y; qk[6] = v1.z; qk[7] = v1.w;
        sk[0] = s0.x; sk[1] = s0.y; sk[2] = s0.z; sk[3] = s0.w;
        sk[4] = s1.x; sk[5] = s1.y; sk[6] = s1.z; sk[7] = s1.w;
    }

    float lg[8];
    float mx = -INFINITY;
#pragma unroll
    for (int j = 0; j < 8; j++) {
        int s = c0 + j;
        float v = (qk[j] + (float)s * sq + tf * sk[j] + 128.f * (float)(t * s)) * 0.03125f;
        lg[j] = (s <= t) ? v : -INFINITY;
        mx = fmaxf(mx, lg[j]);
    }
#pragma unroll
    for (int o = 16; o > 0; o >>= 1)
        mx = fmaxf(mx, __shfl_xor_sync(0xffffffffu, mx, o));
    if ((tid & 31) == 0) red[tid >> 5] = mx;
    __syncthreads();
    float m = red[0];
#pragma unroll
    for (int i = 1; i < 8; i++) m = fmaxf(m, red[i]);
    __syncthreads();

    float ev[8];
    float sum = 0.f;
#pragma unroll
    for (int j = 0; j < 8; j++) {
        ev[j] = __expf(lg[j] - m);
        sum += ev[j];
    }
#pragma unroll
    for (int o = 16; o > 0; o >>= 1)
        sum += __shfl_xor_sync(0xffffffffu, sum, o);
    if ((tid & 31) == 0) red[tid >> 5] = sum;
    __syncthreads();
    float tot = red[0];
#pragma unroll
    for (int i = 1; i < 8; i++) tot += red[i];
    const float rinv = 1.f / tot;

    *(float4*)(row + c0)     = make_float4(ev[0] * rinv, ev[1] * rinv, ev[2] * rinv, ev[3] * rinv);
    *(float4*)(row + c0 + 4) = make_float4(ev[4] * rinv, ev[5] * rinv, ev[6] * rinv, ev[7] * rinv);
}

// ---------------------------------------------------------------------------
// pv: res += attn_chunk @ v_chunk (fp16 hi/lo 3-pass, split-K 256-wide chunks,
// atomicAdd into zeroed res, double-buffered, ldmatrix). B staged transposed.
__global__ __launch_bounds__(256) void pv_mma_kernel(
    const float* __restrict__ attn, float* __restrict__ res)
{
    __shared__ uint32_t Ah[2][128 * LD], Al[2][128 * LD];
    __shared__ uint32_t Bh[2][128 * LD], Bl[2][128 * LD];
    const int b = blockIdx.y;
    int bx = blockIdx.x;
    int kt = 15, chunk = 0;
#pragma unroll
    for (int k = 15; k >= 0; k--) {
        int cnt = (k + 2) >> 1;
        if (bx < cnt) { kt = k; chunk = bx; break; }
        bx -= cnt;
    }
    const int t0 = kt * 128;
    const int sbeg = chunk * 256;
    const int send = min(sbeg + 256, (kt + 1) * 128);
    const int NS = (send - sbeg) >> 4;

    const int tid = threadIdx.x;
    const int w = tid >> 5, lane = tid & 31;
    const int wm = (w & 1) * 64, wn = (w >> 1) * 32;
    const int g = lane >> 2, t = lane & 3;
    const int pr = tid >> 1, pc = (tid & 1) * 4;   // A stager
    const int sp = tid & 7, hq = tid >> 3;         // B stager: s-pair, h-quad

    MAKE_LDSM_OFFSETS();
    const uint32_t bAh = smem_u32(&Ah[0][0]), bAl = smem_u32(&Al[0][0]);
    const uint32_t bBh = smem_u32(&Bh[0][0]), bBl = smem_u32(&Bl[0][0]);

    const float* ap = attn + (size_t)(b * T + t0 + pr) * T + sbeg + pc * 2;
    const uint32_t* vh = g_vh + (size_t)(b * T + sbeg + 2 * sp) * 64 + 2 * hq;
    const uint32_t* vl = g_vl + (size_t)(b * T + sbeg + 2 * sp) * 64 + 2 * hq;

    float4 rA0 = *(const float4*)ap, rA1 = *(const float4*)(ap + 4);
    uint2 rha = *(const uint2*)vh,   rhb = *(const uint2*)(vh + 64);
    uint2 rla = *(const uint2*)vl,   rlb = *(const uint2*)(vl + 64);

    float acc[4][4][4];
#pragma unroll
    for (int i = 0; i < 4; i++)
#pragma unroll
        for (int j = 0; j < 4; j++)
#pragma unroll
            for (int q = 0; q < 4; q++) acc[i][j][q] = 0.f;

    {
        uint32_t h0, h1, h2, h3, l0, l1, l2, l3;
        splitH4(rA0, h0, h1, l0, l1); splitH4(rA1, h2, h3, l2, l3);
        *(uint4*)&Ah[0][pr * LD + pc] = make_uint4(h0, h1, h2, h3);
        *(uint4*)&Al[0][pr * LD + pc] = make_uint4(l0, l1, l2, l3);
        Bh[0][(4 * hq + 0) * LD + sp] = __byte_perm(rha.x, rhb.x, 0x5410);
        Bh[0][(4 * hq + 1) * LD + sp] = __byte_perm(rha.x, rhb.x, 0x7632);
        Bh[0][(4 * hq + 2) * LD + sp] = __byte_perm(rha.y, rhb.y, 0x5410);
        Bh[0][(4 * hq + 3) * LD + sp] = __byte_perm(rha.y, rhb.y, 0x7632);
        Bl[0][(4 * hq + 0) * LD + sp] = __byte_perm(rla.x, rlb.x, 0x5410);
        Bl[0][(4 * hq + 1) * LD + sp] = __byte_perm(rla.x, rlb.x, 0x7632);
        Bl[0][(4 * hq + 2) * LD + sp] = __byte_perm(rla.y, rlb.y, 0x5410);
        Bl[0][(4 * hq + 3) * LD + sp] = __byte_perm(rla.y, rlb.y, 0x7632);
    }
#pragma unroll 1
    for (int s = 0; s < NS; s++) {
        const int cur = s & 1, nxt = cur ^ 1;
        const uint32_t bo = (uint32_t)(cur * BUF_BYTES);
        __syncthreads();
        if (s + 1 < NS) {
            rA0 = *(const float4*)(ap + (s + 1) * 16);
            rA1 = *(const float4*)(ap + (s + 1) * 16 + 4);
            const uint32_t* vh2 = vh + (size_t)(s + 1) * 16 * 64;
            const uint32_t* vl2 = vl + (size_t)(s + 1) * 16 * 64;
            rha = *(const uint2*)vh2; rhb = *(const uint2*)(vh2 + 64);
            rla = *(const uint2*)vl2; rlb = *(const uint2*)(vl2 + 64);
        }
        mma_slab(bAh + bo, bAl + bo, bBh + bo, bBl + bo, aoff, boff, acc);
        if (s + 1 < NS) {
            uint32_t h0, h1, h2, h3, l0, l1, l2, l3;
            splitH4(rA0, h0, h1, l0, l1); splitH4(rA1, h2, h3, l2, l3);
            *(uint4*)&Ah[nxt][pr * LD + pc] = make_uint4(h0, h1, h2, h3);
            *(uint4*)&Al[nxt][pr * LD + pc] = make_uint4(l0, l1, l2, l3);
            Bh[nxt][(4 * hq + 0) * LD + sp] = __byte_perm(rha.x, rhb.x, 0x5410);
            Bh[nxt][(4 * hq + 1) * LD + sp] = __byte_perm(rha.x, rhb.x, 0x7632);
            Bh[nxt][(4 * hq + 2) * LD + sp] = __byte_perm(rha.y, rhb.y, 0x5410);
            Bh[nxt][(4 * hq + 3) * LD + sp] = __byte_perm(rha.y, rhb.y, 0x7632);
            Bl[nxt][(4 * hq + 0) * LD + sp] = __byte_perm(rla.x, rlb.x, 0x5410);
            Bl[nxt][(4 * hq + 1) * LD + sp] = __byte_perm(rla.x, rlb.x, 0x7632);
            Bl[nxt][(4 * hq + 2) * LD + sp] = __byte_perm(rla.y, rlb.y, 0x5410);
            Bl[nxt][(4 * hq + 3) * LD + sp] = __byte_perm(rla.y, rlb.y, 0x7632);
        }
    }
#pragma unroll
    for (int i = 0; i < 4; i++)
#pragma unroll
        for (int j = 0; j < 4; j++) {
            int row = t0 + wm + 16 * i + g;
            int col = wn + 8 * j + 2 * t;
            float* p0 = res + (size_t)(b * T + row) * H + col;
            float* p1 = res + (size_t)(b * T + row + 8) * H + col;
            atomicAdd(p0,     acc[i][j][0]);
            atomicAdd(p0 + 1, acc[i][j][1]);
            atomicAdd(p1,     acc[i][j][2]);
            atomicAdd(p1 + 1, acc[i][j][3]);
        }
}

// ---------------------------------------------------------------------------
extern "C" void kernel_launch(void* const* d_in, const int* in_sizes, int n_in,
                              void* d_out, int out_size)
{
    const float* x  = (const float*)d_in[0];
    const float* Wq = (const float*)d_in[1];
    const float* Wk = (const float*)d_in[2];
    const float* Wv = (const float*)d_in[3];
    float* res  = (float*)d_out;
    float* attn = res + (size_t)B * T * H;

    cudaMemsetAsync(res, 0, (size_t)NR * H * sizeof(float));
    proj_mma_kernel<<<dim3(NR / 128, 3), 256>>>(x, Wq, Wk, Wv);
    score_mma_kernel<<<dim3(136, 8), 256>>>(attn);
    softmax_kernel<<<NR, 256>>>(attn);
    pv_mma_kernel<<<dim3(72, 8), 256>>>(attn, res);
}

// round 14
// speedup vs baseline: 4.0075x; 1.0627x over previous
#include <cuda_runtime.h>
#include <cuda_fp16.h>
#include <math.h>
#include <stddef.h>
#include <stdint.h>

// NOTE: harness builds via compute_103 virtual arch -> tcgen05/TMEM PTX is
// rejected by ptxas. mma.sync (HMMA) + ldmatrix is the available tensor path.

namespace {
constexpr int B = 8, T = 2048, C = 1024, H = 128;
constexpr int NR = B * T;   // 16384 rows
constexpr int LD = 12;      // smem row stride in u32 (48B rows: LDSM conflict-free)
constexpr int BUF_BYTES = 128 * LD * 4;   // one buffer of one operand array
}

// scratch (device globals: allocation-free per harness rules)
__device__ float    g_sq[NR];
__device__ float    g_sk[NR];
// pre-split packed half2 (k-pair) operands (q: hi only — residual unused)
__device__ uint32_t g_qh[NR * 64];
__device__ uint32_t g_kh[NR * 64], g_kl[NR * 64];
__device__ uint32_t g_vh[NR * 64], g_vl[NR * 64];   // plain h-order halves

// ---------------------------------------------------------------------------
__device__ __forceinline__ uint32_t smem_u32(const void* p) {
    uint32_t a;
    asm("{ .reg .u64 t; cvta.to.shared.u64 t, %1; cvt.u32.u64 %0, t; }" : "=r"(a) : "l"(p));
    return a;
}

__device__ __forceinline__ void splitH4(float4 v, uint32_t& h0, uint32_t& h1,
                                        uint32_t& l0, uint32_t& l1) {
    __half2 a = __floats2half2_rn(v.x, v.y);
    __half2 b = __floats2half2_rn(v.z, v.w);
    float2 af = __half22float2(a), bf = __half22float2(b);
    __half2 al = __floats2half2_rn(v.x - af.x, v.y - af.y);
    __half2 bl = __floats2half2_rn(v.z - bf.x, v.w - bf.y);
    h0 = *(uint32_t*)&a;  h1 = *(uint32_t*)&b;
    l0 = *(uint32_t*)&al; l1 = *(uint32_t*)&bl;
}

__device__ __forceinline__ void cvtH4(float4 v, uint32_t& h0, uint32_t& h1) {
    __half2 a = __floats2half2_rn(v.x, v.y);
    __half2 b = __floats2half2_rn(v.z, v.w);
    h0 = *(uint32_t*)&a; h1 = *(uint32_t*)&b;
}

__device__ __forceinline__ void splitH2(float a, float b, uint32_t& h, uint32_t& l) {
    __half2 hh = __floats2half2_rn(a, b);
    float2 hf = __half22float2(hh);
    __half2 ll = __floats2half2_rn(a - hf.x, b - hf.y);
    h = *(uint32_t*)&hh; l = *(uint32_t*)&ll;
}

#define MMAH(c, a, b) \
    asm volatile("mma.sync.aligned.m16n8k16.row.col.f32.f16.f16.f32 " \
        "{%0,%1,%2,%3},{%4,%5,%6,%7},{%8,%9},{%0,%1,%2,%3};" \
        : "+f"((c)[0]), "+f"((c)[1]), "+f"((c)[2]), "+f"((c)[3]) \
        : "r"((a)[0]), "r"((a)[1]), "r"((a)[2]), "r"((a)[3]), \
          "r"((b)[0]), "r"((b)[1]))

__device__ __forceinline__ void ldsm_x4(uint32_t addr, uint32_t* r) {
    asm volatile("ldmatrix.sync.aligned.m8n8.x4.shared.b16 {%0,%1,%2,%3}, [%4];"
        : "=r"(r[0]), "=r"(r[1]), "=r"(r[2]), "=r"(r[3]) : "r"(addr));
}

// 3-pass slab: hh + lh + hl
__device__ __forceinline__ void mma_slab3(
    uint32_t aAh, uint32_t aAl, uint32_t aBh, uint32_t aBl,
    const uint32_t* aoff, const uint32_t* boff, float acc[4][4][4])
{
    uint32_t ah[4][4], al[4][4], bh[4][2], bl[4][2];
#pragma unroll
    for (int i = 0; i < 4; i++) {
        ldsm_x4(aAh + aoff[i], ah[i]);
        ldsm_x4(aAl + aoff[i], al[i]);
    }
#pragma unroll
    for (int p = 0; p < 2; p++) {
        uint32_t rb[4];
        ldsm_x4(aBh + boff[p], rb);
        bh[2 * p][0] = rb[0]; bh[2 * p + 1][0] = rb[1];
        bh[2 * p][1] = rb[2]; bh[2 * p + 1][1] = rb[3];
        ldsm_x4(aBl + boff[p], rb);
        bl[2 * p][0] = rb[0]; bl[2 * p + 1][0] = rb[1];
        bl[2 * p][1] = rb[2]; bl[2 * p + 1][1] = rb[3];
    }
#pragma unroll
    for (int i = 0; i < 4; i++)
#pragma unroll
        for (int j = 0; j < 4; j++) {
            MMAH(acc[i][j], ah[i], bh[j]);
            MMAH(acc[i][j], al[i], bh[j]);
            MMAH(acc[i][j], ah[i], bl[j]);
        }
}

// 2-pass slab: hh + hl (A hi only; error lands in logits only)
__device__ __forceinline__ void mma_slab2(
    uint32_t aAh, uint32_t aBh, uint32_t aBl,
    const uint32_t* aoff, const uint32_t* boff, float acc[4][4][4])
{
    uint32_t ah[4][4], bh[4][2], bl[4][2];
#pragma unroll
    for (int i = 0; i < 4; i++)
        ldsm_x4(aAh + aoff[i], ah[i]);
#pragma unroll
    for (int p = 0; p < 2; p++) {
        uint32_t rb[4];
        ldsm_x4(aBh + boff[p], rb);
        bh[2 * p][0] = rb[0]; bh[2 * p + 1][0] = rb[1];
        bh[2 * p][1] = rb[2]; bh[2 * p + 1][1] = rb[3];
        ldsm_x4(aBl + boff[p], rb);
        bl[2 * p][0] = rb[0]; bl[2 * p + 1][0] = rb[1];
        bl[2 * p][1] = rb[2]; bl[2 * p + 1][1] = rb[3];
    }
#pragma unroll
    for (int i = 0; i < 4; i++)
#pragma unroll
        for (int j = 0; j < 4; j++) {
            MMAH(acc[i][j], ah[i], bh[j]);
            MMAH(acc[i][j], ah[i], bl[j]);
        }
}

// per-warp ldmatrix address offsets (bytes) within one operand buffer
#define MAKE_LDSM_OFFSETS()                                              \
    uint32_t aoff[4], boff[2];                                           \
    {                                                                    \
        const int l15 = lane & 15, lhi = lane >> 4;                      \
        _Pragma("unroll")                                                \
        for (int i = 0; i < 4; i++)                                      \
            aoff[i] = (uint32_t)((wm + 16 * i + l15) * 48 + lhi * 16);   \
        _Pragma("unroll")                                                \
        for (int p = 0; p < 2; p++)                                      \
            boff[p] = (uint32_t)((wn + 16 * p + l15) * 48 + lhi * 16);   \
    }

// ---------------------------------------------------------------------------
// proj q/k: 2-pass (x hi only; W hi/lo). Writes pre-split halves + row sums.
__global__ __launch_bounds__(256) void proj_qk_kernel(
    const float* __restrict__ x, const float* __restrict__ Wq,
    const float* __restrict__ Wk)
{
    __shared__ uint32_t Ah[2][128 * LD];
    __shared__ uint32_t Bh[2][128 * LD], Bl[2][128 * LD];
    __shared__ float ssum[128];
    const int isQ = (blockIdx.y == 0);
    const float* W = isQ ? Wq : Wk;
    const int m0 = blockIdx.x * 128;
    const int tid = threadIdx.x;
    const int w = tid >> 5, lane = tid & 31;
    const int wm = (w & 1) * 64, wn = (w >> 1) * 32;
    const int g = lane >> 2, t = lane & 3;
    const int pr = tid >> 1, pc = (tid & 1) * 4;

    MAKE_LDSM_OFFSETS();
    const uint32_t bAh = smem_u32(&Ah[0][0]);
    const uint32_t bBh = smem_u32(&Bh[0][0]), bBl = smem_u32(&Bl[0][0]);

    if (tid < 128) ssum[tid] = 0.f;

    const float* ap = x + (size_t)(m0 + pr) * C + pc * 2;
    const float* bp = W + (size_t)pr * C + pc * 2;

    float4 rA0 = *(const float4*)ap, rA1 = *(const float4*)(ap + 4);
    float4 rB0 = *(const float4*)bp, rB1 = *(const float4*)(bp + 4);

    float acc[4][4][4];
#pragma unroll
    for (int i = 0; i < 4; i++)
#pragma unroll
        for (int j = 0; j < 4; j++)
#pragma unroll
            for (int q = 0; q < 4; q++) acc[i][j][q] = 0.f;

    const int NS = C / 16;
    {
        uint32_t h0, h1, h2, h3, l0, l1, l2, l3;
        cvtH4(rA0, h0, h1); cvtH4(rA1, h2, h3);
        *(uint4*)&Ah[0][pr * LD + pc] = make_uint4(h0, h1, h2, h3);
        splitH4(rB0, h0, h1, l0, l1); splitH4(rB1, h2, h3, l2, l3);
        *(uint4*)&Bh[0][pr * LD + pc] = make_uint4(h0, h1, h2, h3);
        *(uint4*)&Bl[0][pr * LD + pc] = make_uint4(l0, l1, l2, l3);
    }
#pragma unroll 1
    for (int s = 0; s < NS; s++) {
        const int cur = s & 1, nxt = cur ^ 1;
        const uint32_t bo = (uint32_t)(cur * BUF_BYTES);
        __syncthreads();
        if (s + 1 < NS) {
            rA0 = *(const float4*)(ap + (s + 1) * 16);
            rA1 = *(const float4*)(ap + (s + 1) * 16 + 4);
            rB0 = *(const float4*)(bp + (s + 1) * 16);
            rB1 = *(const float4*)(bp + (s + 1) * 16 + 4);
        }
        mma_slab2(bAh + bo, bBh + bo, bBl + bo, aoff, boff, acc);
        if (s + 1 < NS) {
            uint32_t h0, h1, h2, h3, l0, l1, l2, l3;
            cvtH4(rA0, h0, h1); cvtH4(rA1, h2, h3);
            *(uint4*)&Ah[nxt][pr * LD + pc] = make_uint4(h0, h1, h2, h3);
            splitH4(rB0, h0, h1, l0, l1); splitH4(rB1, h2, h3, l2, l3);
            *(uint4*)&Bh[nxt][pr * LD + pc] = make_uint4(h0, h1, h2, h3);
            *(uint4*)&Bl[nxt][pr * LD + pc] = make_uint4(l0, l1, l2, l3);
        }
    }
    // epilogue: q -> hi only; k -> hi/lo; both reduce row sums
#pragma unroll
    for (int i = 0; i < 4; i++) {
        const int r0 = wm + 16 * i + g;
        float s0 = 0.f, s1 = 0.f;
#pragma unroll
        for (int j = 0; j < 4; j++) {
            const int p = (wn >> 1) + 4 * j + t;
            if (isQ) {
                __half2 h2a = __floats2half2_rn(acc[i][j][0], acc[i][j][1]);
                g_qh[(size_t)(m0 + r0) * 64 + p] = *(uint32_t*)&h2a;
                __half2 h2b = __floats2half2_rn(acc[i][j][2], acc[i][j][3]);
                g_qh[(size_t)(m0 + r0 + 8) * 64 + p] = *(uint32_t*)&h2b;
            } else {
                uint32_t h, l;
                splitH2(acc[i][j][0], acc[i][j][1], h, l);
                g_kh[(size_t)(m0 + r0) * 64 + p] = h;
                g_kl[(size_t)(m0 + r0) * 64 + p] = l;
                splitH2(acc[i][j][2], acc[i][j][3], h, l);
                g_kh[(size_t)(m0 + r0 + 8) * 64 + p] = h;
                g_kl[(size_t)(m0 + r0 + 8) * 64 + p] = l;
            }
            s0 += acc[i][j][0] + acc[i][j][1];
            s1 += acc[i][j][2] + acc[i][j][3];
        }
        atomicAdd(&ssum[r0], s0);
        atomicAdd(&ssum[r0 + 8], s1);
    }
    __syncthreads();
    if (tid < 128) {
        float* gs = isQ ? g_sq : g_sk;
        gs[m0 + tid] = ssum[tid];
    }
}

// ---------------------------------------------------------------------------
// proj v: 3-pass (res accuracy depends on v). Writes pre-split halves.
__global__ __launch_bounds__(256) void proj_v_kernel(
    const float* __restrict__ x, const float* __restrict__ Wv)
{
    __shared__ uint32_t Ah[2][128 * LD], Al[2][128 * LD];
    __shared__ uint32_t Bh[2][128 * LD], Bl[2][128 * LD];
    const int m0 = blockIdx.x * 128;
    const int tid = threadIdx.x;
    const int w = tid >> 5, lane = tid & 31;
    const int wm = (w & 1) * 64, wn = (w >> 1) * 32;
    const int g = lane >> 2, t = lane & 3;
    const int pr = tid >> 1, pc = (tid & 1) * 4;

    MAKE_LDSM_OFFSETS();
    const uint32_t bAh = smem_u32(&Ah[0][0]), bAl = smem_u32(&Al[0][0]);
    const uint32_t bBh = smem_u32(&Bh[0][0]), bBl = smem_u32(&Bl[0][0]);

    const float* ap = x + (size_t)(m0 + pr) * C + pc * 2;
    const float* bp = Wv + (size_t)pr * C + pc * 2;

    float4 rA0 = *(const float4*)ap, rA1 = *(const float4*)(ap + 4);
    float4 rB0 = *(const float4*)bp, rB1 = *(const float4*)(bp + 4);

    float acc[4][4][4];
#pragma unroll
    for (int i = 0; i < 4; i++)
#pragma unroll
        for (int j = 0; j < 4; j++)
#pragma unroll
            for (int q = 0; q < 4; q++) acc[i][j][q] = 0.f;

    const int NS = C / 16;
    {
        uint32_t h0, h1, h2, h3, l0, l1, l2, l3;
        splitH4(rA0, h0, h1, l0, l1); splitH4(rA1, h2, h3, l2, l3);
        *(uint4*)&Ah[0][pr * LD + pc] = make_uint4(h0, h1, h2, h3);
        *(uint4*)&Al[0][pr * LD + pc] = make_uint4(l0, l1, l2, l3);
        splitH4(rB0, h0, h1, l0, l1); splitH4(rB1, h2, h3, l2, l3);
        *(uint4*)&Bh[0][pr * LD + pc] = make_uint4(h0, h1, h2, h3);
        *(uint4*)&Bl[0][pr * LD + pc] = make_uint4(l0, l1, l2, l3);
    }
#pragma unroll 1
    for (int s = 0; s < NS; s++) {
        const int cur = s & 1, nxt = cur ^ 1;
        const uint32_t bo = (uint32_t)(cur * BUF_BYTES);
        __syncthreads();
        if (s + 1 < NS) {
            rA0 = *(const float4*)(ap + (s + 1) * 16);
            rA1 = *(const float4*)(ap + (s + 1) * 16 + 4);
            rB0 = *(const float4*)(bp + (s + 1) * 16);
            rB1 = *(const float4*)(bp + (s + 1) * 16 + 4);
        }
        mma_slab3(bAh + bo, bAl + bo, bBh + bo, bBl + bo, aoff, boff, acc);
        if (s + 1 < NS) {
            uint32_t h0, h1, h2, h3, l0, l1, l2, l3;
            splitH4(rA0, h0, h1, l0, l1); splitH4(rA1, h2, h3, l2, l3);
            *(uint4*)&Ah[nxt][pr * LD + pc] = make_uint4(h0, h1, h2, h3);
            *(uint4*)&Al[nxt][pr * LD + pc] = make_uint4(l0, l1, l2, l3);
            splitH4(rB0, h0, h1, l0, l1); splitH4(rB1, h2, h3, l2, l3);
            *(uint4*)&Bh[nxt][pr * LD + pc] = make_uint4(h0, h1, h2, h3);
            *(uint4*)&Bl[nxt][pr * LD + pc] = make_uint4(l0, l1, l2, l3);
        }
    }
#pragma unroll
    for (int i = 0; i < 4; i++) {
        const int r0 = wm + 16 * i + g;
#pragma unroll
        for (int j = 0; j < 4; j++) {
            const int p = (wn >> 1) + 4 * j + t;
            uint32_t h, l;
            splitH2(acc[i][j][0], acc[i][j][1], h, l);
            g_vh[(size_t)(m0 + r0) * 64 + p] = h;
            g_vl[(size_t)(m0 + r0) * 64 + p] = l;
            splitH2(acc[i][j][2], acc[i][j][3], h, l);
            g_vh[(size_t)(m0 + r0 + 8) * 64 + p] = h;
            g_vl[(size_t)(m0 + r0 + 8) * 64 + p] = l;
        }
    }
}

// ---------------------------------------------------------------------------
// score: raw S = qh.k over lower-band 128x128 tiles (2-pass: qh*(kh+kl))
__global__ __launch_bounds__(256) void score_mma_kernel(float* __restrict__ attn)
{
    __shared__ uint32_t Ah[2][128 * LD];
    __shared__ uint32_t Bh[2][128 * LD], Bl[2][128 * LD];
    const int b = blockIdx.y;
    const int idx = blockIdx.x;
    int ti = (int)((sqrtf(8.f * (float)idx + 1.f) - 1.f) * 0.5f);
    if (ti > 15) ti = 15;
    while ((ti + 1) * (ti + 2) / 2 <= idx) ti++;
    while (ti * (ti + 1) / 2 > idx) ti--;
    const int tj = idx - ti * (ti + 1) / 2;
    const int t0 = ti * 128, s0 = tj * 128;

    const int tid = threadIdx.x;
    const int w = tid >> 5, lane = tid & 31;
    const int wm = (w & 1) * 64, wn = (w >> 1) * 32;
    const int g = lane >> 2, t = lane & 3;
    const int pr = tid >> 1, pc = (tid & 1) * 4;

    MAKE_LDSM_OFFSETS();
    const uint32_t bAh = smem_u32(&Ah[0][0]);
    const uint32_t bBh = smem_u32(&Bh[0][0]), bBl = smem_u32(&Bl[0][0]);

    const uint32_t* qh = g_qh + (size_t)(b * T + t0 + pr) * 64 + pc;
    const uint32_t* kh = g_kh + (size_t)(b * T + s0 + pr) * 64 + pc;
    const uint32_t* kl = g_kl + (size_t)(b * T + s0 + pr) * 64 + pc;

    uint4 rAh = *(const uint4*)qh;
    uint4 rBh = *(const uint4*)kh, rBl = *(const uint4*)kl;

    float acc[4][4][4];
#pragma unroll
    for (int i = 0; i < 4; i++)
#pragma unroll
        for (int j = 0; j < 4; j++)
#pragma unroll
            for (int q = 0; q < 4; q++) acc[i][j][q] = 0.f;

    const int NS = H / 16;  // 8
    *(uint4*)&Ah[0][pr * LD + pc] = rAh;
    *(uint4*)&Bh[0][pr * LD + pc] = rBh;
    *(uint4*)&Bl[0][pr * LD + pc] = rBl;
#pragma unroll 1
    for (int s = 0; s < NS; s++) {
        const int cur = s & 1, nxt = cur ^ 1;
        const uint32_t bo = (uint32_t)(cur * BUF_BYTES);
        __syncthreads();
        if (s + 1 < NS) {
            rAh = *(const uint4*)(qh + (s + 1) * 8);
            rBh = *(const uint4*)(kh + (s + 1) * 8);
            rBl = *(const uint4*)(kl + (s + 1) * 8);
        }
        mma_slab2(bAh + bo, bBh + bo, bBl + bo, aoff, boff, acc);
        if (s + 1 < NS) {
            *(uint4*)&Ah[nxt][pr * LD + pc] = rAh;
            *(uint4*)&Bh[nxt][pr * LD + pc] = rBh;
            *(uint4*)&Bl[nxt][pr * LD + pc] = rBl;
        }
    }
#pragma unroll
    for (int i = 0; i < 4; i++)
#pragma unroll
        for (int j = 0; j < 4; j++) {
            int row = t0 + wm + 16 * i + g;
            int col = s0 + wn + 8 * j + 2 * t;
            *(float2*)&attn[(size_t)(b * T + row) * T + col]     = make_float2(acc[i][j][0], acc[i][j][1]);
            *(float2*)&attn[(size_t)(b * T + row + 8) * T + col] = make_float2(acc[i][j][2], acc[i][j][3]);
        }
}

// ---------------------------------------------------------------------------
// softmax: in-place per row; band-only reads, adds pos terms, masks, normalizes.
__global__ __launch_bounds__(256) void softmax_kernel(float* __restrict__ attn)
{
    __shared__ float red[8];
    const int r = blockIdx.x;
    const int b = r >> 11;
    const int t = r & (T - 1);
    float* row = attn + (size_t)r * T;
    const float* skrow = g_sk + (size_t)b * T;
    const float sq = g_sq[r];
    const float tf = (float)t;
    const int tid = threadIdx.x;
    const int c0 = tid * 8;
    const bool act = (c0 <= t);

    float qk[8] = {0, 0, 0, 0, 0, 0, 0, 0};
    float sk[8] = {0, 0, 0, 0, 0, 0, 0, 0};
    if (act) {
        float4 v0 = *(const float4*)(row + c0);
        float4 v1 = *(const float4*)(row + c0 + 4);
        float4 s0 = *(const float4*)(skrow + c0);
        float4 s1 = *(const float4*)(skrow + c0 + 4);
        qk[0] = v0.x; qk[1] = v0.y; qk[2] = v0.z; qk[3] = v0.w;
        qk[4] = v1.x; qk[5] = v1.y; qk[6] = v1.z; qk[7] = v1.w;
        sk[0] = s0.x; sk[1] = s0.y; sk[2] = s0.z; sk[3] = s0.w;
        sk[4] = s1.x; sk[5] = s1.y; sk[6] = s1.z; sk[7] = s1.w;
    }

    float lg[8];
    float mx = -INFINITY;
#pragma unroll
    for (int j = 0; j < 8; j++) {
        int s = c0 + j;
        float v = (qk[j] + (float)s * sq + tf * sk[j] + 128.f * (float)(t * s)) * 0.03125f;
        lg[j] = (s <= t) ? v : -INFINITY;
        mx = fmaxf(mx, lg[j]);
    }
#pragma unroll
    for (int o = 16; o > 0; o >>= 1)
        mx = fmaxf(mx, __shfl_xor_sync(0xffffffffu, mx, o));
    if ((tid & 31) == 0) red[tid >> 5] = mx;
    __syncthreads();
    float m = red[0];
#pragma unroll
    for (int i = 1; i < 8; i++) m = fmaxf(m, red[i]);
    __syncthreads();

    float ev[8];
    float sum = 0.f;
#pragma unroll
    for (int j = 0; j < 8; j++) {
        ev[j] = __expf(lg[j] - m);
        sum += ev[j];
    }
#pragma unroll
    for (int o = 16; o > 0; o >>= 1)
        sum += __shfl_xor_sync(0xffffffffu, sum, o);
    if ((tid & 31) == 0) red[tid >> 5] = sum;
    __syncthreads();
    float tot = red[0];
#pragma unroll
    for (int i = 1; i < 8; i++) tot += red[i];
    const float rinv = 1.f / tot;

    *(float4*)(row + c0)     = make_float4(ev[0] * rinv, ev[1] * rinv, ev[2] * rinv, ev[3] * rinv);
    *(float4*)(row + c0 + 4) = make_float4(ev[4] * rinv, ev[5] * rinv, ev[6] * rinv, ev[7] * rinv);
}

// ---------------------------------------------------------------------------
// pv: res += attn_chunk @ v_chunk (fp16 hi/lo 3-pass, uniform 128-wide split-K
// chunks, atomicAdd into zeroed res, double-buffered, ldmatrix).
__global__ __launch_bounds__(256) void pv_mma_kernel(
    const float* __restrict__ attn, float* __restrict__ res)
{
    __shared__ uint32_t Ah[2][128 * LD], Al[2][128 * LD];
    __shared__ uint32_t Bh[2][128 * LD], Bl[2][128 * LD];
    const int b = blockIdx.y;
    const int idx = blockIdx.x;
    int kt = (int)((sqrtf(8.f * (float)idx + 1.f) - 1.f) * 0.5f);
    if (kt > 15) kt = 15;
    while ((kt + 1) * (kt + 2) / 2 <= idx) kt++;
    while (kt * (kt + 1) / 2 > idx) kt--;
    const int chunk = idx - kt * (kt + 1) / 2;
    const int t0 = kt * 128;
    const int sbeg = chunk * 128;
    const int NS = 8;

    const int tid = threadIdx.x;
    const int w = tid >> 5, lane = tid & 31;
    const int wm = (w & 1) * 64, wn = (w >> 1) * 32;
    const int g = lane >> 2, t = lane & 3;
    const int pr = tid >> 1, pc = (tid & 1) * 4;   // A stager
    const int sp = tid & 7, hq = tid >> 3;         // B stager: s-pair, h-quad

    MAKE_LDSM_OFFSETS();
    const uint32_t bAh = smem_u32(&Ah[0][0]), bAl = smem_u32(&Al[0][0]);
    const uint32_t bBh = smem_u32(&Bh[0][0]), bBl = smem_u32(&Bl[0][0]);

    const float* ap = attn + (size_t)(b * T + t0 + pr) * T + sbeg + pc * 2;
    const uint32_t* vh = g_vh + (size_t)(b * T + sbeg + 2 * sp) * 64 + 2 * hq;
    const uint32_t* vl = g_vl + (size_t)(b * T + sbeg + 2 * sp) * 64 + 2 * hq;

    float4 rA0 = *(const float4*)ap, rA1 = *(const float4*)(ap + 4);
    uint2 rha = *(const uint2*)vh,   rhb = *(const uint2*)(vh + 64);
    uint2 rla = *(const uint2*)vl,   rlb = *(const uint2*)(vl + 64);

    float acc[4][4][4];
#pragma unroll
    for (int i = 0; i < 4; i++)
#pragma unroll
        for (int j = 0; j < 4; j++)
#pragma unroll
            for (int q = 0; q < 4; q++) acc[i][j][q] = 0.f;

    {
        uint32_t h0, h1, h2, h3, l0, l1, l2, l3;
        splitH4(rA0, h0, h1, l0, l1); splitH4(rA1, h2, h3, l2, l3);
        *(uint4*)&Ah[0][pr * LD + pc] = make_uint4(h0, h1, h2, h3);
        *(uint4*)&Al[0][pr * LD + pc] = make_uint4(l0, l1, l2, l3);
        Bh[0][(4 * hq + 0) * LD + sp] = __byte_perm(rha.x, rhb.x, 0x5410);
        Bh[0][(4 * hq + 1) * LD + sp] = __byte_perm(rha.x, rhb.x, 0x7632);
        Bh[0][(4 * hq + 2) * LD + sp] = __byte_perm(rha.y, rhb.y, 0x5410);
        Bh[0][(4 * hq + 3) * LD + sp] = __byte_perm(rha.y, rhb.y, 0x7632);
        Bl[0][(4 * hq + 0) * LD + sp] = __byte_perm(rla.x, rlb.x, 0x5410);
        Bl[0][(4 * hq + 1) * LD + sp] = __byte_perm(rla.x, rlb.x, 0x7632);
        Bl[0][(4 * hq + 2) * LD + sp] = __byte_perm(rla.y, rlb.y, 0x5410);
        Bl[0][(4 * hq + 3) * LD + sp] = __byte_perm(rla.y, rlb.y, 0x7632);
    }
#pragma unroll 1
    for (int s = 0; s < NS; s++) {
        const int cur = s & 1, nxt = cur ^ 1;
        const uint32_t bo = (uint32_t)(cur * BUF_BYTES);
        __syncthreads();
        if (s + 1 < NS) {
            rA0 = *(const float4*)(ap + (s + 1) * 16);
            rA1 = *(const float4*)(ap + (s + 1) * 16 + 4);
            const uint32_t* vh2 = vh + (size_t)(s + 1) * 16 * 64;
            const uint32_t* vl2 = vl + (size_t)(s + 1) * 16 * 64;
            rha = *(const uint2*)vh2; rhb = *(const uint2*)(vh2 + 64);
            rla = *(const uint2*)vl2; rlb = *(const uint2*)(vl2 + 64);
        }
        mma_slab3(bAh + bo, bAl + bo, bBh + bo, bBl + bo, aoff, boff, acc);
        if (s + 1 < NS) {
            uint32_t h0, h1, h2, h3, l0, l1, l2, l3;
            splitH4(rA0, h0, h1, l0, l1); splitH4(rA1, h2, h3, l2, l3);
            *(uint4*)&Ah[nxt][pr * LD + pc] = make_uint4(h0, h1, h2, h3);
            *(uint4*)&Al[nxt][pr * LD + pc] = make_uint4(l0, l1, l2, l3);
            Bh[nxt][(4 * hq + 0) * LD + sp] = __byte_perm(rha.x, rhb.x, 0x5410);
            Bh[nxt][(4 * hq + 1) * LD + sp] = __byte_perm(rha.x, rhb.x, 0x7632);
            Bh[nxt][(4 * hq + 2) * LD + sp] = __byte_perm(rha.y, rhb.y, 0x5410);
            Bh[nxt][(4 * hq + 3) * LD + sp] = __byte_perm(rha.y, rhb.y, 0x7632);
            Bl[nxt][(4 * hq + 0) * LD + sp] = __byte_perm(rla.x, rlb.x, 0x5410);
            Bl[nxt][(4 * hq + 1) * LD + sp] = __byte_perm(rla.x, rlb.x, 0x7632);
            Bl[nxt][(4 * hq + 2) * LD + sp] = __byte_perm(rla.y, rlb.y, 0x5410);
            Bl[nxt][(4 * hq + 3) * LD + sp] = __byte_perm(rla.y, rlb.y, 0x7632);
        }
    }
#pragma unroll
    for (int i = 0; i < 4; i++)
#pragma unroll
        for (int j = 0; j < 4; j++) {
            int row = t0 + wm + 16 * i + g;
            int col = wn + 8 * j + 2 * t;
            float* p0 = res + (size_t)(b * T + row) * H + col;
            float* p1 = res + (size_t)(b * T + row + 8) * H + col;
            atomicAdd(p0,     acc[i][j][0]);
            atomicAdd(p0 + 1, acc[i][j][1]);
            atomicAdd(p1,     acc[i][j][2]);
            atomicAdd(p1 + 1, acc[i][j][3]);
        }
}

// ---------------------------------------------------------------------------
extern "C" void kernel_launch(void* const* d_in, const int* in_sizes, int n_in,
                              void* d_out, int out_size)
{
    const float* x  = (const float*)d_in[0];
    const float* Wq = (const float*)d_in[1];
    const float* Wk = (const float*)d_in[2];
    const float* Wv = (const float*)d_in[3];
    float* res  = (float*)d_out;
    float* attn = res + (size_t)B * T * H;

    cudaMemsetAsync(res, 0, (size_t)NR * H * sizeof(float));
    proj_qk_kernel<<<dim3(NR / 128, 2), 256>>>(x, Wq, Wk);
    proj_v_kernel<<<NR / 128, 256>>>(x, Wv);
    score_mma_kernel<<<dim3(136, 8), 256>>>(attn);
    softmax_kernel<<<NR, 256>>>(attn);
    pv_mma_kernel<<<dim3(136, 8), 256>>>(attn, res);
}

// round 15
// speedup vs baseline: 4.3034x; 1.0738x over previous
#include <cuda_runtime.h>
#include <cuda_fp16.h>
#include <math.h>
#include <stddef.h>
#include <stdint.h>

// NOTE: harness builds via compute_103 virtual arch -> tcgen05/TMEM PTX is
// rejected by ptxas. mma.sync (HMMA) + ldmatrix is the available tensor path.

namespace {
constexpr int B = 8, T = 2048, C = 1024, H = 128;
constexpr int NR = B * T;   // 16384 rows
constexpr int LD = 12;      // smem row stride in u32 (48B rows: LDSM conflict-free)
constexpr int BUF_BYTES = 128 * LD * 4;   // one buffer of one operand array
}

// scratch (device globals: allocation-free per harness rules)
__device__ float    g_sq[NR];
__device__ float    g_sk[NR];
// packed half2 (k-pair) operands. q/k: hi only (gap-protected logits).
__device__ uint32_t g_qh[NR * 64];
__device__ uint32_t g_kh[NR * 64];
__device__ uint32_t g_vh[NR * 64], g_vl[NR * 64];   // v: hi/lo (res-critical)

// ---------------------------------------------------------------------------
__device__ __forceinline__ uint32_t smem_u32(const void* p) {
    uint32_t a;
    asm("{ .reg .u64 t; cvta.to.shared.u64 t, %1; cvt.u32.u64 %0, t; }" : "=r"(a) : "l"(p));
    return a;
}

__device__ __forceinline__ void splitH4(float4 v, uint32_t& h0, uint32_t& h1,
                                        uint32_t& l0, uint32_t& l1) {
    __half2 a = __floats2half2_rn(v.x, v.y);
    __half2 b = __floats2half2_rn(v.z, v.w);
    float2 af = __half22float2(a), bf = __half22float2(b);
    __half2 al = __floats2half2_rn(v.x - af.x, v.y - af.y);
    __half2 bl = __floats2half2_rn(v.z - bf.x, v.w - bf.y);
    h0 = *(uint32_t*)&a;  h1 = *(uint32_t*)&b;
    l0 = *(uint32_t*)&al; l1 = *(uint32_t*)&bl;
}

__device__ __forceinline__ void cvtH4(float4 v, uint32_t& h0, uint32_t& h1) {
    __half2 a = __floats2half2_rn(v.x, v.y);
    __half2 b = __floats2half2_rn(v.z, v.w);
    h0 = *(uint32_t*)&a; h1 = *(uint32_t*)&b;
}

__device__ __forceinline__ void splitH2(float a, float b, uint32_t& h, uint32_t& l) {
    __half2 hh = __floats2half2_rn(a, b);
    float2 hf = __half22float2(hh);
    __half2 ll = __floats2half2_rn(a - hf.x, b - hf.y);
    h = *(uint32_t*)&hh; l = *(uint32_t*)&ll;
}

#define MMAH(c, a, b) \
    asm volatile("mma.sync.aligned.m16n8k16.row.col.f32.f16.f16.f32 " \
        "{%0,%1,%2,%3},{%4,%5,%6,%7},{%8,%9},{%0,%1,%2,%3};" \
        : "+f"((c)[0]), "+f"((c)[1]), "+f"((c)[2]), "+f"((c)[3]) \
        : "r"((a)[0]), "r"((a)[1]), "r"((a)[2]), "r"((a)[3]), \
          "r"((b)[0]), "r"((b)[1]))

__device__ __forceinline__ void ldsm_x4(uint32_t addr, uint32_t* r) {
    asm volatile("ldmatrix.sync.aligned.m8n8.x4.shared.b16 {%0,%1,%2,%3}, [%4];"
        : "=r"(r[0]), "=r"(r[1]), "=r"(r[2]), "=r"(r[3]) : "r"(addr));
}

// 3-pass slab: hh + lh + hl (res-critical paths)
__device__ __forceinline__ void mma_slab3(
    uint32_t aAh, uint32_t aAl, uint32_t aBh, uint32_t aBl,
    const uint32_t* aoff, const uint32_t* boff, float acc[4][4][4])
{
    uint32_t ah[4][4], al[4][4], bh[4][2], bl[4][2];
#pragma unroll
    for (int i = 0; i < 4; i++) {
        ldsm_x4(aAh + aoff[i], ah[i]);
        ldsm_x4(aAl + aoff[i], al[i]);
    }
#pragma unroll
    for (int p = 0; p < 2; p++) {
        uint32_t rb[4];
        ldsm_x4(aBh + boff[p], rb);
        bh[2 * p][0] = rb[0]; bh[2 * p + 1][0] = rb[1];
        bh[2 * p][1] = rb[2]; bh[2 * p + 1][1] = rb[3];
        ldsm_x4(aBl + boff[p], rb);
        bl[2 * p][0] = rb[0]; bl[2 * p + 1][0] = rb[1];
        bl[2 * p][1] = rb[2]; bl[2 * p + 1][1] = rb[3];
    }
#pragma unroll
    for (int i = 0; i < 4; i++)
#pragma unroll
        for (int j = 0; j < 4; j++) {
            MMAH(acc[i][j], ah[i], bh[j]);
            MMAH(acc[i][j], al[i], bh[j]);
            MMAH(acc[i][j], ah[i], bl[j]);
        }
}

// 1-pass slab: hh only (gap-protected logit paths)
__device__ __forceinline__ void mma_slab1(
    uint32_t aAh, uint32_t aBh,
    const uint32_t* aoff, const uint32_t* boff, float acc[4][4][4])
{
    uint32_t ah[4][4], bh[4][2];
#pragma unroll
    for (int i = 0; i < 4; i++)
        ldsm_x4(aAh + aoff[i], ah[i]);
#pragma unroll
    for (int p = 0; p < 2; p++) {
        uint32_t rb[4];
        ldsm_x4(aBh + boff[p], rb);
        bh[2 * p][0] = rb[0]; bh[2 * p + 1][0] = rb[1];
        bh[2 * p][1] = rb[2]; bh[2 * p + 1][1] = rb[3];
    }
#pragma unroll
    for (int i = 0; i < 4; i++)
#pragma unroll
        for (int j = 0; j < 4; j++)
            MMAH(acc[i][j], ah[i], bh[j]);
}

// per-warp ldmatrix address offsets (bytes) within one operand buffer
#define MAKE_LDSM_OFFSETS()                                              \
    uint32_t aoff[4], boff[2];                                           \
    {                                                                    \
        const int l15 = lane & 15, lhi = lane >> 4;                      \
        _Pragma("unroll")                                                \
        for (int i = 0; i < 4; i++)                                      \
            aoff[i] = (uint32_t)((wm + 16 * i + l15) * 48 + lhi * 16);   \
        _Pragma("unroll")                                                \
        for (int p = 0; p < 2; p++)                                      \
            boff[p] = (uint32_t)((wn + 16 * p + l15) * 48 + lhi * 16);   \
    }

// ---------------------------------------------------------------------------
// proj q/k: 1-pass (xh * Wh). Writes hi-only halves + row sums.
__global__ __launch_bounds__(256) void proj_qk_kernel(
    const float* __restrict__ x, const float* __restrict__ Wq,
    const float* __restrict__ Wk)
{
    __shared__ uint32_t Ah[2][128 * LD];
    __shared__ uint32_t Bh[2][128 * LD];
    __shared__ float ssum[128];
    const int isQ = (blockIdx.y == 0);
    const float* W = isQ ? Wq : Wk;
    uint32_t* outh = isQ ? g_qh : g_kh;
    const int m0 = blockIdx.x * 128;
    const int tid = threadIdx.x;
    const int w = tid >> 5, lane = tid & 31;
    const int wm = (w & 1) * 64, wn = (w >> 1) * 32;
    const int g = lane >> 2, t = lane & 3;
    const int pr = tid >> 1, pc = (tid & 1) * 4;

    MAKE_LDSM_OFFSETS();
    const uint32_t bAh = smem_u32(&Ah[0][0]);
    const uint32_t bBh = smem_u32(&Bh[0][0]);

    if (tid < 128) ssum[tid] = 0.f;

    const float* ap = x + (size_t)(m0 + pr) * C + pc * 2;
    const float* bp = W + (size_t)pr * C + pc * 2;

    float4 rA0 = *(const float4*)ap, rA1 = *(const float4*)(ap + 4);
    float4 rB0 = *(const float4*)bp, rB1 = *(const float4*)(bp + 4);

    float acc[4][4][4];
#pragma unroll
    for (int i = 0; i < 4; i++)
#pragma unroll
        for (int j = 0; j < 4; j++)
#pragma unroll
            for (int q = 0; q < 4; q++) acc[i][j][q] = 0.f;

    const int NS = C / 16;
    {
        uint32_t h0, h1, h2, h3;
        cvtH4(rA0, h0, h1); cvtH4(rA1, h2, h3);
        *(uint4*)&Ah[0][pr * LD + pc] = make_uint4(h0, h1, h2, h3);
        cvtH4(rB0, h0, h1); cvtH4(rB1, h2, h3);
        *(uint4*)&Bh[0][pr * LD + pc] = make_uint4(h0, h1, h2, h3);
    }
#pragma unroll 1
    for (int s = 0; s < NS; s++) {
        const int cur = s & 1, nxt = cur ^ 1;
        const uint32_t bo = (uint32_t)(cur * BUF_BYTES);
        __syncthreads();
        if (s + 1 < NS) {
            rA0 = *(const float4*)(ap + (s + 1) * 16);
            rA1 = *(const float4*)(ap + (s + 1) * 16 + 4);
            rB0 = *(const float4*)(bp + (s + 1) * 16);
            rB1 = *(const float4*)(bp + (s + 1) * 16 + 4);
        }
        mma_slab1(bAh + bo, bBh + bo, aoff, boff, acc);
        if (s + 1 < NS) {
            uint32_t h0, h1, h2, h3;
            cvtH4(rA0, h0, h1); cvtH4(rA1, h2, h3);
            *(uint4*)&Ah[nxt][pr * LD + pc] = make_uint4(h0, h1, h2, h3);
            cvtH4(rB0, h0, h1); cvtH4(rB1, h2, h3);
            *(uint4*)&Bh[nxt][pr * LD + pc] = make_uint4(h0, h1, h2, h3);
        }
    }
    // epilogue: hi-only write + row sums
#pragma unroll
    for (int i = 0; i < 4; i++) {
        const int r0 = wm + 16 * i + g;
        float s0 = 0.f, s1 = 0.f;
#pragma unroll
        for (int j = 0; j < 4; j++) {
            const int p = (wn >> 1) + 4 * j + t;
            __half2 h2a = __floats2half2_rn(acc[i][j][0], acc[i][j][1]);
            outh[(size_t)(m0 + r0) * 64 + p] = *(uint32_t*)&h2a;
            __half2 h2b = __floats2half2_rn(acc[i][j][2], acc[i][j][3]);
            outh[(size_t)(m0 + r0 + 8) * 64 + p] = *(uint32_t*)&h2b;
            s0 += acc[i][j][0] + acc[i][j][1];
            s1 += acc[i][j][2] + acc[i][j][3];
        }
        atomicAdd(&ssum[r0], s0);
        atomicAdd(&ssum[r0 + 8], s1);
    }
    __syncthreads();
    if (tid < 128) {
        float* gs = isQ ? g_sq : g_sk;
        gs[m0 + tid] = ssum[tid];
    }
}

// ---------------------------------------------------------------------------
// proj v: 3-pass (res accuracy depends on v). Writes pre-split halves.
__global__ __launch_bounds__(256) void proj_v_kernel(
    const float* __restrict__ x, const float* __restrict__ Wv)
{
    __shared__ uint32_t Ah[2][128 * LD], Al[2][128 * LD];
    __shared__ uint32_t Bh[2][128 * LD], Bl[2][128 * LD];
    const int m0 = blockIdx.x * 128;
    const int tid = threadIdx.x;
    const int w = tid >> 5, lane = tid & 31;
    const int wm = (w & 1) * 64, wn = (w >> 1) * 32;
    const int g = lane >> 2, t = lane & 3;
    const int pr = tid >> 1, pc = (tid & 1) * 4;

    MAKE_LDSM_OFFSETS();
    const uint32_t bAh = smem_u32(&Ah[0][0]), bAl = smem_u32(&Al[0][0]);
    const uint32_t bBh = smem_u32(&Bh[0][0]), bBl = smem_u32(&Bl[0][0]);

    const float* ap = x + (size_t)(m0 + pr) * C + pc * 2;
    const float* bp = Wv + (size_t)pr * C + pc * 2;

    float4 rA0 = *(const float4*)ap, rA1 = *(const float4*)(ap + 4);
    float4 rB0 = *(const float4*)bp, rB1 = *(const float4*)(bp + 4);

    float acc[4][4][4];
#pragma unroll
    for (int i = 0; i < 4; i++)
#pragma unroll
        for (int j = 0; j < 4; j++)
#pragma unroll
            for (int q = 0; q < 4; q++) acc[i][j][q] = 0.f;

    const int NS = C / 16;
    {
        uint32_t h0, h1, h2, h3, l0, l1, l2, l3;
        splitH4(rA0, h0, h1, l0, l1); splitH4(rA1, h2, h3, l2, l3);
        *(uint4*)&Ah[0][pr * LD + pc] = make_uint4(h0, h1, h2, h3);
        *(uint4*)&Al[0][pr * LD + pc] = make_uint4(l0, l1, l2, l3);
        splitH4(rB0, h0, h1, l0, l1); splitH4(rB1, h2, h3, l2, l3);
        *(uint4*)&Bh[0][pr * LD + pc] = make_uint4(h0, h1, h2, h3);
        *(uint4*)&Bl[0][pr * LD + pc] = make_uint4(l0, l1, l2, l3);
    }
#pragma unroll 1
    for (int s = 0; s < NS; s++) {
        const int cur = s & 1, nxt = cur ^ 1;
        const uint32_t bo = (uint32_t)(cur * BUF_BYTES);
        __syncthreads();
        if (s + 1 < NS) {
            rA0 = *(const float4*)(ap + (s + 1) * 16);
            rA1 = *(const float4*)(ap + (s + 1) * 16 + 4);
            rB0 = *(const float4*)(bp + (s + 1) * 16);
            rB1 = *(const float4*)(bp + (s + 1) * 16 + 4);
        }
        mma_slab3(bAh + bo, bAl + bo, bBh + bo, bBl + bo, aoff, boff, acc);
        if (s + 1 < NS) {
            uint32_t h0, h1, h2, h3, l0, l1, l2, l3;
            splitH4(rA0, h0, h1, l0, l1); splitH4(rA1, h2, h3, l2, l3);
            *(uint4*)&Ah[nxt][pr * LD + pc] = make_uint4(h0, h1, h2, h3);
            *(uint4*)&Al[nxt][pr * LD + pc] = make_uint4(l0, l1, l2, l3);
            splitH4(rB0, h0, h1, l0, l1); splitH4(rB1, h2, h3, l2, l3);
            *(uint4*)&Bh[nxt][pr * LD + pc] = make_uint4(h0, h1, h2, h3);
            *(uint4*)&Bl[nxt][pr * LD + pc] = make_uint4(l0, l1, l2, l3);
        }
    }
#pragma unroll
    for (int i = 0; i < 4; i++) {
        const int r0 = wm + 16 * i + g;
#pragma unroll
        for (int j = 0; j < 4; j++) {
            const int p = (wn >> 1) + 4 * j + t;
            uint32_t h, l;
            splitH2(acc[i][j][0], acc[i][j][1], h, l);
            g_vh[(size_t)(m0 + r0) * 64 + p] = h;
            g_vl[(size_t)(m0 + r0) * 64 + p] = l;
            splitH2(acc[i][j][2], acc[i][j][3], h, l);
            g_vh[(size_t)(m0 + r0 + 8) * 64 + p] = h;
            g_vl[(size_t)(m0 + r0 + 8) * 64 + p] = l;
        }
    }
}

// ---------------------------------------------------------------------------
// score: raw S = qh.kh over lower-band 128x128 tiles (1-pass)
__global__ __launch_bounds__(256) void score_mma_kernel(float* __restrict__ attn)
{
    __shared__ uint32_t Ah[2][128 * LD];
    __shared__ uint32_t Bh[2][128 * LD];
    const int b = blockIdx.y;
    const int idx = blockIdx.x;
    int ti = (int)((sqrtf(8.f * (float)idx + 1.f) - 1.f) * 0.5f);
    if (ti > 15) ti = 15;
    while ((ti + 1) * (ti + 2) / 2 <= idx) ti++;
    while (ti * (ti + 1) / 2 > idx) ti--;
    const int tj = idx - ti * (ti + 1) / 2;
    const int t0 = ti * 128, s0 = tj * 128;

    const int tid = threadIdx.x;
    const int w = tid >> 5, lane = tid & 31;
    const int wm = (w & 1) * 64, wn = (w >> 1) * 32;
    const int g = lane >> 2, t = lane & 3;
    const int pr = tid >> 1, pc = (tid & 1) * 4;

    MAKE_LDSM_OFFSETS();
    const uint32_t bAh = smem_u32(&Ah[0][0]);
    const uint32_t bBh = smem_u32(&Bh[0][0]);

    const uint32_t* qh = g_qh + (size_t)(b * T + t0 + pr) * 64 + pc;
    const uint32_t* kh = g_kh + (size_t)(b * T + s0 + pr) * 64 + pc;

    uint4 rAh = *(const uint4*)qh;
    uint4 rBh = *(const uint4*)kh;

    float acc[4][4][4];
#pragma unroll
    for (int i = 0; i < 4; i++)
#pragma unroll
        for (int j = 0; j < 4; j++)
#pragma unroll
            for (int q = 0; q < 4; q++) acc[i][j][q] = 0.f;

    const int NS = H / 16;  // 8
    *(uint4*)&Ah[0][pr * LD + pc] = rAh;
    *(uint4*)&Bh[0][pr * LD + pc] = rBh;
#pragma unroll 1
    for (int s = 0; s < NS; s++) {
        const int cur = s & 1, nxt = cur ^ 1;
        const uint32_t bo = (uint32_t)(cur * BUF_BYTES);
        __syncthreads();
        if (s + 1 < NS) {
            rAh = *(const uint4*)(qh + (s + 1) * 8);
            rBh = *(const uint4*)(kh + (s + 1) * 8);
        }
        mma_slab1(bAh + bo, bBh + bo, aoff, boff, acc);
        if (s + 1 < NS) {
            *(uint4*)&Ah[nxt][pr * LD + pc] = rAh;
            *(uint4*)&Bh[nxt][pr * LD + pc] = rBh;
        }
    }
#pragma unroll
    for (int i = 0; i < 4; i++)
#pragma unroll
        for (int j = 0; j < 4; j++) {
            int row = t0 + wm + 16 * i + g;
            int col = s0 + wn + 8 * j + 2 * t;
            *(float2*)&attn[(size_t)(b * T + row) * T + col]     = make_float2(acc[i][j][0], acc[i][j][1]);
            *(float2*)&attn[(size_t)(b * T + row + 8) * T + col] = make_float2(acc[i][j][2], acc[i][j][3]);
        }
}

// ---------------------------------------------------------------------------
// softmax: in-place per row; band-only reads, pos terms folded as 3 FMA.
__global__ __launch_bounds__(256) void softmax_kernel(float* __restrict__ attn)
{
    __shared__ float red[8];
    const int r = blockIdx.x;
    const int b = r >> 11;
    const int t = r & (T - 1);
    float* row = attn + (size_t)r * T;
    const float* skrow = g_sk + (size_t)b * T;
    const int tid = threadIdx.x;
    const int c0 = tid * 8;
    const bool act = (c0 <= t);

    // lg = qk/32 + s*(sq+128t)/32 + (t/32)*sk
    const float aco = (g_sq[r] + 128.f * (float)t) * 0.03125f;
    const float tk  = (float)t * 0.03125f;

    float qk[8] = {0, 0, 0, 0, 0, 0, 0, 0};
    float sk[8] = {0, 0, 0, 0, 0, 0, 0, 0};
    if (act) {
        float4 v0 = *(const float4*)(row + c0);
        float4 v1 = *(const float4*)(row + c0 + 4);
        float4 s0 = *(const float4*)(skrow + c0);
        float4 s1 = *(const float4*)(skrow + c0 + 4);
        qk[0] = v0.x; qk[1] = v0.y; qk[2] = v0.z; qk[3] = v0.w;
        qk[4] = v1.x; qk[5] = v1.y; qk[6] = v1.z; qk[7] = v1.w;
        sk[0] = s0.x; sk[1] = s0.y; sk[2] = s0.z; sk[3] = s0.w;
        sk[4] = s1.x; sk[5] = s1.y; sk[6] = s1.z; sk[7] = s1.w;
    }

    float lg[8];
    float mx = -INFINITY;
#pragma unroll
    for (int j = 0; j < 8; j++) {
        int s = c0 + j;
        float v = fmaf((float)s, aco, fmaf(tk, sk[j], qk[j] * 0.03125f));
        lg[j] = (s <= t) ? v : -INFINITY;
        mx = fmaxf(mx, lg[j]);
    }
#pragma unroll
    for (int o = 16; o > 0; o >>= 1)
        mx = fmaxf(mx, __shfl_xor_sync(0xffffffffu, mx, o));
    if ((tid & 31) == 0) red[tid >> 5] = mx;
    __syncthreads();
    float m = red[0];
#pragma unroll
    for (int i = 1; i < 8; i++) m = fmaxf(m, red[i]);
    __syncthreads();

    float ev[8];
    float sum = 0.f;
#pragma unroll
    for (int j = 0; j < 8; j++) {
        ev[j] = __expf(lg[j] - m);
        sum += ev[j];
    }
#pragma unroll
    for (int o = 16; o > 0; o >>= 1)
        sum += __shfl_xor_sync(0xffffffffu, sum, o);
    if ((tid & 31) == 0) red[tid >> 5] = sum;
    __syncthreads();
    float tot = red[0];
#pragma unroll
    for (int i = 1; i < 8; i++) tot += red[i];
    const float rinv = 1.f / tot;

    *(float4*)(row + c0)     = make_float4(ev[0] * rinv, ev[1] * rinv, ev[2] * rinv, ev[3] * rinv);
    *(float4*)(row + c0 + 4) = make_float4(ev[4] * rinv, ev[5] * rinv, ev[6] * rinv, ev[7] * rinv);
}

// ---------------------------------------------------------------------------
// pv: res += attn_chunk @ v_chunk (fp16 hi/lo 3-pass, uniform 128-wide split-K
// chunks, atomicAdd into zeroed res, double-buffered, ldmatrix).
__global__ __launch_bounds__(256) void pv_mma_kernel(
    const float* __restrict__ attn, float* __restrict__ res)
{
    __shared__ uint32_t Ah[2][128 * LD], Al[2][128 * LD];
    __shared__ uint32_t Bh[2][128 * LD], Bl[2][128 * LD];
    const int b = blockIdx.y;
    const int idx = blockIdx.x;
    int kt = (int)((sqrtf(8.f * (float)idx + 1.f) - 1.f) * 0.5f);
    if (kt > 15) kt = 15;
    while ((kt + 1) * (kt + 2) / 2 <= idx) kt++;
    while (kt * (kt + 1) / 2 > idx) kt--;
    const int chunk = idx - kt * (kt + 1) / 2;
    const int t0 = kt * 128;
    const int sbeg = chunk * 128;
    const int NS = 8;

    const int tid = threadIdx.x;
    const int w = tid >> 5, lane = tid & 31;
    const int wm = (w & 1) * 64, wn = (w >> 1) * 32;
    const int g = lane >> 2, t = lane & 3;
    const int pr = tid >> 1, pc = (tid & 1) * 4;   // A stager
    const int sp = tid & 7, hq = tid >> 3;         // B stager: s-pair, h-quad

    MAKE_LDSM_OFFSETS();
    const uint32_t bAh = smem_u32(&Ah[0][0]), bAl = smem_u32(&Al[0][0]);
    const uint32_t bBh = smem_u32(&Bh[0][0]), bBl = smem_u32(&Bl[0][0]);

    const float* ap = attn + (size_t)(b * T + t0 + pr) * T + sbeg + pc * 2;
    const uint32_t* vh = g_vh + (size_t)(b * T + sbeg + 2 * sp) * 64 + 2 * hq;
    const uint32_t* vl = g_vl + (size_t)(b * T + sbeg + 2 * sp) * 64 + 2 * hq;

    float4 rA0 = *(const float4*)ap, rA1 = *(const float4*)(ap + 4);
    uint2 rha = *(const uint2*)vh,   rhb = *(const uint2*)(vh + 64);
    uint2 rla = *(const uint2*)vl,   rlb = *(const uint2*)(vl + 64);

    float acc[4][4][4];
#pragma unroll
    for (int i = 0; i < 4; i++)
#pragma unroll
        for (int j = 0; j < 4; j++)
#pragma unroll
            for (int q = 0; q < 4; q++) acc[i][j][q] = 0.f;

    {
        uint32_t h0, h1, h2, h3, l0, l1, l2, l3;
        splitH4(rA0, h0, h1, l0, l1); splitH4(rA1, h2, h3, l2, l3);
        *(uint4*)&Ah[0][pr * LD + pc] = make_uint4(h0, h1, h2, h3);
        *(uint4*)&Al[0][pr * LD + pc] = make_uint4(l0, l1, l2, l3);
        Bh[0][(4 * hq + 0) * LD + sp] = __byte_perm(rha.x, rhb.x, 0x5410);
        Bh[0][(4 * hq + 1) * LD + sp] = __byte_perm(rha.x, rhb.x, 0x7632);
        Bh[0][(4 * hq + 2) * LD + sp] = __byte_perm(rha.y, rhb.y, 0x5410);
        Bh[0][(4 * hq + 3) * LD + sp] = __byte_perm(rha.y, rhb.y, 0x7632);
        Bl[0][(4 * hq + 0) * LD + sp] = __byte_perm(rla.x, rlb.x, 0x5410);
        Bl[0][(4 * hq + 1) * LD + sp] = __byte_perm(rla.x, rlb.x, 0x7632);
        Bl[0][(4 * hq + 2) * LD + sp] = __byte_perm(rla.y, rlb.y, 0x5410);
        Bl[0][(4 * hq + 3) * LD + sp] = __byte_perm(rla.y, rlb.y, 0x7632);
    }
#pragma unroll 1
    for (int s = 0; s < NS; s++) {
        const int cur = s & 1, nxt = cur ^ 1;
        const uint32_t bo = (uint32_t)(cur * BUF_BYTES);
        __syncthreads();
        if (s + 1 < NS) {
            rA0 = *(const float4*)(ap + (s + 1) * 16);
            rA1 = *(const float4*)(ap + (s + 1) * 16 + 4);
            const uint32_t* vh2 = vh + (size_t)(s + 1) * 16 * 64;
            const uint32_t* vl2 = vl + (size_t)(s + 1) * 16 * 64;
            rha = *(const uint2*)vh2; rhb = *(const uint2*)(vh2 + 64);
            rla = *(const uint2*)vl2; rlb = *(const uint2*)(vl2 + 64);
        }
        mma_slab3(bAh + bo, bAl + bo, bBh + bo, bBl + bo, aoff, boff, acc);
        if (s + 1 < NS) {
            uint32_t h0, h1, h2, h3, l0, l1, l2, l3;
            splitH4(rA0, h0, h1, l0, l1); splitH4(rA1, h2, h3, l2, l3);
            *(uint4*)&Ah[nxt][pr * LD + pc] = make_uint4(h0, h1, h2, h3);
            *(uint4*)&Al[nxt][pr * LD + pc] = make_uint4(l0, l1, l2, l3);
            Bh[nxt][(4 * hq + 0) * LD + sp] = __byte_perm(rha.x, rhb.x, 0x5410);
            Bh[nxt][(4 * hq + 1) * LD + sp] = __byte_perm(rha.x, rhb.x, 0x7632);
            Bh[nxt][(4 * hq + 2) * LD + sp] = __byte_perm(rha.y, rhb.y, 0x5410);
            Bh[nxt][(4 * hq + 3) * LD + sp] = __byte_perm(rha.y, rhb.y, 0x7632);
            Bl[nxt][(4 * hq + 0) * LD + sp] = __byte_perm(rla.x, rlb.x, 0x5410);
            Bl[nxt][(4 * hq + 1) * LD + sp] = __byte_perm(rla.x, rlb.x, 0x7632);
            Bl[nxt][(4 * hq + 2) * LD + sp] = __byte_perm(rla.y, rlb.y, 0x5410);
            Bl[nxt][(4 * hq + 3) * LD + sp] = __byte_perm(rla.y, rlb.y, 0x7632);
        }
    }
#pragma unroll
    for (int i = 0; i < 4; i++)
#pragma unroll
        for (int j = 0; j < 4; j++) {
            int row = t0 + wm + 16 * i + g;
            int col = wn + 8 * j + 2 * t;
            float* p0 = res + (size_t)(b * T + row) * H + col;
            float* p1 = res + (size_t)(b * T + row + 8) * H + col;
            atomicAdd(p0,     acc[i][j][0]);
            atomicAdd(p0 + 1, acc[i][j][1]);
            atomicAdd(p1,     acc[i][j][2]);
            atomicAdd(p1 + 1, acc[i][j][3]);
        }
}

// ---------------------------------------------------------------------------
extern "C" void kernel_launch(void* const* d_in, const int* in_sizes, int n_in,
                              void* d_out, int out_size)
{
    const float* x  = (const float*)d_in[0];
    const float* Wq = (const float*)d_in[1];
    const float* Wk = (const float*)d_in[2];
    const float* Wv = (const float*)d_in[3];
    float* res  = (float*)d_out;
    float* attn = res + (size_t)B * T * H;

    cudaMemsetAsync(res, 0, (size_t)NR * H * sizeof(float));
    proj_qk_kernel<<<dim3(NR / 128, 2), 256>>>(x, Wq, Wk);
    proj_v_kernel<<<NR / 128, 256>>>(x, Wv);
    score_mma_kernel<<<dim3(136, 8), 256>>>(attn);
    softmax_kernel<<<NR, 256>>>(attn);
    pv_mma_kernel<<<dim3(136, 8), 256>>>(attn, res);
}

// round 16
// speedup vs baseline: 4.3968x; 1.0217x over previous
#include <cuda_runtime.h>
#include <cuda_fp16.h>
#include <math.h>
#include <stddef.h>
#include <stdint.h>

// NOTE: harness builds via compute_103 virtual arch -> tcgen05/TMEM PTX is
// rejected by ptxas. mma.sync (HMMA) + ldmatrix is the available tensor path.

namespace {
constexpr int B = 8, T = 2048, C = 1024, H = 128;
constexpr int NR = B * T;   // 16384 rows
constexpr int LD = 12;      // smem row stride in u32 (48B rows: LDSM conflict-free)
constexpr int BUF_BYTES = 128 * LD * 4;   // one buffer of one operand array
}

// scratch (device globals: allocation-free per harness rules)
__device__ float    g_sq[NR];
__device__ float    g_sk[NR];
// packed half2 (k-pair) operands. q/k: hi only (gap-protected logits).
__device__ uint32_t g_qh[NR * 64];
__device__ uint32_t g_kh[NR * 64];
__device__ uint32_t g_vh[NR * 64], g_vl[NR * 64];   // v: hi/lo (res-critical)

// ---------------------------------------------------------------------------
__device__ __forceinline__ uint32_t smem_u32(const void* p) {
    uint32_t a;
    asm("{ .reg .u64 t; cvta.to.shared.u64 t, %1; cvt.u32.u64 %0, t; }" : "=r"(a) : "l"(p));
    return a;
}

__device__ __forceinline__ void splitH4(float4 v, uint32_t& h0, uint32_t& h1,
                                        uint32_t& l0, uint32_t& l1) {
    __half2 a = __floats2half2_rn(v.x, v.y);
    __half2 b = __floats2half2_rn(v.z, v.w);
    float2 af = __half22float2(a), bf = __half22float2(b);
    __half2 al = __floats2half2_rn(v.x - af.x, v.y - af.y);
    __half2 bl = __floats2half2_rn(v.z - bf.x, v.w - bf.y);
    h0 = *(uint32_t*)&a;  h1 = *(uint32_t*)&b;
    l0 = *(uint32_t*)&al; l1 = *(uint32_t*)&bl;
}

__device__ __forceinline__ void cvtH4(float4 v, uint32_t& h0, uint32_t& h1) {
    __half2 a = __floats2half2_rn(v.x, v.y);
    __half2 b = __floats2half2_rn(v.z, v.w);
    h0 = *(uint32_t*)&a; h1 = *(uint32_t*)&b;
}

__device__ __forceinline__ void splitH2(float a, float b, uint32_t& h, uint32_t& l) {
    __half2 hh = __floats2half2_rn(a, b);
    float2 hf = __half22float2(hh);
    __half2 ll = __floats2half2_rn(a - hf.x, b - hf.y);
    h = *(uint32_t*)&hh; l = *(uint32_t*)&ll;
}

#define MMAH(c, a, b) \
    asm volatile("mma.sync.aligned.m16n8k16.row.col.f32.f16.f16.f32 " \
        "{%0,%1,%2,%3},{%4,%5,%6,%7},{%8,%9},{%0,%1,%2,%3};" \
        : "+f"((c)[0]), "+f"((c)[1]), "+f"((c)[2]), "+f"((c)[3]) \
        : "r"((a)[0]), "r"((a)[1]), "r"((a)[2]), "r"((a)[3]), \
          "r"((b)[0]), "r"((b)[1]))

__device__ __forceinline__ void ldsm_x4(uint32_t addr, uint32_t* r) {
    asm volatile("ldmatrix.sync.aligned.m8n8.x4.shared.b16 {%0,%1,%2,%3}, [%4];"
        : "=r"(r[0]), "=r"(r[1]), "=r"(r[2]), "=r"(r[3]) : "r"(addr));
}

// 3-pass slab: hh + lh + hl (res-critical: proj_v)
__device__ __forceinline__ void mma_slab3(
    uint32_t aAh, uint32_t aAl, uint32_t aBh, uint32_t aBl,
    const uint32_t* aoff, const uint32_t* boff, float acc[4][4][4])
{
    uint32_t ah[4][4], al[4][4], bh[4][2], bl[4][2];
#pragma unroll
    for (int i = 0; i < 4; i++) {
        ldsm_x4(aAh + aoff[i], ah[i]);
        ldsm_x4(aAl + aoff[i], al[i]);
    }
#pragma unroll
    for (int p = 0; p < 2; p++) {
        uint32_t rb[4];
        ldsm_x4(aBh + boff[p], rb);
        bh[2 * p][0] = rb[0]; bh[2 * p + 1][0] = rb[1];
        bh[2 * p][1] = rb[2]; bh[2 * p + 1][1] = rb[3];
        ldsm_x4(aBl + boff[p], rb);
        bl[2 * p][0] = rb[0]; bl[2 * p + 1][0] = rb[1];
        bl[2 * p][1] = rb[2]; bl[2 * p + 1][1] = rb[3];
    }
#pragma unroll
    for (int i = 0; i < 4; i++)
#pragma unroll
        for (int j = 0; j < 4; j++) {
            MMAH(acc[i][j], ah[i], bh[j]);
            MMAH(acc[i][j], al[i], bh[j]);
            MMAH(acc[i][j], ah[i], bl[j]);
        }
}

// 2-pass slab: hh + hl (A hi only; B hi/lo) — pv
__device__ __forceinline__ void mma_slab2(
    uint32_t aAh, uint32_t aBh, uint32_t aBl,
    const uint32_t* aoff, const uint32_t* boff, float acc[4][4][4])
{
    uint32_t ah[4][4], bh[4][2], bl[4][2];
#pragma unroll
    for (int i = 0; i < 4; i++)
        ldsm_x4(aAh + aoff[i], ah[i]);
#pragma unroll
    for (int p = 0; p < 2; p++) {
        uint32_t rb[4];
        ldsm_x4(aBh + boff[p], rb);
        bh[2 * p][0] = rb[0]; bh[2 * p + 1][0] = rb[1];
        bh[2 * p][1] = rb[2]; bh[2 * p + 1][1] = rb[3];
        ldsm_x4(aBl + boff[p], rb);
        bl[2 * p][0] = rb[0]; bl[2 * p + 1][0] = rb[1];
        bl[2 * p][1] = rb[2]; bl[2 * p + 1][1] = rb[3];
    }
#pragma unroll
    for (int i = 0; i < 4; i++)
#pragma unroll
        for (int j = 0; j < 4; j++) {
            MMAH(acc[i][j], ah[i], bh[j]);
            MMAH(acc[i][j], ah[i], bl[j]);
        }
}

// 1-pass slab: hh only (gap-protected logit paths)
__device__ __forceinline__ void mma_slab1(
    uint32_t aAh, uint32_t aBh,
    const uint32_t* aoff, const uint32_t* boff, float acc[4][4][4])
{
    uint32_t ah[4][4], bh[4][2];
#pragma unroll
    for (int i = 0; i < 4; i++)
        ldsm_x4(aAh + aoff[i], ah[i]);
#pragma unroll
    for (int p = 0; p < 2; p++) {
        uint32_t rb[4];
        ldsm_x4(aBh + boff[p], rb);
        bh[2 * p][0] = rb[0]; bh[2 * p + 1][0] = rb[1];
        bh[2 * p][1] = rb[2]; bh[2 * p + 1][1] = rb[3];
    }
#pragma unroll
    for (int i = 0; i < 4; i++)
#pragma unroll
        for (int j = 0; j < 4; j++)
            MMAH(acc[i][j], ah[i], bh[j]);
}

// per-warp ldmatrix address offsets (bytes) within one operand buffer
#define MAKE_LDSM_OFFSETS()                                              \
    uint32_t aoff[4], boff[2];                                           \
    {                                                                    \
        const int l15 = lane & 15, lhi = lane >> 4;                      \
        _Pragma("unroll")                                                \
        for (int i = 0; i < 4; i++)                                      \
            aoff[i] = (uint32_t)((wm + 16 * i + l15) * 48 + lhi * 16);   \
        _Pragma("unroll")                                                \
        for (int p = 0; p < 2; p++)                                      \
            boff[p] = (uint32_t)((wn + 16 * p + l15) * 48 + lhi * 16);   \
    }

// ---------------------------------------------------------------------------
// proj q/k: 1-pass (xh * Wh). Writes hi-only halves + row sums.
__global__ __launch_bounds__(256) void proj_qk_kernel(
    const float* __restrict__ x, const float* __restrict__ Wq,
    const float* __restrict__ Wk)
{
    __shared__ uint32_t Ah[2][128 * LD];
    __shared__ uint32_t Bh[2][128 * LD];
    __shared__ float ssum[128];
    const int isQ = (blockIdx.y == 0);
    const float* W = isQ ? Wq : Wk;
    uint32_t* outh = isQ ? g_qh : g_kh;
    const int m0 = blockIdx.x * 128;
    const int tid = threadIdx.x;
    const int w = tid >> 5, lane = tid & 31;
    const int wm = (w & 1) * 64, wn = (w >> 1) * 32;
    const int g = lane >> 2, t = lane & 3;
    const int pr = tid >> 1, pc = (tid & 1) * 4;

    MAKE_LDSM_OFFSETS();
    const uint32_t bAh = smem_u32(&Ah[0][0]);
    const uint32_t bBh = smem_u32(&Bh[0][0]);

    if (tid < 128) ssum[tid] = 0.f;

    const float* ap = x + (size_t)(m0 + pr) * C + pc * 2;
    const float* bp = W + (size_t)pr * C + pc * 2;

    float4 rA0 = *(const float4*)ap, rA1 = *(const float4*)(ap + 4);
    float4 rB0 = *(const float4*)bp, rB1 = *(const float4*)(bp + 4);

    float acc[4][4][4];
#pragma unroll
    for (int i = 0; i < 4; i++)
#pragma unroll
        for (int j = 0; j < 4; j++)
#pragma unroll
            for (int q = 0; q < 4; q++) acc[i][j][q] = 0.f;

    const int NS = C / 16;
    {
        uint32_t h0, h1, h2, h3;
        cvtH4(rA0, h0, h1); cvtH4(rA1, h2, h3);
        *(uint4*)&Ah[0][pr * LD + pc] = make_uint4(h0, h1, h2, h3);
        cvtH4(rB0, h0, h1); cvtH4(rB1, h2, h3);
        *(uint4*)&Bh[0][pr * LD + pc] = make_uint4(h0, h1, h2, h3);
    }
#pragma unroll 1
    for (int s = 0; s < NS; s++) {
        const int cur = s & 1, nxt = cur ^ 1;
        const uint32_t bo = (uint32_t)(cur * BUF_BYTES);
        __syncthreads();
        if (s + 1 < NS) {
            rA0 = *(const float4*)(ap + (s + 1) * 16);
            rA1 = *(const float4*)(ap + (s + 1) * 16 + 4);
            rB0 = *(const float4*)(bp + (s + 1) * 16);
            rB1 = *(const float4*)(bp + (s + 1) * 16 + 4);
        }
        mma_slab1(bAh + bo, bBh + bo, aoff, boff, acc);
        if (s + 1 < NS) {
            uint32_t h0, h1, h2, h3;
            cvtH4(rA0, h0, h1); cvtH4(rA1, h2, h3);
            *(uint4*)&Ah[nxt][pr * LD + pc] = make_uint4(h0, h1, h2, h3);
            cvtH4(rB0, h0, h1); cvtH4(rB1, h2, h3);
            *(uint4*)&Bh[nxt][pr * LD + pc] = make_uint4(h0, h1, h2, h3);
        }
    }
    // epilogue: hi-only write + row sums
#pragma unroll
    for (int i = 0; i < 4; i++) {
        const int r0 = wm + 16 * i + g;
        float s0 = 0.f, s1 = 0.f;
#pragma unroll
        for (int j = 0; j < 4; j++) {
            const int p = (wn >> 1) + 4 * j + t;
            __half2 h2a = __floats2half2_rn(acc[i][j][0], acc[i][j][1]);
            outh[(size_t)(m0 + r0) * 64 + p] = *(uint32_t*)&h2a;
            __half2 h2b = __floats2half2_rn(acc[i][j][2], acc[i][j][3]);
            outh[(size_t)(m0 + r0 + 8) * 64 + p] = *(uint32_t*)&h2b;
            s0 += acc[i][j][0] + acc[i][j][1];
            s1 += acc[i][j][2] + acc[i][j][3];
        }
        atomicAdd(&ssum[r0], s0);
        atomicAdd(&ssum[r0 + 8], s1);
    }
    __syncthreads();
    if (tid < 128) {
        float* gs = isQ ? g_sq : g_sk;
        gs[m0 + tid] = ssum[tid];
    }
}

// ---------------------------------------------------------------------------
// proj v: 3-pass (res accuracy depends on v). Writes pre-split halves.
__global__ __launch_bounds__(256) void proj_v_kernel(
    const float* __restrict__ x, const float* __restrict__ Wv)
{
    __shared__ uint32_t Ah[2][128 * LD], Al[2][128 * LD];
    __shared__ uint32_t Bh[2][128 * LD], Bl[2][128 * LD];
    const int m0 = blockIdx.x * 128;
    const int tid = threadIdx.x;
    const int w = tid >> 5, lane = tid & 31;
    const int wm = (w & 1) * 64, wn = (w >> 1) * 32;
    const int g = lane >> 2, t = lane & 3;
    const int pr = tid >> 1, pc = (tid & 1) * 4;

    MAKE_LDSM_OFFSETS();
    const uint32_t bAh = smem_u32(&Ah[0][0]), bAl = smem_u32(&Al[0][0]);
    const uint32_t bBh = smem_u32(&Bh[0][0]), bBl = smem_u32(&Bl[0][0]);

    const float* ap = x + (size_t)(m0 + pr) * C + pc * 2;
    const float* bp = Wv + (size_t)pr * C + pc * 2;

    float4 rA0 = *(const float4*)ap, rA1 = *(const float4*)(ap + 4);
    float4 rB0 = *(const float4*)bp, rB1 = *(const float4*)(bp + 4);

    float acc[4][4][4];
#pragma unroll
    for (int i = 0; i < 4; i++)
#pragma unroll
        for (int j = 0; j < 4; j++)
#pragma unroll
            for (int q = 0; q < 4; q++) acc[i][j][q] = 0.f;

    const int NS = C / 16;
    {
        uint32_t h0, h1, h2, h3, l0, l1, l2, l3;
        splitH4(rA0, h0, h1, l0, l1); splitH4(rA1, h2, h3, l2, l3);
        *(uint4*)&Ah[0][pr * LD + pc] = make_uint4(h0, h1, h2, h3);
        *(uint4*)&Al[0][pr * LD + pc] = make_uint4(l0, l1, l2, l3);
        splitH4(rB0, h0, h1, l0, l1); splitH4(rB1, h2, h3, l2, l3);
        *(uint4*)&Bh[0][pr * LD + pc] = make_uint4(h0, h1, h2, h3);
        *(uint4*)&Bl[0][pr * LD + pc] = make_uint4(l0, l1, l2, l3);
    }
#pragma unroll 1
    for (int s = 0; s < NS; s++) {
        const int cur = s & 1, nxt = cur ^ 1;
        const uint32_t bo = (uint32_t)(cur * BUF_BYTES);
        __syncthreads();
        if (s + 1 < NS) {
            rA0 = *(const float4*)(ap + (s + 1) * 16);
            rA1 = *(const float4*)(ap + (s + 1) * 16 + 4);
            rB0 = *(const float4*)(bp + (s + 1) * 16);
            rB1 = *(const float4*)(bp + (s + 1) * 16 + 4);
        }
        mma_slab3(bAh + bo, bAl + bo, bBh + bo, bBl + bo, aoff, boff, acc);
        if (s + 1 < NS) {
            uint32_t h0, h1, h2, h3, l0, l1, l2, l3;
            splitH4(rA0, h0, h1, l0, l1); splitH4(rA1, h2, h3, l2, l3);
            *(uint4*)&Ah[nxt][pr * LD + pc] = make_uint4(h0, h1, h2, h3);
            *(uint4*)&Al[nxt][pr * LD + pc] = make_uint4(l0, l1, l2, l3);
            splitH4(rB0, h0, h1, l0, l1); splitH4(rB1, h2, h3, l2, l3);
            *(uint4*)&Bh[nxt][pr * LD + pc] = make_uint4(h0, h1, h2, h3);
            *(uint4*)&Bl[nxt][pr * LD + pc] = make_uint4(l0, l1, l2, l3);
        }
    }
#pragma unroll
    for (int i = 0; i < 4; i++) {
        const int r0 = wm + 16 * i + g;
#pragma unroll
        for (int j = 0; j < 4; j++) {
            const int p = (wn >> 1) + 4 * j + t;
            uint32_t h, l;
            splitH2(acc[i][j][0], acc[i][j][1], h, l);
            g_vh[(size_t)(m0 + r0) * 64 + p] = h;
            g_vl[(size_t)(m0 + r0) * 64 + p] = l;
            splitH2(acc[i][j][2], acc[i][j][3], h, l);
            g_vh[(size_t)(m0 + r0 + 8) * 64 + p] = h;
            g_vl[(size_t)(m0 + r0 + 8) * 64 + p] = l;
        }
    }
}

// ---------------------------------------------------------------------------
// score: raw S = qh.kh over lower-band 128x128 tiles (1-pass)
__global__ __launch_bounds__(256) void score_mma_kernel(float* __restrict__ attn)
{
    __shared__ uint32_t Ah[2][128 * LD];
    __shared__ uint32_t Bh[2][128 * LD];
    const int b = blockIdx.y;
    const int idx = blockIdx.x;
    int ti = (int)((sqrtf(8.f * (float)idx + 1.f) - 1.f) * 0.5f);
    if (ti > 15) ti = 15;
    while ((ti + 1) * (ti + 2) / 2 <= idx) ti++;
    while (ti * (ti + 1) / 2 > idx) ti--;
    const int tj = idx - ti * (ti + 1) / 2;
    const int t0 = ti * 128, s0 = tj * 128;

    const int tid = threadIdx.x;
    const int w = tid >> 5, lane = tid & 31;
    const int wm = (w & 1) * 64, wn = (w >> 1) * 32;
    const int g = lane >> 2, t = lane & 3;
    const int pr = tid >> 1, pc = (tid & 1) * 4;

    MAKE_LDSM_OFFSETS();
    const uint32_t bAh = smem_u32(&Ah[0][0]);
    const uint32_t bBh = smem_u32(&Bh[0][0]);

    const uint32_t* qh = g_qh + (size_t)(b * T + t0 + pr) * 64 + pc;
    const uint32_t* kh = g_kh + (size_t)(b * T + s0 + pr) * 64 + pc;

    uint4 rAh = *(const uint4*)qh;
    uint4 rBh = *(const uint4*)kh;

    float acc[4][4][4];
#pragma unroll
    for (int i = 0; i < 4; i++)
#pragma unroll
        for (int j = 0; j < 4; j++)
#pragma unroll
            for (int q = 0; q < 4; q++) acc[i][j][q] = 0.f;

    const int NS = H / 16;  // 8
    *(uint4*)&Ah[0][pr * LD + pc] = rAh;
    *(uint4*)&Bh[0][pr * LD + pc] = rBh;
#pragma unroll 1
    for (int s = 0; s < NS; s++) {
        const int cur = s & 1, nxt = cur ^ 1;
        const uint32_t bo = (uint32_t)(cur * BUF_BYTES);
        __syncthreads();
        if (s + 1 < NS) {
            rAh = *(const uint4*)(qh + (s + 1) * 8);
            rBh = *(const uint4*)(kh + (s + 1) * 8);
        }
        mma_slab1(bAh + bo, bBh + bo, aoff, boff, acc);
        if (s + 1 < NS) {
            *(uint4*)&Ah[nxt][pr * LD + pc] = rAh;
            *(uint4*)&Bh[nxt][pr * LD + pc] = rBh;
        }
    }
#pragma unroll
    for (int i = 0; i < 4; i++)
#pragma unroll
        for (int j = 0; j < 4; j++) {
            int row = t0 + wm + 16 * i + g;
            int col = s0 + wn + 8 * j + 2 * t;
            *(float2*)&attn[(size_t)(b * T + row) * T + col]     = make_float2(acc[i][j][0], acc[i][j][1]);
            *(float2*)&attn[(size_t)(b * T + row + 8) * T + col] = make_float2(acc[i][j][2], acc[i][j][3]);
        }
}

// ---------------------------------------------------------------------------
// softmax: in-place per row; band-only reads, pos terms folded as 3 FMA.
__global__ __launch_bounds__(256) void softmax_kernel(float* __restrict__ attn)
{
    __shared__ float red[8];
    const int r = blockIdx.x;
    const int b = r >> 11;
    const int t = r & (T - 1);
    float* row = attn + (size_t)r * T;
    const float* skrow = g_sk + (size_t)b * T;
    const int tid = threadIdx.x;
    const int c0 = tid * 8;
    const bool act = (c0 <= t);

    // lg = qk/32 + s*(sq+128t)/32 + (t/32)*sk
    const float aco = (g_sq[r] + 128.f * (float)t) * 0.03125f;
    const float tk  = (float)t * 0.03125f;

    float qk[8] = {0, 0, 0, 0, 0, 0, 0, 0};
    float sk[8] = {0, 0, 0, 0, 0, 0, 0, 0};
    if (act) {
        float4 v0 = *(const float4*)(row + c0);
        float4 v1 = *(const float4*)(row + c0 + 4);
        float4 s0 = *(const float4*)(skrow + c0);
        float4 s1 = *(const float4*)(skrow + c0 + 4);
        qk[0] = v0.x; qk[1] = v0.y; qk[2] = v0.z; qk[3] = v0.w;
        qk[4] = v1.x; qk[5] = v1.y; qk[6] = v1.z; qk[7] = v1.w;
        sk[0] = s0.x; sk[1] = s0.y; sk[2] = s0.z; sk[3] = s0.w;
        sk[4] = s1.x; sk[5] = s1.y; sk[6] = s1.z; sk[7] = s1.w;
    }

    float lg[8];
    float mx = -INFINITY;
#pragma unroll
    for (int j = 0; j < 8; j++) {
        int s = c0 + j;
        float v = fmaf((float)s, aco, fmaf(tk, sk[j], qk[j] * 0.03125f));
        lg[j] = (s <= t) ? v : -INFINITY;
        mx = fmaxf(mx, lg[j]);
    }
#pragma unroll
    for (int o = 16; o > 0; o >>= 1)
        mx = fmaxf(mx, __shfl_xor_sync(0xffffffffu, mx, o));
    if ((tid & 31) == 0) red[tid >> 5] = mx;
    __syncthreads();
    float m = red[0];
#pragma unroll
    for (int i = 1; i < 8; i++) m = fmaxf(m, red[i]);
    __syncthreads();

    float ev[8];
    float sum = 0.f;
#pragma unroll
    for (int j = 0; j < 8; j++) {
        ev[j] = __expf(lg[j] - m);
        sum += ev[j];
    }
#pragma unroll
    for (int o = 16; o > 0; o >>= 1)
        sum += __shfl_xor_sync(0xffffffffu, sum, o);
    if ((tid & 31) == 0) red[tid >> 5] = sum;
    __syncthreads();
    float tot = red[0];
#pragma unroll
    for (int i = 1; i < 8; i++) tot += red[i];
    const float rinv = 1.f / tot;

    *(float4*)(row + c0)     = make_float4(ev[0] * rinv, ev[1] * rinv, ev[2] * rinv, ev[3] * rinv);
    *(float4*)(row + c0 + 4) = make_float4(ev[4] * rinv, ev[5] * rinv, ev[6] * rinv, ev[7] * rinv);
}

// ---------------------------------------------------------------------------
// pv: res += attn_chunk @ v_chunk (2-pass: ph*vh + ph*vl; attn hi-only,
// uniform 128-wide split-K chunks, atomicAdd into zeroed res, ldmatrix).
__global__ __launch_bounds__(256) void pv_mma_kernel(
    const float* __restrict__ attn, float* __restrict__ res)
{
    __shared__ uint32_t Ah[2][128 * LD];
    __shared__ uint32_t Bh[2][128 * LD], Bl[2][128 * LD];
    const int b = blockIdx.y;
    const int idx = blockIdx.x;
    int kt = (int)((sqrtf(8.f * (float)idx + 1.f) - 1.f) * 0.5f);
    if (kt > 15) kt = 15;
    while ((kt + 1) * (kt + 2) / 2 <= idx) kt++;
    while (kt * (kt + 1) / 2 > idx) kt--;
    const int chunk = idx - kt * (kt + 1) / 2;
    const int t0 = kt * 128;
    const int sbeg = chunk * 128;
    const int NS = 8;

    const int tid = threadIdx.x;
    const int w = tid >> 5, lane = tid & 31;
    const int wm = (w & 1) * 64, wn = (w >> 1) * 32;
    const int g = lane >> 2, t = lane & 3;
    const int pr = tid >> 1, pc = (tid & 1) * 4;   // A stager
    const int sp = tid & 7, hq = tid >> 3;         // B stager: s-pair, h-quad

    MAKE_LDSM_OFFSETS();
    const uint32_t bAh = smem_u32(&Ah[0][0]);
    const uint32_t bBh = smem_u32(&Bh[0][0]), bBl = smem_u32(&Bl[0][0]);

    const float* ap = attn + (size_t)(b * T + t0 + pr) * T + sbeg + pc * 2;
    const uint32_t* vh = g_vh + (size_t)(b * T + sbeg + 2 * sp) * 64 + 2 * hq;
    const uint32_t* vl = g_vl + (size_t)(b * T + sbeg + 2 * sp) * 64 + 2 * hq;

    float4 rA0 = *(const float4*)ap, rA1 = *(const float4*)(ap + 4);
    uint2 rha = *(const uint2*)vh,   rhb = *(const uint2*)(vh + 64);
    uint2 rla = *(const uint2*)vl,   rlb = *(const uint2*)(vl + 64);

    float acc[4][4][4];
#pragma unroll
    for (int i = 0; i < 4; i++)
#pragma unroll
        for (int j = 0; j < 4; j++)
#pragma unroll
            for (int q = 0; q < 4; q++) acc[i][j][q] = 0.f;

    {
        uint32_t h0, h1, h2, h3;
        cvtH4(rA0, h0, h1); cvtH4(rA1, h2, h3);
        *(uint4*)&Ah[0][pr * LD + pc] = make_uint4(h0, h1, h2, h3);
        Bh[0][(4 * hq + 0) * LD + sp] = __byte_perm(rha.x, rhb.x, 0x5410);
        Bh[0][(4 * hq + 1) * LD + sp] = __byte_perm(rha.x, rhb.x, 0x7632);
        Bh[0][(4 * hq + 2) * LD + sp] = __byte_perm(rha.y, rhb.y, 0x5410);
        Bh[0][(4 * hq + 3) * LD + sp] = __byte_perm(rha.y, rhb.y, 0x7632);
        Bl[0][(4 * hq + 0) * LD + sp] = __byte_perm(rla.x, rlb.x, 0x5410);
        Bl[0][(4 * hq + 1) * LD + sp] = __byte_perm(rla.x, rlb.x, 0x7632);
        Bl[0][(4 * hq + 2) * LD + sp] = __byte_perm(rla.y, rlb.y, 0x5410);
        Bl[0][(4 * hq + 3) * LD + sp] = __byte_perm(rla.y, rlb.y, 0x7632);
    }
#pragma unroll 1
    for (int s = 0; s < NS; s++) {
        const int cur = s & 1, nxt = cur ^ 1;
        const uint32_t bo = (uint32_t)(cur * BUF_BYTES);
        __syncthreads();
        if (s + 1 < NS) {
            rA0 = *(const float4*)(ap + (s + 1) * 16);
            rA1 = *(const float4*)(ap + (s + 1) * 16 + 4);
            const uint32_t* vh2 = vh + (size_t)(s + 1) * 16 * 64;
            const uint32_t* vl2 = vl + (size_t)(s + 1) * 16 * 64;
            rha = *(const uint2*)vh2; rhb = *(const uint2*)(vh2 + 64);
            rla = *(const uint2*)vl2; rlb = *(const uint2*)(vl2 + 64);
        }
        mma_slab2(bAh + bo, bBh + bo, bBl + bo, aoff, boff, acc);
        if (s + 1 < NS) {
            uint32_t h0, h1, h2, h3;
            cvtH4(rA0, h0, h1); cvtH4(rA1, h2, h3);
            *(uint4*)&Ah[nxt][pr * LD + pc] = make_uint4(h0, h1, h2, h3);
            Bh[nxt][(4 * hq + 0) * LD + sp] = __byte_perm(rha.x, rhb.x, 0x5410);
            Bh[nxt][(4 * hq + 1) * LD + sp] = __byte_perm(rha.x, rhb.x, 0x7632);
            Bh[nxt][(4 * hq + 2) * LD + sp] = __byte_perm(rha.y, rhb.y, 0x5410);
            Bh[nxt][(4 * hq + 3) * LD + sp] = __byte_perm(rha.y, rhb.y, 0x7632);
            Bl[nxt][(4 * hq + 0) * LD + sp] = __byte_perm(rla.x, rlb.x, 0x5410);
            Bl[nxt][(4 * hq + 1) * LD + sp] = __byte_perm(rla.x, rlb.x, 0x7632);
            Bl[nxt][(4 * hq + 2) * LD + sp] = __byte_perm(rla.y, rlb.y, 0x5410);
            Bl[nxt][(4 * hq + 3) * LD + sp] = __byte_perm(rla.y, rlb.y, 0x7632);
        }
    }
#pragma unroll
    for (int i = 0; i < 4; i++)
#pragma unroll
        for (int j = 0; j < 4; j++) {
            int row = t0 + wm + 16 * i + g;
            int col = wn + 8 * j + 2 * t;
            float* p0 = res + (size_t)(b * T + row) * H + col;
            float* p1 = res + (size_t)(b * T + row + 8) * H + col;
            atomicAdd(p0,     acc[i][j][0]);
            atomicAdd(p0 + 1, acc[i][j][1]);
            atomicAdd(p1,     acc[i][j][2]);
            atomicAdd(p1 + 1, acc[i][j][3]);
        }
}

// ---------------------------------------------------------------------------
extern "C" void kernel_launch(void* const* d_in, const int* in_sizes, int n_in,
                              void* d_out, int out_size)
{
    const float* x  = (const float*)d_in[0];
    const float* Wq = (const float*)d_in[1];
    const float* Wk = (const float*)d_in[2];
    const float* Wv = (const float*)d_in[3];
    float* res  = (float*)d_out;
    float* attn = res + (size_t)B * T * H;

    cudaMemsetAsync(res, 0, (size_t)NR * H * sizeof(float));
    proj_qk_kernel<<<dim3(NR / 128, 2), 256>>>(x, Wq, Wk);
    proj_v_kernel<<<NR / 128, 256>>>(x, Wv);
    score_mma_kernel<<<dim3(136, 8), 256>>>(attn);
    softmax_kernel<<<NR, 256>>>(attn);
    pv_mma_kernel<<<dim3(136, 8), 256>>>(attn, res);
}